// round 1
// baseline (speedup 1.0000x reference)
#include <cuda_runtime.h>
#include <math.h>

// Problem constants
#define B_  2
#define C_  128
#define D_  4
#define H_  48
#define W_  48
#define NTOK (B_*D_*H_*W_)   // 18432
#define NHEAD 4
#define HD 32
#define KW 7

// Scratch (device globals — no allocation allowed)
__device__ float g_t   [NTOK*128];
__device__ float g_ln  [NTOK*128];
__device__ float g_qkv [NTOK*384];
__device__ float g_attn[NTOK*128];
__device__ float g_h1  [NTOK*256];

// ---------------------------------------------------------------------------
// Transpose in: x (B,C,D,H,W) -> t (N=B*D*H*W, C)
// ---------------------------------------------------------------------------
__global__ void t_in_kernel(const float* __restrict__ x, float* __restrict__ t) {
    __shared__ float sm[16][17];
    int bz = blockIdx.z;                 // over (b,d,h): 2*4*48 = 384
    int b = bz / (D_*H_);
    int rem = bz % (D_*H_);
    int d = rem / H_;
    int h = rem % H_;
    int w = blockIdx.x*16 + threadIdx.x;
    int c = blockIdx.y*16 + threadIdx.y;
    sm[threadIdx.y][threadIdx.x] =
        x[(( (long)b*C_ + c)*D_ + d)*(H_*W_) + h*W_ + w];
    __syncthreads();
    int c2 = blockIdx.y*16 + threadIdx.x;
    int w2 = blockIdx.x*16 + threadIdx.y;
    t[((((b*D_ + d)*H_ + h)*W_ + w2) * (long)C_) + c2] = sm[threadIdx.x][threadIdx.y];
}

// ---------------------------------------------------------------------------
// Transpose out: t (N, C) -> out (B,C,D,H,W)
// ---------------------------------------------------------------------------
__global__ void t_out_kernel(const float* __restrict__ t, float* __restrict__ out) {
    __shared__ float sm[16][17];
    int bz = blockIdx.z;
    int b = bz / (D_*H_);
    int rem = bz % (D_*H_);
    int d = rem / H_;
    int h = rem % H_;
    // load: rows = w, cols = c (coalesced over c)
    int w_l = blockIdx.x*16 + threadIdx.y;
    int c_l = blockIdx.y*16 + threadIdx.x;
    sm[threadIdx.y][threadIdx.x] =
        t[((((b*D_ + d)*H_ + h)*W_ + w_l) * (long)C_) + c_l];
    __syncthreads();
    int c_s = blockIdx.y*16 + threadIdx.y;
    int w_s = blockIdx.x*16 + threadIdx.x;
    out[(((long)b*C_ + c_s)*D_ + d)*(H_*W_) + h*W_ + w_s] = sm[threadIdx.x][threadIdx.y];
}

// ---------------------------------------------------------------------------
// LayerNorm over C=128, one token per 128-thread block
// ---------------------------------------------------------------------------
__global__ void ln_kernel(const float* __restrict__ in,
                          const float* __restrict__ w,
                          const float* __restrict__ b,
                          float* __restrict__ out) {
    int n = blockIdx.x;
    int tid = threadIdx.x;
    float v = in[(long)n*128 + tid];
    float s = v, s2 = v*v;
    #pragma unroll
    for (int o = 16; o > 0; o >>= 1) {
        s  += __shfl_xor_sync(0xffffffffu, s,  o);
        s2 += __shfl_xor_sync(0xffffffffu, s2, o);
    }
    __shared__ float sh[8];
    int warp = tid >> 5, lane = tid & 31;
    if (lane == 0) { sh[warp] = s; sh[4+warp] = s2; }
    __syncthreads();
    s  = sh[0]+sh[1]+sh[2]+sh[3];
    s2 = sh[4]+sh[5]+sh[6]+sh[7];
    float m   = s  * (1.0f/128.0f);
    float var = s2 * (1.0f/128.0f) - m*m;
    float inv = rsqrtf(var + 1e-5f);
    out[(long)n*128 + tid] = (v - m) * inv * w[tid] + b[tid];
}

// ---------------------------------------------------------------------------
// Tiled fp32 GEMM: out[N,M] = A[N,K] @ W[M,K]^T + bias, with epilogues.
// BM=BN=64, BK=16, 256 threads, 4x4 per thread. N,M multiples of 64, K of 16.
// EPI: 0 = bias only, 1 = bias + exact GELU, 2 = bias + add into out (residual)
// ---------------------------------------------------------------------------
template<int EPI>
__global__ void gemm_kernel(const float* __restrict__ A,
                            const float* __restrict__ Wt,
                            const float* __restrict__ bias,
                            float* __restrict__ out,
                            int N, int M, int K) {
    __shared__ float As[16][68];
    __shared__ float Bs[16][68];
    int tid = threadIdx.x;
    int n0 = blockIdx.y * 64;
    int m0 = blockIdx.x * 64;
    int ar = tid >> 2;          // 0..63
    int ac = (tid & 3) * 4;     // 0,4,8,12
    int ty = tid >> 4;          // 0..15 (rows)
    int tx = tid & 15;          // 0..15 (cols)

    float acc[4][4];
    #pragma unroll
    for (int i = 0; i < 4; i++)
        #pragma unroll
        for (int j = 0; j < 4; j++) acc[i][j] = 0.0f;

    for (int k0 = 0; k0 < K; k0 += 16) {
        float4 a4 = *reinterpret_cast<const float4*>(A  + (long)(n0+ar)*K + k0 + ac);
        float4 b4 = *reinterpret_cast<const float4*>(Wt + (long)(m0+ar)*K + k0 + ac);
        As[ac+0][ar] = a4.x; As[ac+1][ar] = a4.y; As[ac+2][ar] = a4.z; As[ac+3][ar] = a4.w;
        Bs[ac+0][ar] = b4.x; Bs[ac+1][ar] = b4.y; Bs[ac+2][ar] = b4.z; Bs[ac+3][ar] = b4.w;
        __syncthreads();
        #pragma unroll
        for (int kk = 0; kk < 16; kk++) {
            float4 ra = *reinterpret_cast<const float4*>(&As[kk][ty*4]);
            float4 rb = *reinterpret_cast<const float4*>(&Bs[kk][tx*4]);
            float raa[4] = {ra.x, ra.y, ra.z, ra.w};
            float rbb[4] = {rb.x, rb.y, rb.z, rb.w};
            #pragma unroll
            for (int i = 0; i < 4; i++)
                #pragma unroll
                for (int j = 0; j < 4; j++)
                    acc[i][j] += raa[i] * rbb[j];
        }
        __syncthreads();
    }

    float4 bi = *reinterpret_cast<const float4*>(bias + m0 + tx*4);
    float bb[4] = {bi.x, bi.y, bi.z, bi.w};
    #pragma unroll
    for (int i = 0; i < 4; i++) {
        long n = n0 + ty*4 + i;
        float r[4];
        #pragma unroll
        for (int j = 0; j < 4; j++) {
            float v = acc[i][j] + bb[j];
            if (EPI == 1) v = 0.5f * v * (1.0f + erff(v * 0.70710678118654752f));
            r[j] = v;
        }
        float4* dst = reinterpret_cast<float4*>(out + n*M + m0 + tx*4);
        if (EPI == 2) {
            float4 old = *dst;
            r[0] += old.x; r[1] += old.y; r[2] += old.z; r[3] += old.w;
        }
        float4 st; st.x = r[0]; st.y = r[1]; st.z = r[2]; st.w = r[3];
        *dst = st;
    }
}

// ---------------------------------------------------------------------------
// Neighborhood attention: one block per token (128 threads = 4 warps = 4 heads)
// lane = head dim (hd=32). k/v gathered once, kept in registers.
// ---------------------------------------------------------------------------
__global__ void attn_kernel(const float* __restrict__ qkv,
                            const float* __restrict__ rpb,
                            float* __restrict__ attn_out) {
    int n = blockIdx.x;
    int head = threadIdx.x >> 5;
    int lane = threadIdx.x & 31;

    int bd  = n / (H_*W_);
    int rem = n % (H_*W_);
    int h = rem / W_;
    int w = rem % W_;
    int sh = min(max(h - 3, 0), H_ - KW);  // 0..41
    int sw = min(max(w - 3, 0), W_ - KW);

    const float scale = 0.17677669529663687f; // 32^-0.5
    float q = qkv[(long)n*384 + head*32 + lane] * scale;

    float s[49];
    float vv[49];
    #pragma unroll
    for (int jh = 0; jh < KW; jh++) {
        int row = (bd*H_ + sh + jh) * W_ + sw;
        int bh = sh + jh - h + (KW - 1);
        #pragma unroll
        for (int jw = 0; jw < KW; jw++) {
            int nn = row + jw;
            long base = (long)nn*384 + head*32 + lane;
            float kd = qkv[base + 128];
            float vd = qkv[base + 256];
            float p = q * kd;
            #pragma unroll
            for (int o = 16; o > 0; o >>= 1)
                p += __shfl_xor_sync(0xffffffffu, p, o);
            int bw = sw + jw - w + (KW - 1);
            s[jh*KW + jw]  = p + rpb[head*169 + bh*13 + bw];
            vv[jh*KW + jw] = vd;
        }
    }

    // softmax over 49 (computed redundantly per lane; identical values)
    float mx = s[0];
    #pragma unroll
    for (int j = 1; j < 49; j++) mx = fmaxf(mx, s[j]);
    float sum = 0.0f;
    #pragma unroll
    for (int j = 0; j < 49; j++) { s[j] = __expf(s[j] - mx); sum += s[j]; }
    float inv = 1.0f / sum;

    float o = 0.0f;
    #pragma unroll
    for (int j = 0; j < 49; j++) o += s[j] * vv[j];

    attn_out[(long)n*128 + head*32 + lane] = o * inv;
}

// ---------------------------------------------------------------------------
// Launch
// ---------------------------------------------------------------------------
extern "C" void kernel_launch(void* const* d_in, const int* in_sizes, int n_in,
                              void* d_out, int out_size) {
    const float* x      = (const float*)d_in[0];
    const float* n1w    = (const float*)d_in[1];
    const float* n1b    = (const float*)d_in[2];
    const float* qkv_w  = (const float*)d_in[3];
    const float* qkv_b  = (const float*)d_in[4];
    const float* rpb    = (const float*)d_in[5];
    const float* proj_w = (const float*)d_in[6];
    const float* proj_b = (const float*)d_in[7];
    const float* n2w    = (const float*)d_in[8];
    const float* n2b    = (const float*)d_in[9];
    const float* fc1_w  = (const float*)d_in[10];
    const float* fc1_b  = (const float*)d_in[11];
    const float* fc2_w  = (const float*)d_in[12];
    const float* fc2_b  = (const float*)d_in[13];
    float* out = (float*)d_out;

    float *t_p, *ln_p, *qkv_p, *attn_p, *h1_p;
    cudaGetSymbolAddress((void**)&t_p,    g_t);
    cudaGetSymbolAddress((void**)&ln_p,   g_ln);
    cudaGetSymbolAddress((void**)&qkv_p,  g_qkv);
    cudaGetSymbolAddress((void**)&attn_p, g_attn);
    cudaGetSymbolAddress((void**)&h1_p,   g_h1);

    dim3 tb(16, 16);
    dim3 tg(W_/16, C_/16, B_*D_*H_);   // (3, 8, 384)

    // 1. transpose in
    t_in_kernel<<<tg, tb>>>(x, t_p);
    // 2. LN1
    ln_kernel<<<NTOK, 128>>>(t_p, n1w, n1b, ln_p);
    // 3. qkv = ln1 @ qkv_w^T + b      (N x 384, K=128)
    gemm_kernel<0><<<dim3(384/64, NTOK/64), 256>>>(ln_p, qkv_w, qkv_b, qkv_p, NTOK, 384, 128);
    // 4. neighborhood attention
    attn_kernel<<<NTOK, 128>>>(qkv_p, rpb, attn_p);
    // 5. t += attn @ proj_w^T + b     (N x 128, K=128)
    gemm_kernel<2><<<dim3(128/64, NTOK/64), 256>>>(attn_p, proj_w, proj_b, t_p, NTOK, 128, 128);
    // 6. LN2
    ln_kernel<<<NTOK, 128>>>(t_p, n2w, n2b, ln_p);
    // 7. h1 = gelu(ln2 @ fc1_w^T + b) (N x 256, K=128)
    gemm_kernel<1><<<dim3(256/64, NTOK/64), 256>>>(ln_p, fc1_w, fc1_b, h1_p, NTOK, 256, 128);
    // 8. t += h1 @ fc2_w^T + b        (N x 128, K=256)
    gemm_kernel<2><<<dim3(128/64, NTOK/64), 256>>>(h1_p, fc2_w, fc2_b, t_p, NTOK, 128, 256);
    // 9. transpose out
    t_out_kernel<<<tg, tb>>>(t_p, out);
}

// round 2
// speedup vs baseline: 1.2637x; 1.2637x over previous
#include <cuda_runtime.h>
#include <math.h>

// Problem constants
#define B_  2
#define C_  128
#define D_  4
#define H_  48
#define W_  48
#define NTOK (B_*D_*H_*W_)   // 18432
#define NHEAD 4
#define HD 32
#define KW 7

// Scratch (device globals — no allocation allowed)
__device__ float g_t   [NTOK*128];
__device__ float g_ln  [NTOK*128];
__device__ float g_qkv [NTOK*384];
__device__ float g_attn[NTOK*128];
__device__ float g_h1  [NTOK*256];

// ---------------------------------------------------------------------------
// Transpose in: x (B,C,D,H,W) -> t (N=B*D*H*W, C)
// ---------------------------------------------------------------------------
__global__ void t_in_kernel(const float* __restrict__ x, float* __restrict__ t) {
    __shared__ float sm[16][17];
    int bz = blockIdx.z;                 // over (b,d,h): 2*4*48 = 384
    int b = bz / (D_*H_);
    int rem = bz % (D_*H_);
    int d = rem / H_;
    int h = rem % H_;
    int w = blockIdx.x*16 + threadIdx.x;
    int c = blockIdx.y*16 + threadIdx.y;
    sm[threadIdx.y][threadIdx.x] =
        x[(( (long)b*C_ + c)*D_ + d)*(H_*W_) + h*W_ + w];
    __syncthreads();
    int c2 = blockIdx.y*16 + threadIdx.x;
    int w2 = blockIdx.x*16 + threadIdx.y;
    t[((((b*D_ + d)*H_ + h)*W_ + w2) * (long)C_) + c2] = sm[threadIdx.x][threadIdx.y];
}

// ---------------------------------------------------------------------------
// Transpose out: t (N, C) -> out (B,C,D,H,W)
// ---------------------------------------------------------------------------
__global__ void t_out_kernel(const float* __restrict__ t, float* __restrict__ out) {
    __shared__ float sm[16][17];
    int bz = blockIdx.z;
    int b = bz / (D_*H_);
    int rem = bz % (D_*H_);
    int d = rem / H_;
    int h = rem % H_;
    int w_l = blockIdx.x*16 + threadIdx.y;
    int c_l = blockIdx.y*16 + threadIdx.x;
    sm[threadIdx.y][threadIdx.x] =
        t[((((b*D_ + d)*H_ + h)*W_ + w_l) * (long)C_) + c_l];
    __syncthreads();
    int c_s = blockIdx.y*16 + threadIdx.y;
    int w_s = blockIdx.x*16 + threadIdx.x;
    out[(((long)b*C_ + c_s)*D_ + d)*(H_*W_) + h*W_ + w_s] = sm[threadIdx.x][threadIdx.y];
}

// ---------------------------------------------------------------------------
// LayerNorm over C=128, one token per 128-thread block
// ---------------------------------------------------------------------------
__global__ void ln_kernel(const float* __restrict__ in,
                          const float* __restrict__ w,
                          const float* __restrict__ b,
                          float* __restrict__ out) {
    int n = blockIdx.x;
    int tid = threadIdx.x;
    float v = in[(long)n*128 + tid];
    float s = v, s2 = v*v;
    #pragma unroll
    for (int o = 16; o > 0; o >>= 1) {
        s  += __shfl_xor_sync(0xffffffffu, s,  o);
        s2 += __shfl_xor_sync(0xffffffffu, s2, o);
    }
    __shared__ float sh[8];
    int warp = tid >> 5, lane = tid & 31;
    if (lane == 0) { sh[warp] = s; sh[4+warp] = s2; }
    __syncthreads();
    s  = sh[0]+sh[1]+sh[2]+sh[3];
    s2 = sh[4]+sh[5]+sh[6]+sh[7];
    float m   = s  * (1.0f/128.0f);
    float var = s2 * (1.0f/128.0f) - m*m;
    float inv = rsqrtf(var + 1e-5f);
    out[(long)n*128 + tid] = (v - m) * inv * w[tid] + b[tid];
}

// ---------------------------------------------------------------------------
// Tiled fp32 GEMM: out[N,M] = A[N,K] @ W[M,K]^T + bias, with epilogues.
// ---------------------------------------------------------------------------
template<int EPI>
__global__ void gemm_kernel(const float* __restrict__ A,
                            const float* __restrict__ Wt,
                            const float* __restrict__ bias,
                            float* __restrict__ out,
                            int N, int M, int K) {
    __shared__ float As[16][68];
    __shared__ float Bs[16][68];
    int tid = threadIdx.x;
    int n0 = blockIdx.y * 64;
    int m0 = blockIdx.x * 64;
    int ar = tid >> 2;
    int ac = (tid & 3) * 4;
    int ty = tid >> 4;
    int tx = tid & 15;

    float acc[4][4];
    #pragma unroll
    for (int i = 0; i < 4; i++)
        #pragma unroll
        for (int j = 0; j < 4; j++) acc[i][j] = 0.0f;

    for (int k0 = 0; k0 < K; k0 += 16) {
        float4 a4 = *reinterpret_cast<const float4*>(A  + (long)(n0+ar)*K + k0 + ac);
        float4 b4 = *reinterpret_cast<const float4*>(Wt + (long)(m0+ar)*K + k0 + ac);
        As[ac+0][ar] = a4.x; As[ac+1][ar] = a4.y; As[ac+2][ar] = a4.z; As[ac+3][ar] = a4.w;
        Bs[ac+0][ar] = b4.x; Bs[ac+1][ar] = b4.y; Bs[ac+2][ar] = b4.z; Bs[ac+3][ar] = b4.w;
        __syncthreads();
        #pragma unroll
        for (int kk = 0; kk < 16; kk++) {
            float4 ra = *reinterpret_cast<const float4*>(&As[kk][ty*4]);
            float4 rb = *reinterpret_cast<const float4*>(&Bs[kk][tx*4]);
            float raa[4] = {ra.x, ra.y, ra.z, ra.w};
            float rbb[4] = {rb.x, rb.y, rb.z, rb.w};
            #pragma unroll
            for (int i = 0; i < 4; i++)
                #pragma unroll
                for (int j = 0; j < 4; j++)
                    acc[i][j] += raa[i] * rbb[j];
        }
        __syncthreads();
    }

    float4 bi = *reinterpret_cast<const float4*>(bias + m0 + tx*4);
    float bb[4] = {bi.x, bi.y, bi.z, bi.w};
    #pragma unroll
    for (int i = 0; i < 4; i++) {
        long n = n0 + ty*4 + i;
        float r[4];
        #pragma unroll
        for (int j = 0; j < 4; j++) {
            float v = acc[i][j] + bb[j];
            if (EPI == 1) v = 0.5f * v * (1.0f + erff(v * 0.70710678118654752f));
            r[j] = v;
        }
        float4* dst = reinterpret_cast<float4*>(out + n*M + m0 + tx*4);
        if (EPI == 2) {
            float4 old = *dst;
            r[0] += old.x; r[1] += old.y; r[2] += old.z; r[3] += old.w;
        }
        float4 st; st.x = r[0]; st.y = r[1]; st.z = r[2]; st.w = r[3];
        *dst = st;
    }
}

// ---------------------------------------------------------------------------
// Neighborhood attention, tiled:
// grid = (36 tiles of 8x8, NHEAD, B*D). block = 256 (8 warps).
// Stage 14x14 K/V window for this head into smem; warp = query row;
// dense-in-w banded scores (14 wide, masked to the 7 valid), exact in h.
// ---------------------------------------------------------------------------
#define KSTRIDE 36
#define PSTRIDE 113

__global__ void __launch_bounds__(256, 2)
attn_kernel(const float* __restrict__ qkv,
            const float* __restrict__ rpb,
            float* __restrict__ attn_out) {
    extern __shared__ float smem[];
    float* Ks = smem;                       // [198][36]
    float* Vs = Ks + 198*KSTRIDE;           // [196][36]
    float* Ps = Vs + 196*KSTRIDE;           // [8][8][113]

    int tile = blockIdx.x;        // 0..35
    int head = blockIdx.y;
    int bd   = blockIdx.z;
    int h0 = (tile / 6) * 8;
    int w0 = (tile % 6) * 8;
    int kh0 = min(max(h0-3, 0), H_-KW);
    int kw0 = min(max(w0-3, 0), W_-KW);

    int tid = threadIdx.x;

    // ---- Stage K and V window: 196 tokens x 32 dims (clamped at image edge)
    for (int e = tid; e < 196*8; e += 256) {
        int rowi = e >> 3, d4 = e & 7;
        int rr = rowi / 14, cc = rowi % 14;
        int gh = min(kh0 + rr, H_-1);
        int gw = min(kw0 + cc, W_-1);
        long tok = ((long)(bd*H_ + gh))*W_ + gw;
        const float* base = qkv + tok*384 + head*32 + d4*4;
        float4 kv = *reinterpret_cast<const float4*>(base + 128);
        float4 vv = *reinterpret_cast<const float4*>(base + 256);
        *reinterpret_cast<float4*>(&Ks[rowi*KSTRIDE + d4*4]) = kv;
        *reinterpret_cast<float4*>(&Vs[rowi*KSTRIDE + d4*4]) = vv;
    }
    __syncthreads();

    int warp = tid >> 5, lane = tid & 31;
    int q  = lane >> 2;          // query col within tile (0..7)
    int kg = lane & 3;
    int r  = warp;               // query row within tile (0..7)

    int h = h0 + r, w = w0 + q;
    int sh = min(max(h-3, 0), H_-KW);
    int sw = min(max(w-3, 0), W_-KW);
    int rel_h = sh - kh0;        // 0..7 (uniform per warp)
    int ws    = sw - kw0;        // 0..7 ; valid c in [ws, ws+6]
    long tok = ((long)(bd*H_ + h))*W_ + w;

    // ---- Load Q into registers (scaled)
    const float scale = 0.17677669529663687f; // 32^-0.5
    float4 Q[8];
    #pragma unroll
    for (int i = 0; i < 8; i++) {
        float4 qv = *reinterpret_cast<const float4*>(qkv + tok*384 + head*32 + i*4);
        qv.x *= scale; qv.y *= scale; qv.z *= scale; qv.w *= scale;
        Q[i] = qv;
    }

    // ---- Scores: per o (key-row offset), 4 key cols per lane {kg, kg+4, kg+8, kg+12}
    float s[28];
    #pragma unroll
    for (int o = 0; o < 7; o++) {
        int krow = rel_h + o;
        float a0 = 0.f, a1 = 0.f, a2 = 0.f, a3 = 0.f;
        const float* kb = &Ks[(krow*14 + kg)*KSTRIDE];
        #pragma unroll
        for (int d4 = 0; d4 < 8; d4++) {
            float4 qv = Q[d4];
            float4 k0 = *reinterpret_cast<const float4*>(kb +  0*KSTRIDE + d4*4);
            float4 k1 = *reinterpret_cast<const float4*>(kb +  4*KSTRIDE + d4*4);
            float4 k2 = *reinterpret_cast<const float4*>(kb +  8*KSTRIDE + d4*4);
            float4 k3 = *reinterpret_cast<const float4*>(kb + 12*KSTRIDE + d4*4);
            a0 += qv.x*k0.x + qv.y*k0.y + qv.z*k0.z + qv.w*k0.w;
            a1 += qv.x*k1.x + qv.y*k1.y + qv.z*k1.z + qv.w*k1.w;
            a2 += qv.x*k2.x + qv.y*k2.y + qv.z*k2.z + qv.w*k2.w;
            a3 += qv.x*k3.x + qv.y*k3.y + qv.z*k3.z + qv.w*k3.w;
        }
        s[o*4+0] = a0; s[o*4+1] = a1; s[o*4+2] = a2; s[o*4+3] = a3;
    }

    // ---- Bias + mask + softmax (reduce across the 4-lane quad)
    int bh_base = sh - h + 6;
    int bw_base = kw0 - w + 6;
    float mx = -1e30f;
    #pragma unroll
    for (int o = 0; o < 7; o++) {
        #pragma unroll
        for (int cc = 0; cc < 4; cc++) {
            int c = kg + cc*4;
            float v;
            if (c >= ws && c <= ws+6)
                v = s[o*4+cc] + __ldg(&rpb[head*169 + (bh_base+o)*13 + (bw_base+c)]);
            else
                v = -1e30f;
            s[o*4+cc] = v;
            mx = fmaxf(mx, v);
        }
    }
    mx = fmaxf(mx, __shfl_xor_sync(0xffffffffu, mx, 1));
    mx = fmaxf(mx, __shfl_xor_sync(0xffffffffu, mx, 2));
    float sum = 0.f;
    #pragma unroll
    for (int j = 0; j < 28; j++) {
        float e = __expf(s[j] - mx);
        s[j] = e;
        sum += e;
    }
    sum += __shfl_xor_sync(0xffffffffu, sum, 1);
    sum += __shfl_xor_sync(0xffffffffu, sum, 2);
    float inv = 1.0f / sum;

    float* Pw = &Ps[(r*8 + q)*PSTRIDE];
    #pragma unroll
    for (int o = 0; o < 7; o++)
        #pragma unroll
        for (int cc = 0; cc < 4; cc++)
            Pw[o*16 + kg + cc*4] = s[o*4+cc] * inv;
    __syncwarp();

    // ---- AV: lane = (q, dim-group of 8)
    int dg = lane & 3;
    float4 acc0 = make_float4(0.f,0.f,0.f,0.f);
    float4 acc1 = make_float4(0.f,0.f,0.f,0.f);
    const float* Pr = &Ps[(r*8 + q)*PSTRIDE];
    #pragma unroll
    for (int o = 0; o < 7; o++) {
        int krow = rel_h + o;
        #pragma unroll
        for (int c = 0; c < 14; c++) {
            float p = Pr[o*16 + c];
            const float* vp = &Vs[(krow*14 + c)*KSTRIDE + dg*8];
            float4 v0 = *reinterpret_cast<const float4*>(vp);
            float4 v1 = *reinterpret_cast<const float4*>(vp + 4);
            acc0.x += p*v0.x; acc0.y += p*v0.y; acc0.z += p*v0.z; acc0.w += p*v0.w;
            acc1.x += p*v1.x; acc1.y += p*v1.y; acc1.z += p*v1.z; acc1.w += p*v1.w;
        }
    }
    float* op = attn_out + tok*128 + head*32 + dg*8;
    *reinterpret_cast<float4*>(op)     = acc0;
    *reinterpret_cast<float4*>(op + 4) = acc1;
}

// ---------------------------------------------------------------------------
// Launch
// ---------------------------------------------------------------------------
extern "C" void kernel_launch(void* const* d_in, const int* in_sizes, int n_in,
                              void* d_out, int out_size) {
    const float* x      = (const float*)d_in[0];
    const float* n1w    = (const float*)d_in[1];
    const float* n1b    = (const float*)d_in[2];
    const float* qkv_w  = (const float*)d_in[3];
    const float* qkv_b  = (const float*)d_in[4];
    const float* rpb    = (const float*)d_in[5];
    const float* proj_w = (const float*)d_in[6];
    const float* proj_b = (const float*)d_in[7];
    const float* n2w    = (const float*)d_in[8];
    const float* n2b    = (const float*)d_in[9];
    const float* fc1_w  = (const float*)d_in[10];
    const float* fc1_b  = (const float*)d_in[11];
    const float* fc2_w  = (const float*)d_in[12];
    const float* fc2_b  = (const float*)d_in[13];
    float* out = (float*)d_out;

    float *t_p, *ln_p, *qkv_p, *attn_p, *h1_p;
    cudaGetSymbolAddress((void**)&t_p,    g_t);
    cudaGetSymbolAddress((void**)&ln_p,   g_ln);
    cudaGetSymbolAddress((void**)&qkv_p,  g_qkv);
    cudaGetSymbolAddress((void**)&attn_p, g_attn);
    cudaGetSymbolAddress((void**)&h1_p,   g_h1);

    int attn_smem = (198*KSTRIDE + 196*KSTRIDE + 8*8*PSTRIDE) * (int)sizeof(float);
    cudaFuncSetAttribute(attn_kernel, cudaFuncAttributeMaxDynamicSharedMemorySize, attn_smem);

    dim3 tb(16, 16);
    dim3 tg(W_/16, C_/16, B_*D_*H_);

    // 1. transpose in
    t_in_kernel<<<tg, tb>>>(x, t_p);
    // 2. LN1
    ln_kernel<<<NTOK, 128>>>(t_p, n1w, n1b, ln_p);
    // 3. qkv = ln1 @ qkv_w^T + b
    gemm_kernel<0><<<dim3(384/64, NTOK/64), 256>>>(ln_p, qkv_w, qkv_b, qkv_p, NTOK, 384, 128);
    // 4. neighborhood attention (tiled)
    attn_kernel<<<dim3(36, NHEAD, B_*D_), 256, attn_smem>>>(qkv_p, rpb, attn_p);
    // 5. t += attn @ proj_w^T + b
    gemm_kernel<2><<<dim3(128/64, NTOK/64), 256>>>(attn_p, proj_w, proj_b, t_p, NTOK, 128, 128);
    // 6. LN2
    ln_kernel<<<NTOK, 128>>>(t_p, n2w, n2b, ln_p);
    // 7. h1 = gelu(ln2 @ fc1_w^T + b)
    gemm_kernel<1><<<dim3(256/64, NTOK/64), 256>>>(ln_p, fc1_w, fc1_b, h1_p, NTOK, 256, 128);
    // 8. t += h1 @ fc2_w^T + b
    gemm_kernel<2><<<dim3(128/64, NTOK/64), 256>>>(h1_p, fc2_w, fc2_b, t_p, NTOK, 128, 256);
    // 9. transpose out
    t_out_kernel<<<tg, tb>>>(t_p, out);
}

// round 4
// speedup vs baseline: 1.4797x; 1.1709x over previous
#include <cuda_runtime.h>
#include <math.h>
#include <stdint.h>

// Problem constants
#define B_  2
#define C_  128
#define D_  4
#define H_  48
#define W_  48
#define NTOK (B_*D_*H_*W_)   // 18432
#define NHEAD 4
#define HD 32
#define KW 7

// Scratch (device globals — no allocation allowed)
__device__ float g_t   [NTOK*128];
__device__ float g_ln  [NTOK*128];
__device__ float g_qkv [NTOK*384];
__device__ float g_attn[NTOK*128];
__device__ float g_h1  [NTOK*256];

// ===========================================================================
// Warp-level tf32 MMA helpers (m16n8k8), 3xTF32 splitting for fp32 accuracy
// ===========================================================================
__device__ __forceinline__ void mma_tf32(float* c, const uint32_t* a, const uint32_t* b) {
    asm volatile(
        "mma.sync.aligned.m16n8k8.row.col.f32.tf32.tf32.f32 "
        "{%0,%1,%2,%3}, {%4,%5,%6,%7}, {%8,%9}, {%0,%1,%2,%3};"
        : "+f"(c[0]), "+f"(c[1]), "+f"(c[2]), "+f"(c[3])
        : "r"(a[0]), "r"(a[1]), "r"(a[2]), "r"(a[3]), "r"(b[0]), "r"(b[1]));
}

__device__ __forceinline__ void tf32_split(float x, uint32_t& hi, uint32_t& lo) {
    asm("cvt.rna.tf32.f32 %0, %1;" : "=r"(hi) : "f"(x));
    float l = x - __uint_as_float(hi);
    asm("cvt.rna.tf32.f32 %0, %1;" : "=r"(lo) : "f"(l));
}

// ===========================================================================
// Tensor-core GEMM: out[NTOK,M] = A[NTOK,K] @ W[M,K]^T + bias (+epilogue)
// Block = 256 thr (8 warps): 128 tokens x 64 out cols. Warp = 32x32.
// EPI: 0 bias, 1 bias+GELU, 2 bias+residual-add into out.
// ===========================================================================
#define ASTR 36

template<int EPI>
__global__ void __launch_bounds__(256, 2)
gemm_mma_kernel(const float* __restrict__ A,
                const float* __restrict__ Wt,
                const float* __restrict__ bias,
                float* __restrict__ out,
                int M, int K) {
    __shared__ float As[128 * ASTR];
    __shared__ float Bs[64 * ASTR];

    int tid = threadIdx.x;
    int wid = tid >> 5, lane = tid & 31;
    int warp_m = wid & 3;       // token group of 32
    int warp_n = wid >> 2;      // col group of 32
    int gid = lane >> 2;        // 0..7
    int tig = lane & 3;         // 0..3

    int n0 = blockIdx.y * 128;
    int m0 = blockIdx.x * 64;

    float acc[2][4][4];
    #pragma unroll
    for (int mt = 0; mt < 2; mt++)
        #pragma unroll
        for (int nt = 0; nt < 4; nt++)
            #pragma unroll
            for (int i = 0; i < 4; i++) acc[mt][nt][i] = 0.f;

    for (int k0 = 0; k0 < K; k0 += 32) {
        // Stage A: 128 rows x 32 cols (1024 float4)
        #pragma unroll
        for (int i = 0; i < 4; i++) {
            int idx = i * 256 + tid;
            int row = idx >> 3, c4 = idx & 7;
            float4 v = *reinterpret_cast<const float4*>(A + (long)(n0 + row) * K + k0 + c4 * 4);
            *reinterpret_cast<float4*>(&As[row * ASTR + c4 * 4]) = v;
        }
        // Stage B: 64 rows x 32 cols (512 float4)
        #pragma unroll
        for (int i = 0; i < 2; i++) {
            int idx = i * 256 + tid;
            int row = idx >> 3, c4 = idx & 7;
            float4 v = *reinterpret_cast<const float4*>(Wt + (long)(m0 + row) * K + k0 + c4 * 4);
            *reinterpret_cast<float4*>(&Bs[row * ASTR + c4 * 4]) = v;
        }
        __syncthreads();

        #pragma unroll
        for (int ks = 0; ks < 4; ks++) {
            int kk = ks * 8;
            // A fragments (2 m-tiles)
            uint32_t ahi[2][4], alo[2][4];
            #pragma unroll
            for (int mt = 0; mt < 2; mt++) {
                int r = warp_m * 32 + mt * 16 + gid;
                int c = kk + tig;
                float a0 = As[r * ASTR + c];
                float a1 = As[(r + 8) * ASTR + c];
                float a2 = As[r * ASTR + c + 4];
                float a3 = As[(r + 8) * ASTR + c + 4];
                tf32_split(a0, ahi[mt][0], alo[mt][0]);
                tf32_split(a1, ahi[mt][1], alo[mt][1]);
                tf32_split(a2, ahi[mt][2], alo[mt][2]);
                tf32_split(a3, ahi[mt][3], alo[mt][3]);
            }
            // B fragments (4 n-tiles)
            uint32_t bhi[4][2], blo[4][2];
            #pragma unroll
            for (int nt = 0; nt < 4; nt++) {
                int mr = warp_n * 32 + nt * 8 + gid;
                int c = kk + tig;
                float b0 = Bs[mr * ASTR + c];
                float b1 = Bs[mr * ASTR + c + 4];
                tf32_split(b0, bhi[nt][0], blo[nt][0]);
                tf32_split(b1, bhi[nt][1], blo[nt][1]);
            }
            #pragma unroll
            for (int mt = 0; mt < 2; mt++)
                #pragma unroll
                for (int nt = 0; nt < 4; nt++) {
                    mma_tf32(acc[mt][nt], ahi[mt], bhi[nt]);
                    mma_tf32(acc[mt][nt], ahi[mt], blo[nt]);
                    mma_tf32(acc[mt][nt], alo[mt], bhi[nt]);
                }
        }
        __syncthreads();
    }

    // Epilogue
    int row_base = n0 + warp_m * 32;
    int col_base = m0 + warp_n * 32;
    #pragma unroll
    for (int nt = 0; nt < 4; nt++) {
        int col = col_base + nt * 8 + 2 * tig;
        float b0 = bias[col], b1 = bias[col + 1];
        #pragma unroll
        for (int mt = 0; mt < 2; mt++) {
            #pragma unroll
            for (int half = 0; half < 2; half++) {
                int r = row_base + mt * 16 + gid + half * 8;
                float v0 = acc[mt][nt][half * 2 + 0] + b0;
                float v1 = acc[mt][nt][half * 2 + 1] + b1;
                if (EPI == 1) {
                    v0 = 0.5f * v0 * (1.0f + erff(v0 * 0.70710678118654752f));
                    v1 = 0.5f * v1 * (1.0f + erff(v1 * 0.70710678118654752f));
                }
                float2* dst = reinterpret_cast<float2*>(out + (long)r * M + col);
                if (EPI == 2) {
                    float2 old = *dst;
                    v0 += old.x; v1 += old.y;
                }
                float2 st; st.x = v0; st.y = v1;
                *dst = st;
            }
        }
    }
}

// ---------------------------------------------------------------------------
// Transpose in: x (B,C,D,H,W) -> t (N=B*D*H*W, C)
// ---------------------------------------------------------------------------
__global__ void t_in_kernel(const float* __restrict__ x, float* __restrict__ t) {
    __shared__ float sm[16][17];
    int bz = blockIdx.z;
    int b = bz / (D_*H_);
    int rem = bz % (D_*H_);
    int d = rem / H_;
    int h = rem % H_;
    int w = blockIdx.x*16 + threadIdx.x;
    int c = blockIdx.y*16 + threadIdx.y;
    sm[threadIdx.y][threadIdx.x] =
        x[(( (long)b*C_ + c)*D_ + d)*(H_*W_) + h*W_ + w];
    __syncthreads();
    int c2 = blockIdx.y*16 + threadIdx.x;
    int w2 = blockIdx.x*16 + threadIdx.y;
    t[((((b*D_ + d)*H_ + h)*W_ + w2) * (long)C_) + c2] = sm[threadIdx.x][threadIdx.y];
}

// ---------------------------------------------------------------------------
// Transpose out: t (N, C) -> out (B,C,D,H,W)
// ---------------------------------------------------------------------------
__global__ void t_out_kernel(const float* __restrict__ t, float* __restrict__ out) {
    __shared__ float sm[16][17];
    int bz = blockIdx.z;
    int b = bz / (D_*H_);
    int rem = bz % (D_*H_);
    int d = rem / H_;
    int h = rem % H_;
    int w_l = blockIdx.x*16 + threadIdx.y;
    int c_l = blockIdx.y*16 + threadIdx.x;
    sm[threadIdx.y][threadIdx.x] =
        t[((((b*D_ + d)*H_ + h)*W_ + w_l) * (long)C_) + c_l];
    __syncthreads();
    int c_s = blockIdx.y*16 + threadIdx.y;
    int w_s = blockIdx.x*16 + threadIdx.x;
    out[(((long)b*C_ + c_s)*D_ + d)*(H_*W_) + h*W_ + w_s] = sm[threadIdx.x][threadIdx.y];
}

// ---------------------------------------------------------------------------
// LayerNorm over C=128
// ---------------------------------------------------------------------------
__global__ void ln_kernel(const float* __restrict__ in,
                          const float* __restrict__ w,
                          const float* __restrict__ b,
                          float* __restrict__ out) {
    int n = blockIdx.x;
    int tid = threadIdx.x;
    float v = in[(long)n*128 + tid];
    float s = v, s2 = v*v;
    #pragma unroll
    for (int o = 16; o > 0; o >>= 1) {
        s  += __shfl_xor_sync(0xffffffffu, s,  o);
        s2 += __shfl_xor_sync(0xffffffffu, s2, o);
    }
    __shared__ float sh[8];
    int warp = tid >> 5, lane = tid & 31;
    if (lane == 0) { sh[warp] = s; sh[4+warp] = s2; }
    __syncthreads();
    s  = sh[0]+sh[1]+sh[2]+sh[3];
    s2 = sh[4]+sh[5]+sh[6]+sh[7];
    float m   = s  * (1.0f/128.0f);
    float var = s2 * (1.0f/128.0f) - m*m;
    float inv = rsqrtf(var + 1e-5f);
    out[(long)n*128 + tid] = (v - m) * inv * w[tid] + b[tid];
}

// ---------------------------------------------------------------------------
// Neighborhood attention, tiled (same as R2)
// ---------------------------------------------------------------------------
#define KSTRIDE 36
#define PSTRIDE 113

__global__ void __launch_bounds__(256, 2)
attn_kernel(const float* __restrict__ qkv,
            const float* __restrict__ rpb,
            float* __restrict__ attn_out) {
    extern __shared__ float smemf[];
    float* Ks = smemf;
    float* Vs = Ks + 198*KSTRIDE;
    float* Ps = Vs + 196*KSTRIDE;

    int tile = blockIdx.x;
    int head = blockIdx.y;
    int bd   = blockIdx.z;
    int h0 = (tile / 6) * 8;
    int w0 = (tile % 6) * 8;
    int kh0 = min(max(h0-3, 0), H_-KW);
    int kw0 = min(max(w0-3, 0), W_-KW);

    int tid = threadIdx.x;

    for (int e = tid; e < 196*8; e += 256) {
        int rowi = e >> 3, d4 = e & 7;
        int rr = rowi / 14, cc = rowi % 14;
        int gh = min(kh0 + rr, H_-1);
        int gw = min(kw0 + cc, W_-1);
        long tok = ((long)(bd*H_ + gh))*W_ + gw;
        const float* base = qkv + tok*384 + head*32 + d4*4;
        float4 kv = *reinterpret_cast<const float4*>(base + 128);
        float4 vv = *reinterpret_cast<const float4*>(base + 256);
        *reinterpret_cast<float4*>(&Ks[rowi*KSTRIDE + d4*4]) = kv;
        *reinterpret_cast<float4*>(&Vs[rowi*KSTRIDE + d4*4]) = vv;
    }
    __syncthreads();

    int warp = tid >> 5, lane = tid & 31;
    int q  = lane >> 2;
    int kg = lane & 3;
    int r  = warp;

    int h = h0 + r, w = w0 + q;
    int sh = min(max(h-3, 0), H_-KW);
    int sw = min(max(w-3, 0), W_-KW);
    int rel_h = sh - kh0;
    int ws    = sw - kw0;
    long tok = ((long)(bd*H_ + h))*W_ + w;

    const float scale = 0.17677669529663687f;
    float4 Q[8];
    #pragma unroll
    for (int i = 0; i < 8; i++) {
        float4 qv = *reinterpret_cast<const float4*>(qkv + tok*384 + head*32 + i*4);
        qv.x *= scale; qv.y *= scale; qv.z *= scale; qv.w *= scale;
        Q[i] = qv;
    }

    float s[28];
    #pragma unroll
    for (int o = 0; o < 7; o++) {
        int krow = rel_h + o;
        float a0 = 0.f, a1 = 0.f, a2 = 0.f, a3 = 0.f;
        const float* kb = &Ks[(krow*14 + kg)*KSTRIDE];
        #pragma unroll
        for (int d4 = 0; d4 < 8; d4++) {
            float4 qv = Q[d4];
            float4 k0 = *reinterpret_cast<const float4*>(kb +  0*KSTRIDE + d4*4);
            float4 k1 = *reinterpret_cast<const float4*>(kb +  4*KSTRIDE + d4*4);
            float4 k2 = *reinterpret_cast<const float4*>(kb +  8*KSTRIDE + d4*4);
            float4 k3 = *reinterpret_cast<const float4*>(kb + 12*KSTRIDE + d4*4);
            a0 += qv.x*k0.x + qv.y*k0.y + qv.z*k0.z + qv.w*k0.w;
            a1 += qv.x*k1.x + qv.y*k1.y + qv.z*k1.z + qv.w*k1.w;
            a2 += qv.x*k2.x + qv.y*k2.y + qv.z*k2.z + qv.w*k2.w;
            a3 += qv.x*k3.x + qv.y*k3.y + qv.z*k3.z + qv.w*k3.w;
        }
        s[o*4+0] = a0; s[o*4+1] = a1; s[o*4+2] = a2; s[o*4+3] = a3;
    }

    int bh_base = sh - h + 6;
    int bw_base = kw0 - w + 6;
    float mx = -1e30f;
    #pragma unroll
    for (int o = 0; o < 7; o++) {
        #pragma unroll
        for (int cc = 0; cc < 4; cc++) {
            int c = kg + cc*4;
            float v;
            if (c >= ws && c <= ws+6)
                v = s[o*4+cc] + __ldg(&rpb[head*169 + (bh_base+o)*13 + (bw_base+c)]);
            else
                v = -1e30f;
            s[o*4+cc] = v;
            mx = fmaxf(mx, v);
        }
    }
    mx = fmaxf(mx, __shfl_xor_sync(0xffffffffu, mx, 1));
    mx = fmaxf(mx, __shfl_xor_sync(0xffffffffu, mx, 2));
    float sum = 0.f;
    #pragma unroll
    for (int j = 0; j < 28; j++) {
        float e = __expf(s[j] - mx);
        s[j] = e;
        sum += e;
    }
    sum += __shfl_xor_sync(0xffffffffu, sum, 1);
    sum += __shfl_xor_sync(0xffffffffu, sum, 2);
    float inv = 1.0f / sum;

    float* Pw = &Ps[(r*8 + q)*PSTRIDE];
    #pragma unroll
    for (int o = 0; o < 7; o++)
        #pragma unroll
        for (int cc = 0; cc < 4; cc++)
            Pw[o*16 + kg + cc*4] = s[o*4+cc] * inv;
    __syncwarp();

    int dg = lane & 3;
    float4 acc0 = make_float4(0.f,0.f,0.f,0.f);
    float4 acc1 = make_float4(0.f,0.f,0.f,0.f);
    const float* Pr = &Ps[(r*8 + q)*PSTRIDE];
    #pragma unroll
    for (int o = 0; o < 7; o++) {
        int krow = rel_h + o;
        #pragma unroll
        for (int c = 0; c < 14; c++) {
            float p = Pr[o*16 + c];
            const float* vp = &Vs[(krow*14 + c)*KSTRIDE + dg*8];
            float4 v0 = *reinterpret_cast<const float4*>(vp);
            float4 v1 = *reinterpret_cast<const float4*>(vp + 4);
            acc0.x += p*v0.x; acc0.y += p*v0.y; acc0.z += p*v0.z; acc0.w += p*v0.w;
            acc1.x += p*v1.x; acc1.y += p*v1.y; acc1.z += p*v1.z; acc1.w += p*v1.w;
        }
    }
    float* op = attn_out + tok*128 + head*32 + dg*8;
    *reinterpret_cast<float4*>(op)     = acc0;
    *reinterpret_cast<float4*>(op + 4) = acc1;
}

// ---------------------------------------------------------------------------
// Launch
// ---------------------------------------------------------------------------
extern "C" void kernel_launch(void* const* d_in, const int* in_sizes, int n_in,
                              void* d_out, int out_size) {
    const float* x      = (const float*)d_in[0];
    const float* n1w    = (const float*)d_in[1];
    const float* n1b    = (const float*)d_in[2];
    const float* qkv_w  = (const float*)d_in[3];
    const float* qkv_b  = (const float*)d_in[4];
    const float* rpb    = (const float*)d_in[5];
    const float* proj_w = (const float*)d_in[6];
    const float* proj_b = (const float*)d_in[7];
    const float* n2w    = (const float*)d_in[8];
    const float* n2b    = (const float*)d_in[9];
    const float* fc1_w  = (const float*)d_in[10];
    const float* fc1_b  = (const float*)d_in[11];
    const float* fc2_w  = (const float*)d_in[12];
    const float* fc2_b  = (const float*)d_in[13];
    float* out = (float*)d_out;

    float *t_p, *ln_p, *qkv_p, *attn_p, *h1_p;
    cudaGetSymbolAddress((void**)&t_p,    g_t);
    cudaGetSymbolAddress((void**)&ln_p,   g_ln);
    cudaGetSymbolAddress((void**)&qkv_p,  g_qkv);
    cudaGetSymbolAddress((void**)&attn_p, g_attn);
    cudaGetSymbolAddress((void**)&h1_p,   g_h1);

    int attn_smem = (198*KSTRIDE + 196*KSTRIDE + 8*8*PSTRIDE) * (int)sizeof(float);
    cudaFuncSetAttribute(attn_kernel, cudaFuncAttributeMaxDynamicSharedMemorySize, attn_smem);

    dim3 tb(16, 16);
    dim3 tg(W_/16, C_/16, B_*D_*H_);

    // 1. transpose in
    t_in_kernel<<<tg, tb>>>(x, t_p);
    // 2. LN1
    ln_kernel<<<NTOK, 128>>>(t_p, n1w, n1b, ln_p);
    // 3. qkv = ln1 @ qkv_w^T + b   (M=384, K=128)
    gemm_mma_kernel<0><<<dim3(384/64, NTOK/128), 256>>>(ln_p, qkv_w, qkv_b, qkv_p, 384, 128);
    // 4. neighborhood attention (tiled)
    attn_kernel<<<dim3(36, NHEAD, B_*D_), 256, attn_smem>>>(qkv_p, rpb, attn_p);
    // 5. t += attn @ proj_w^T + b  (M=128, K=128)
    gemm_mma_kernel<2><<<dim3(128/64, NTOK/128), 256>>>(attn_p, proj_w, proj_b, t_p, 128, 128);
    // 6. LN2
    ln_kernel<<<NTOK, 128>>>(t_p, n2w, n2b, ln_p);
    // 7. h1 = gelu(ln2 @ fc1_w^T + b)  (M=256, K=128)
    gemm_mma_kernel<1><<<dim3(256/64, NTOK/128), 256>>>(ln_p, fc1_w, fc1_b, h1_p, 256, 128);
    // 8. t += h1 @ fc2_w^T + b     (M=128, K=256)
    gemm_mma_kernel<2><<<dim3(128/64, NTOK/128), 256>>>(h1_p, fc2_w, fc2_b, t_p, 128, 256);
    // 9. transpose out
    t_out_kernel<<<tg, tb>>>(t_p, out);
}

// round 5
// speedup vs baseline: 1.6104x; 1.0883x over previous
#include <cuda_runtime.h>
#include <math.h>
#include <stdint.h>

// Problem constants
#define B_  2
#define C_  128
#define D_  4
#define H_  48
#define W_  48
#define NTOK (B_*D_*H_*W_)   // 18432
#define NHEAD 4
#define HD 32
#define KW 7

// Scratch (device globals — no allocation allowed)
__device__ float g_t   [NTOK*128];
__device__ float g_ln  [NTOK*128];
__device__ float g_qkv [NTOK*384];
__device__ float g_attn[NTOK*128];
__device__ float g_h1  [NTOK*256];

// ===========================================================================
// Warp-level tf32 MMA helpers (m16n8k8), 3xTF32 splitting for fp32 accuracy
// ===========================================================================
__device__ __forceinline__ void mma_tf32(float* c, const uint32_t* a, const uint32_t* b) {
    asm volatile(
        "mma.sync.aligned.m16n8k8.row.col.f32.tf32.tf32.f32 "
        "{%0,%1,%2,%3}, {%4,%5,%6,%7}, {%8,%9}, {%0,%1,%2,%3};"
        : "+f"(c[0]), "+f"(c[1]), "+f"(c[2]), "+f"(c[3])
        : "r"(a[0]), "r"(a[1]), "r"(a[2]), "r"(a[3]), "r"(b[0]), "r"(b[1]));
}

__device__ __forceinline__ void tf32_split(float x, uint32_t& hi, uint32_t& lo) {
    asm("cvt.rna.tf32.f32 %0, %1;" : "=r"(hi) : "f"(x));
    float l = x - __uint_as_float(hi);
    asm("cvt.rna.tf32.f32 %0, %1;" : "=r"(lo) : "f"(l));
}

// ===========================================================================
// Tensor-core GEMM: out[NTOK,M] = A[NTOK,K] @ W[M,K]^T + bias (+epilogue)
// Block = 256 thr (8 warps): 128 tokens x 64 out cols. Warp = 32x32.
// EPI: 0 bias, 1 bias+GELU, 2 bias+residual-add into out.
// ===========================================================================
#define ASTR 36

template<int EPI>
__global__ void __launch_bounds__(256, 2)
gemm_mma_kernel(const float* __restrict__ A,
                const float* __restrict__ Wt,
                const float* __restrict__ bias,
                float* __restrict__ out,
                int M, int K) {
    __shared__ float As[128 * ASTR];
    __shared__ float Bs[64 * ASTR];

    int tid = threadIdx.x;
    int wid = tid >> 5, lane = tid & 31;
    int warp_m = wid & 3;
    int warp_n = wid >> 2;
    int gid = lane >> 2;
    int tig = lane & 3;

    int n0 = blockIdx.y * 128;
    int m0 = blockIdx.x * 64;

    float acc[2][4][4];
    #pragma unroll
    for (int mt = 0; mt < 2; mt++)
        #pragma unroll
        for (int nt = 0; nt < 4; nt++)
            #pragma unroll
            for (int i = 0; i < 4; i++) acc[mt][nt][i] = 0.f;

    for (int k0 = 0; k0 < K; k0 += 32) {
        #pragma unroll
        for (int i = 0; i < 4; i++) {
            int idx = i * 256 + tid;
            int row = idx >> 3, c4 = idx & 7;
            float4 v = *reinterpret_cast<const float4*>(A + (long)(n0 + row) * K + k0 + c4 * 4);
            *reinterpret_cast<float4*>(&As[row * ASTR + c4 * 4]) = v;
        }
        #pragma unroll
        for (int i = 0; i < 2; i++) {
            int idx = i * 256 + tid;
            int row = idx >> 3, c4 = idx & 7;
            float4 v = *reinterpret_cast<const float4*>(Wt + (long)(m0 + row) * K + k0 + c4 * 4);
            *reinterpret_cast<float4*>(&Bs[row * ASTR + c4 * 4]) = v;
        }
        __syncthreads();

        #pragma unroll
        for (int ks = 0; ks < 4; ks++) {
            int kk = ks * 8;
            uint32_t ahi[2][4], alo[2][4];
            #pragma unroll
            for (int mt = 0; mt < 2; mt++) {
                int r = warp_m * 32 + mt * 16 + gid;
                int c = kk + tig;
                float a0 = As[r * ASTR + c];
                float a1 = As[(r + 8) * ASTR + c];
                float a2 = As[r * ASTR + c + 4];
                float a3 = As[(r + 8) * ASTR + c + 4];
                tf32_split(a0, ahi[mt][0], alo[mt][0]);
                tf32_split(a1, ahi[mt][1], alo[mt][1]);
                tf32_split(a2, ahi[mt][2], alo[mt][2]);
                tf32_split(a3, ahi[mt][3], alo[mt][3]);
            }
            uint32_t bhi[4][2], blo[4][2];
            #pragma unroll
            for (int nt = 0; nt < 4; nt++) {
                int mr = warp_n * 32 + nt * 8 + gid;
                int c = kk + tig;
                float b0 = Bs[mr * ASTR + c];
                float b1 = Bs[mr * ASTR + c + 4];
                tf32_split(b0, bhi[nt][0], blo[nt][0]);
                tf32_split(b1, bhi[nt][1], blo[nt][1]);
            }
            #pragma unroll
            for (int mt = 0; mt < 2; mt++)
                #pragma unroll
                for (int nt = 0; nt < 4; nt++) {
                    mma_tf32(acc[mt][nt], ahi[mt], bhi[nt]);
                    mma_tf32(acc[mt][nt], ahi[mt], blo[nt]);
                    mma_tf32(acc[mt][nt], alo[mt], bhi[nt]);
                }
        }
        __syncthreads();
    }

    int row_base = n0 + warp_m * 32;
    int col_base = m0 + warp_n * 32;
    #pragma unroll
    for (int nt = 0; nt < 4; nt++) {
        int col = col_base + nt * 8 + 2 * tig;
        float b0 = bias[col], b1 = bias[col + 1];
        #pragma unroll
        for (int mt = 0; mt < 2; mt++) {
            #pragma unroll
            for (int half = 0; half < 2; half++) {
                int r = row_base + mt * 16 + gid + half * 8;
                float v0 = acc[mt][nt][half * 2 + 0] + b0;
                float v1 = acc[mt][nt][half * 2 + 1] + b1;
                if (EPI == 1) {
                    v0 = 0.5f * v0 * (1.0f + erff(v0 * 0.70710678118654752f));
                    v1 = 0.5f * v1 * (1.0f + erff(v1 * 0.70710678118654752f));
                }
                float2* dst = reinterpret_cast<float2*>(out + (long)r * M + col);
                if (EPI == 2) {
                    float2 old = *dst;
                    v0 += old.x; v1 += old.y;
                }
                float2 st; st.x = v0; st.y = v1;
                *dst = st;
            }
        }
    }
}

// ===========================================================================
// Tensor-core neighborhood attention.
// grid = (36 tiles of 8x8 queries, NHEAD, B*D); block = 128 (4 warps).
// Warp = 16 queries (2 tile rows). Banded 120-key window per warp (15 n-tiles)
// out of a 14x14 (padded to 224) staged K/V window. 3xTF32 mma for QK and PV.
// ===========================================================================
#define NKP 224
#define KST 36
#define VST 228
#define PST 132

__global__ void __launch_bounds__(128, 2)
attn_mma_kernel(const float* __restrict__ qkv,
                const float* __restrict__ rpb,
                float* __restrict__ attn_out) {
    extern __shared__ float smf[];
    float* Ks = smf;                    // [224][36]  K (key-major, dim cols)
    float* Vt = Ks + NKP*KST;           // [32][228]  V transposed (dim-major)
    float* Ps = Vt + 32*VST;            // [4][16][132] per-warp P
    float* rb = Ps + 4*16*PST;          // [169] rpb for this head

    int tile = blockIdx.x, head = blockIdx.y, bd = blockIdx.z;
    int h0 = (tile / 6) * 8;
    int w0 = (tile % 6) * 8;
    int kh0 = min(max(h0 - 3, 0), H_ - KW);
    int kw0 = min(max(w0 - 3, 0), W_ - KW);
    int tid = threadIdx.x;

    // ---- Stage K (key-major) and V^T (dim-major); clamp out-of-image reads
    for (int e = tid; e < 196*8; e += 128) {
        int key = e >> 3, d4 = e & 7;
        int kr = key / 14, kc = key % 14;
        int gh = min(kh0 + kr, H_-1);
        int gw = min(kw0 + kc, W_-1);
        const float* base = qkv + ((long)(bd*H_ + gh)*W_ + gw)*384 + head*32 + d4*4;
        float4 k4 = *reinterpret_cast<const float4*>(base + 128);
        float4 v4 = *reinterpret_cast<const float4*>(base + 256);
        *reinterpret_cast<float4*>(&Ks[key*KST + d4*4]) = k4;
        Vt[(d4*4+0)*VST + key] = v4.x;
        Vt[(d4*4+1)*VST + key] = v4.y;
        Vt[(d4*4+2)*VST + key] = v4.z;
        Vt[(d4*4+3)*VST + key] = v4.w;
    }
    // zero pad keys 196..223
    for (int e = tid; e < 28*8; e += 128) {
        int key = 196 + (e >> 3), d4 = e & 7;
        *reinterpret_cast<float4*>(&Ks[key*KST + d4*4]) = make_float4(0.f,0.f,0.f,0.f);
    }
    for (int e = tid; e < 32*28; e += 128) {
        int d = e / 28, key = 196 + (e % 28);
        Vt[d*VST + key] = 0.f;
    }
    for (int i = tid; i < 169; i += 128) rb[i] = rpb[head*169 + i];
    __syncthreads();

    int warp = tid >> 5, lane = tid & 31;
    int gid = lane >> 2, tig = lane & 3;

    int hq0 = h0 + 2*warp;          // tile row of fragment rows gid
    int hq1 = hq0 + 1;              // tile row of fragment rows gid+8
    int wq  = w0 + gid;             // query column (per lane)
    long tok0 = (long)(bd*H_ + hq0)*W_ + wq;
    long tok1 = tok0 + W_;
    int rel0 = min(max(hq0-3, 0), H_-KW) - kh0;
    int rel1 = min(max(hq1-3, 0), H_-KW) - kh0;
    int ws   = min(max(wq-3, 0), W_-KW) - kw0;
    int n_base = ((min(rel0, rel1) * 14) >> 3) * 8;   // aligned window start

    // ---- Q fragments (scaled, 3x-split), held across all n-tiles
    const float scale = 0.17677669529663687f; // 32^-0.5
    uint32_t qhi[4][4], qlo[4][4];
    #pragma unroll
    for (int ks = 0; ks < 4; ks++) {
        float a0 = qkv[tok0*384 + head*32 + ks*8 + tig] * scale;
        float a1 = qkv[tok1*384 + head*32 + ks*8 + tig] * scale;
        float a2 = qkv[tok0*384 + head*32 + ks*8 + tig + 4] * scale;
        float a3 = qkv[tok1*384 + head*32 + ks*8 + tig + 4] * scale;
        tf32_split(a0, qhi[ks][0], qlo[ks][0]);
        tf32_split(a1, qhi[ks][1], qlo[ks][1]);
        tf32_split(a2, qhi[ks][2], qlo[ks][2]);
        tf32_split(a3, qhi[ks][3], qlo[ks][3]);
    }

    // ---- Scores: 15 n-tiles x 4 k-steps x 3 split
    float acc[15][4];
    #pragma unroll
    for (int nt = 0; nt < 15; nt++)
        #pragma unroll
        for (int i = 0; i < 4; i++) acc[nt][i] = 0.f;

    #pragma unroll
    for (int nt = 0; nt < 15; nt++) {
        int nrow = n_base + nt*8 + gid;
        #pragma unroll
        for (int ks = 0; ks < 4; ks++) {
            float b0 = Ks[nrow*KST + ks*8 + tig];
            float b1 = Ks[nrow*KST + ks*8 + tig + 4];
            uint32_t bh[2], bl[2];
            tf32_split(b0, bh[0], bl[0]);
            tf32_split(b1, bh[1], bl[1]);
            mma_tf32(acc[nt], qhi[ks], bh);
            mma_tf32(acc[nt], qhi[ks], bl);
            mma_tf32(acc[nt], qlo[ks], bh);
        }
    }

    // ---- Bias + mask + softmax (rows gid / gid+8; quad = same row)
    int bh0c = kh0 - hq0 + 6;
    int bh1c = kh0 - hq1 + 6;
    int bwc  = kw0 - wq + 6;
    float mx0 = -1e30f, mx1 = -1e30f;
    #pragma unroll
    for (int nt = 0; nt < 15; nt++) {
        #pragma unroll
        for (int cc = 0; cc < 2; cc++) {
            int n = n_base + nt*8 + 2*tig + cc;
            int kr = n / 14;
            int kc = n - kr*14;
            bool vw = (unsigned)(kc - ws) <= 6u;
            float bias = 0.f;
            bool v0 = vw && (unsigned)(kr - rel0) <= 6u;
            bool v1 = vw && (unsigned)(kr - rel1) <= 6u;
            if (vw) bias = rb[kr*13 + bwc + kc];   // row part added below
            float s0 = v0 ? acc[nt][cc]   + rb[(bh0c+kr)*13 + bwc + kc] : -1e30f;
            float s1 = v1 ? acc[nt][2+cc] + rb[(bh1c+kr)*13 + bwc + kc] : -1e30f;
            (void)bias;
            acc[nt][cc]   = s0;
            acc[nt][2+cc] = s1;
            mx0 = fmaxf(mx0, s0);
            mx1 = fmaxf(mx1, s1);
        }
    }
    mx0 = fmaxf(mx0, __shfl_xor_sync(0xffffffffu, mx0, 1));
    mx0 = fmaxf(mx0, __shfl_xor_sync(0xffffffffu, mx0, 2));
    mx1 = fmaxf(mx1, __shfl_xor_sync(0xffffffffu, mx1, 1));
    mx1 = fmaxf(mx1, __shfl_xor_sync(0xffffffffu, mx1, 2));

    float sum0 = 0.f, sum1 = 0.f;
    #pragma unroll
    for (int nt = 0; nt < 15; nt++) {
        #pragma unroll
        for (int cc = 0; cc < 2; cc++) {
            float e0 = __expf(acc[nt][cc]   - mx0);
            float e1 = __expf(acc[nt][2+cc] - mx1);
            acc[nt][cc]   = e0;
            acc[nt][2+cc] = e1;
            sum0 += e0;
            sum1 += e1;
        }
    }
    sum0 += __shfl_xor_sync(0xffffffffu, sum0, 1);
    sum0 += __shfl_xor_sync(0xffffffffu, sum0, 2);
    sum1 += __shfl_xor_sync(0xffffffffu, sum1, 1);
    sum1 += __shfl_xor_sync(0xffffffffu, sum1, 2);
    float inv0 = 1.0f / sum0;
    float inv1 = 1.0f / sum1;

    // ---- Write P (unnormalized) to per-warp smem
    float* Pw = Ps + warp * 16 * PST;
    #pragma unroll
    for (int nt = 0; nt < 15; nt++) {
        int c = nt*8 + 2*tig;
        Pw[gid*PST + c]       = acc[nt][0];
        Pw[gid*PST + c + 1]   = acc[nt][1];
        Pw[(gid+8)*PST + c]     = acc[nt][2];
        Pw[(gid+8)*PST + c + 1] = acc[nt][3];
    }
    __syncwarp();

    // ---- AV: 15 k-tiles x 4 n-tiles (dims) x 3 split
    float o[4][4];
    #pragma unroll
    for (int nt = 0; nt < 4; nt++)
        #pragma unroll
        for (int i = 0; i < 4; i++) o[nt][i] = 0.f;

    #pragma unroll
    for (int kt = 0; kt < 15; kt++) {
        float a0 = Pw[gid*PST + kt*8 + tig];
        float a1 = Pw[(gid+8)*PST + kt*8 + tig];
        float a2 = Pw[gid*PST + kt*8 + tig + 4];
        float a3 = Pw[(gid+8)*PST + kt*8 + tig + 4];
        uint32_t ph[4], pl[4];
        tf32_split(a0, ph[0], pl[0]);
        tf32_split(a1, ph[1], pl[1]);
        tf32_split(a2, ph[2], pl[2]);
        tf32_split(a3, ph[3], pl[3]);
        int kg = n_base + kt*8;
        #pragma unroll
        for (int nt = 0; nt < 4; nt++) {
            float b0 = Vt[(nt*8+gid)*VST + kg + tig];
            float b1 = Vt[(nt*8+gid)*VST + kg + tig + 4];
            uint32_t vh[2], vl[2];
            tf32_split(b0, vh[0], vl[0]);
            tf32_split(b1, vh[1], vl[1]);
            mma_tf32(o[nt], ph, vh);
            mma_tf32(o[nt], ph, vl);
            mma_tf32(o[nt], pl, vh);
        }
    }

    // ---- Output (normalize per row)
    #pragma unroll
    for (int nt = 0; nt < 4; nt++) {
        int d = head*32 + nt*8 + 2*tig;
        float2 s0; s0.x = o[nt][0]*inv0; s0.y = o[nt][1]*inv0;
        float2 s1; s1.x = o[nt][2]*inv1; s1.y = o[nt][3]*inv1;
        *reinterpret_cast<float2*>(&attn_out[tok0*128 + d]) = s0;
        *reinterpret_cast<float2*>(&attn_out[tok1*128 + d]) = s1;
    }
}

// ---------------------------------------------------------------------------
// Transpose in: x (B,C,D,H,W) -> t (N=B*D*H*W, C)
// ---------------------------------------------------------------------------
__global__ void t_in_kernel(const float* __restrict__ x, float* __restrict__ t) {
    __shared__ float sm[16][17];
    int bz = blockIdx.z;
    int b = bz / (D_*H_);
    int rem = bz % (D_*H_);
    int d = rem / H_;
    int h = rem % H_;
    int w = blockIdx.x*16 + threadIdx.x;
    int c = blockIdx.y*16 + threadIdx.y;
    sm[threadIdx.y][threadIdx.x] =
        x[(( (long)b*C_ + c)*D_ + d)*(H_*W_) + h*W_ + w];
    __syncthreads();
    int c2 = blockIdx.y*16 + threadIdx.x;
    int w2 = blockIdx.x*16 + threadIdx.y;
    t[((((b*D_ + d)*H_ + h)*W_ + w2) * (long)C_) + c2] = sm[threadIdx.x][threadIdx.y];
}

// ---------------------------------------------------------------------------
// Transpose out: t (N, C) -> out (B,C,D,H,W)
// ---------------------------------------------------------------------------
__global__ void t_out_kernel(const float* __restrict__ t, float* __restrict__ out) {
    __shared__ float sm[16][17];
    int bz = blockIdx.z;
    int b = bz / (D_*H_);
    int rem = bz % (D_*H_);
    int d = rem / H_;
    int h = rem % H_;
    int w_l = blockIdx.x*16 + threadIdx.y;
    int c_l = blockIdx.y*16 + threadIdx.x;
    sm[threadIdx.y][threadIdx.x] =
        t[((((b*D_ + d)*H_ + h)*W_ + w_l) * (long)C_) + c_l];
    __syncthreads();
    int c_s = blockIdx.y*16 + threadIdx.y;
    int w_s = blockIdx.x*16 + threadIdx.x;
    out[(((long)b*C_ + c_s)*D_ + d)*(H_*W_) + h*W_ + w_s] = sm[threadIdx.x][threadIdx.y];
}

// ---------------------------------------------------------------------------
// LayerNorm over C=128
// ---------------------------------------------------------------------------
__global__ void ln_kernel(const float* __restrict__ in,
                          const float* __restrict__ w,
                          const float* __restrict__ b,
                          float* __restrict__ out) {
    int n = blockIdx.x;
    int tid = threadIdx.x;
    float v = in[(long)n*128 + tid];
    float s = v, s2 = v*v;
    #pragma unroll
    for (int o = 16; o > 0; o >>= 1) {
        s  += __shfl_xor_sync(0xffffffffu, s,  o);
        s2 += __shfl_xor_sync(0xffffffffu, s2, o);
    }
    __shared__ float sh[8];
    int warp = tid >> 5, lane = tid & 31;
    if (lane == 0) { sh[warp] = s; sh[4+warp] = s2; }
    __syncthreads();
    s  = sh[0]+sh[1]+sh[2]+sh[3];
    s2 = sh[4]+sh[5]+sh[6]+sh[7];
    float m   = s  * (1.0f/128.0f);
    float var = s2 * (1.0f/128.0f) - m*m;
    float inv = rsqrtf(var + 1e-5f);
    out[(long)n*128 + tid] = (v - m) * inv * w[tid] + b[tid];
}

// ---------------------------------------------------------------------------
// Launch
// ---------------------------------------------------------------------------
extern "C" void kernel_launch(void* const* d_in, const int* in_sizes, int n_in,
                              void* d_out, int out_size) {
    const float* x      = (const float*)d_in[0];
    const float* n1w    = (const float*)d_in[1];
    const float* n1b    = (const float*)d_in[2];
    const float* qkv_w  = (const float*)d_in[3];
    const float* qkv_b  = (const float*)d_in[4];
    const float* rpb    = (const float*)d_in[5];
    const float* proj_w = (const float*)d_in[6];
    const float* proj_b = (const float*)d_in[7];
    const float* n2w    = (const float*)d_in[8];
    const float* n2b    = (const float*)d_in[9];
    const float* fc1_w  = (const float*)d_in[10];
    const float* fc1_b  = (const float*)d_in[11];
    const float* fc2_w  = (const float*)d_in[12];
    const float* fc2_b  = (const float*)d_in[13];
    float* out = (float*)d_out;

    float *t_p, *ln_p, *qkv_p, *attn_p, *h1_p;
    cudaGetSymbolAddress((void**)&t_p,    g_t);
    cudaGetSymbolAddress((void**)&ln_p,   g_ln);
    cudaGetSymbolAddress((void**)&qkv_p,  g_qkv);
    cudaGetSymbolAddress((void**)&attn_p, g_attn);
    cudaGetSymbolAddress((void**)&h1_p,   g_h1);

    int attn_smem = (NKP*KST + 32*VST + 4*16*PST + 169) * (int)sizeof(float);
    cudaFuncSetAttribute(attn_mma_kernel, cudaFuncAttributeMaxDynamicSharedMemorySize, attn_smem);

    dim3 tb(16, 16);
    dim3 tg(W_/16, C_/16, B_*D_*H_);

    // 1. transpose in
    t_in_kernel<<<tg, tb>>>(x, t_p);
    // 2. LN1
    ln_kernel<<<NTOK, 128>>>(t_p, n1w, n1b, ln_p);
    // 3. qkv = ln1 @ qkv_w^T + b   (M=384, K=128)
    gemm_mma_kernel<0><<<dim3(384/64, NTOK/128), 256>>>(ln_p, qkv_w, qkv_b, qkv_p, 384, 128);
    // 4. neighborhood attention (tensor-core)
    attn_mma_kernel<<<dim3(36, NHEAD, B_*D_), 128, attn_smem>>>(qkv_p, rpb, attn_p);
    // 5. t += attn @ proj_w^T + b  (M=128, K=128)
    gemm_mma_kernel<2><<<dim3(128/64, NTOK/128), 256>>>(attn_p, proj_w, proj_b, t_p, 128, 128);
    // 6. LN2
    ln_kernel<<<NTOK, 128>>>(t_p, n2w, n2b, ln_p);
    // 7. h1 = gelu(ln2 @ fc1_w^T + b)  (M=256, K=128)
    gemm_mma_kernel<1><<<dim3(256/64, NTOK/128), 256>>>(ln_p, fc1_w, fc1_b, h1_p, 256, 128);
    // 8. t += h1 @ fc2_w^T + b     (M=128, K=256)
    gemm_mma_kernel<2><<<dim3(128/64, NTOK/128), 256>>>(h1_p, fc2_w, fc2_b, t_p, 128, 256);
    // 9. transpose out
    t_out_kernel<<<tg, tb>>>(t_p, out);
}

// round 6
// speedup vs baseline: 2.0039x; 1.2444x over previous
#include <cuda_runtime.h>
#include <cuda_bf16.h>
#include <math.h>
#include <stdint.h>

// Problem constants
#define B_  2
#define C_  128
#define D_  4
#define H_  48
#define W_  48
#define NTOK (B_*D_*H_*W_)   // 18432
#define NHEAD 4
#define HD 32
#define KW 7

// Scratch (device globals — no allocation allowed)
__device__ float g_t   [NTOK*128];
__device__ float g_ln  [NTOK*128];
__device__ float g_qkv [NTOK*384];
__device__ float g_attn[NTOK*128];
__device__ float g_h1  [NTOK*256];

// ===========================================================================
// Warp-level MMA helpers
// ===========================================================================
__device__ __forceinline__ void mma_tf32(float* c, const uint32_t* a, const uint32_t* b) {
    asm volatile(
        "mma.sync.aligned.m16n8k8.row.col.f32.tf32.tf32.f32 "
        "{%0,%1,%2,%3}, {%4,%5,%6,%7}, {%8,%9}, {%0,%1,%2,%3};"
        : "+f"(c[0]), "+f"(c[1]), "+f"(c[2]), "+f"(c[3])
        : "r"(a[0]), "r"(a[1]), "r"(a[2]), "r"(a[3]), "r"(b[0]), "r"(b[1]));
}

__device__ __forceinline__ void mma_bf16(float* c, const uint32_t* a, const uint32_t* b) {
    asm volatile(
        "mma.sync.aligned.m16n8k16.row.col.f32.bf16.bf16.f32 "
        "{%0,%1,%2,%3}, {%4,%5,%6,%7}, {%8,%9}, {%0,%1,%2,%3};"
        : "+f"(c[0]), "+f"(c[1]), "+f"(c[2]), "+f"(c[3])
        : "r"(a[0]), "r"(a[1]), "r"(a[2]), "r"(a[3]), "r"(b[0]), "r"(b[1]));
}

__device__ __forceinline__ void tf32_split(float x, uint32_t& hi, uint32_t& lo) {
    asm("cvt.rna.tf32.f32 %0, %1;" : "=r"(hi) : "f"(x));
    float l = x - __uint_as_float(hi);
    asm("cvt.rna.tf32.f32 %0, %1;" : "=r"(lo) : "f"(l));
}

// Split a float2 (consecutive k pair) into packed bf16x2 hi and lo registers.
// Low 16 bits hold the even-k element (mma fragment order).
__device__ __forceinline__ void bf16_split2(float x0, float x1, uint32_t& hi, uint32_t& lo) {
    __nv_bfloat162 h = __floats2bfloat162_rn(x0, x1);
    float h0 = __bfloat162float(h.x);
    float h1 = __bfloat162float(h.y);
    __nv_bfloat162 l = __floats2bfloat162_rn(x0 - h0, x1 - h1);
    hi = *reinterpret_cast<uint32_t*>(&h);
    lo = *reinterpret_cast<uint32_t*>(&l);
}

// ===========================================================================
// Tensor-core GEMM (bf16 3-term split, m16n8k16):
// out[NTOK,M] = A[NTOK,K] @ W[M,K]^T + bias (+epilogue)
// Block = 256 thr (8 warps): 128 tokens x 64 out cols. Warp = 32x32.
// hi/lo bf16x2 tiles pre-split in smem; inner loop = LDS + HMMA only.
// EPI: 0 bias, 1 bias+GELU, 2 bias+residual-add into out.
// ===========================================================================
#define GSTR 20   // uint32 row stride (16 data cols + pad); gid*20+tig is a bank permutation

template<int EPI>
__global__ void __launch_bounds__(256, 2)
gemm_mma_kernel(const float* __restrict__ A,
                const float* __restrict__ Wt,
                const float* __restrict__ bias,
                float* __restrict__ out,
                int M, int K) {
    __shared__ uint32_t AsH[128 * GSTR];
    __shared__ uint32_t AsL[128 * GSTR];
    __shared__ uint32_t BsH[64 * GSTR];
    __shared__ uint32_t BsL[64 * GSTR];

    int tid = threadIdx.x;
    int wid = tid >> 5, lane = tid & 31;
    int warp_m = wid & 3;
    int warp_n = wid >> 2;
    int gid = lane >> 2;
    int tig = lane & 3;

    int n0 = blockIdx.y * 128;
    int m0 = blockIdx.x * 64;

    float acc[2][4][4];
    #pragma unroll
    for (int mt = 0; mt < 2; mt++)
        #pragma unroll
        for (int nt = 0; nt < 4; nt++)
            #pragma unroll
            for (int i = 0; i < 4; i++) acc[mt][nt][i] = 0.f;

    for (int k0 = 0; k0 < K; k0 += 32) {
        // Stage A: 128 rows x 32 k -> split bf16 hi/lo packed pairs
        #pragma unroll
        for (int i = 0; i < 4; i++) {
            int idx = i * 256 + tid;
            int row = idx >> 3, c4 = idx & 7;
            float4 v = *reinterpret_cast<const float4*>(A + (long)(n0 + row) * K + k0 + c4 * 4);
            uint32_t h0, l0, h1, l1;
            bf16_split2(v.x, v.y, h0, l0);
            bf16_split2(v.z, v.w, h1, l1);
            int o = row * GSTR + c4 * 2;
            AsH[o] = h0; AsH[o + 1] = h1;
            AsL[o] = l0; AsL[o + 1] = l1;
        }
        // Stage B: 64 rows x 32 k
        #pragma unroll
        for (int i = 0; i < 2; i++) {
            int idx = i * 256 + tid;
            int row = idx >> 3, c4 = idx & 7;
            float4 v = *reinterpret_cast<const float4*>(Wt + (long)(m0 + row) * K + k0 + c4 * 4);
            uint32_t h0, l0, h1, l1;
            bf16_split2(v.x, v.y, h0, l0);
            bf16_split2(v.z, v.w, h1, l1);
            int o = row * GSTR + c4 * 2;
            BsH[o] = h0; BsH[o + 1] = h1;
            BsL[o] = l0; BsL[o + 1] = l1;
        }
        __syncthreads();

        #pragma unroll
        for (int ks = 0; ks < 2; ks++) {
            int jc = ks * 8;
            uint32_t ahi[2][4], alo[2][4];
            #pragma unroll
            for (int mt = 0; mt < 2; mt++) {
                int r = warp_m * 32 + mt * 16 + gid;
                int o0 = r * GSTR + jc + tig;
                int o1 = (r + 8) * GSTR + jc + tig;
                ahi[mt][0] = AsH[o0];     ahi[mt][1] = AsH[o1];
                ahi[mt][2] = AsH[o0 + 4]; ahi[mt][3] = AsH[o1 + 4];
                alo[mt][0] = AsL[o0];     alo[mt][1] = AsL[o1];
                alo[mt][2] = AsL[o0 + 4]; alo[mt][3] = AsL[o1 + 4];
            }
            uint32_t bhi[4][2], blo[4][2];
            #pragma unroll
            for (int nt = 0; nt < 4; nt++) {
                int br = warp_n * 32 + nt * 8 + gid;
                int o = br * GSTR + jc + tig;
                bhi[nt][0] = BsH[o]; bhi[nt][1] = BsH[o + 4];
                blo[nt][0] = BsL[o]; blo[nt][1] = BsL[o + 4];
            }
            #pragma unroll
            for (int mt = 0; mt < 2; mt++)
                #pragma unroll
                for (int nt = 0; nt < 4; nt++) {
                    mma_bf16(acc[mt][nt], ahi[mt], bhi[nt]);
                    mma_bf16(acc[mt][nt], alo[mt], bhi[nt]);
                    mma_bf16(acc[mt][nt], ahi[mt], blo[nt]);
                }
        }
        __syncthreads();
    }

    int row_base = n0 + warp_m * 32;
    int col_base = m0 + warp_n * 32;
    #pragma unroll
    for (int nt = 0; nt < 4; nt++) {
        int col = col_base + nt * 8 + 2 * tig;
        float b0 = bias[col], b1 = bias[col + 1];
        #pragma unroll
        for (int mt = 0; mt < 2; mt++) {
            #pragma unroll
            for (int half = 0; half < 2; half++) {
                int r = row_base + mt * 16 + gid + half * 8;
                float v0 = acc[mt][nt][half * 2 + 0] + b0;
                float v1 = acc[mt][nt][half * 2 + 1] + b1;
                if (EPI == 1) {
                    v0 = 0.5f * v0 * (1.0f + erff(v0 * 0.70710678118654752f));
                    v1 = 0.5f * v1 * (1.0f + erff(v1 * 0.70710678118654752f));
                }
                float2* dst = reinterpret_cast<float2*>(out + (long)r * M + col);
                if (EPI == 2) {
                    float2 old = *dst;
                    v0 += old.x; v1 += old.y;
                }
                float2 st; st.x = v0; st.y = v1;
                *dst = st;
            }
        }
    }
}

// ===========================================================================
// Tensor-core neighborhood attention (same as R5).
// ===========================================================================
#define NKP 224
#define KST 36
#define VST 228
#define PST 132

__global__ void __launch_bounds__(128, 2)
attn_mma_kernel(const float* __restrict__ qkv,
                const float* __restrict__ rpb,
                float* __restrict__ attn_out) {
    extern __shared__ float smf[];
    float* Ks = smf;                    // [224][36]  K (key-major, dim cols)
    float* Vt = Ks + NKP*KST;           // [32][228]  V transposed (dim-major)
    float* Ps = Vt + 32*VST;            // [4][16][132] per-warp P
    float* rb = Ps + 4*16*PST;          // [169] rpb for this head

    int tile = blockIdx.x, head = blockIdx.y, bd = blockIdx.z;
    int h0 = (tile / 6) * 8;
    int w0 = (tile % 6) * 8;
    int kh0 = min(max(h0 - 3, 0), H_ - KW);
    int kw0 = min(max(w0 - 3, 0), W_ - KW);
    int tid = threadIdx.x;

    for (int e = tid; e < 196*8; e += 128) {
        int key = e >> 3, d4 = e & 7;
        int kr = key / 14, kc = key % 14;
        int gh = min(kh0 + kr, H_-1);
        int gw = min(kw0 + kc, W_-1);
        const float* base = qkv + ((long)(bd*H_ + gh)*W_ + gw)*384 + head*32 + d4*4;
        float4 k4 = *reinterpret_cast<const float4*>(base + 128);
        float4 v4 = *reinterpret_cast<const float4*>(base + 256);
        *reinterpret_cast<float4*>(&Ks[key*KST + d4*4]) = k4;
        Vt[(d4*4+0)*VST + key] = v4.x;
        Vt[(d4*4+1)*VST + key] = v4.y;
        Vt[(d4*4+2)*VST + key] = v4.z;
        Vt[(d4*4+3)*VST + key] = v4.w;
    }
    for (int e = tid; e < 28*8; e += 128) {
        int key = 196 + (e >> 3), d4 = e & 7;
        *reinterpret_cast<float4*>(&Ks[key*KST + d4*4]) = make_float4(0.f,0.f,0.f,0.f);
    }
    for (int e = tid; e < 32*28; e += 128) {
        int d = e / 28, key = 196 + (e % 28);
        Vt[d*VST + key] = 0.f;
    }
    for (int i = tid; i < 169; i += 128) rb[i] = rpb[head*169 + i];
    __syncthreads();

    int warp = tid >> 5, lane = tid & 31;
    int gid = lane >> 2, tig = lane & 3;

    int hq0 = h0 + 2*warp;
    int hq1 = hq0 + 1;
    int wq  = w0 + gid;
    long tok0 = (long)(bd*H_ + hq0)*W_ + wq;
    long tok1 = tok0 + W_;
    int rel0 = min(max(hq0-3, 0), H_-KW) - kh0;
    int rel1 = min(max(hq1-3, 0), H_-KW) - kh0;
    int ws   = min(max(wq-3, 0), W_-KW) - kw0;
    int n_base = ((min(rel0, rel1) * 14) >> 3) * 8;

    const float scale = 0.17677669529663687f;
    uint32_t qhi[4][4], qlo[4][4];
    #pragma unroll
    for (int ks = 0; ks < 4; ks++) {
        float a0 = qkv[tok0*384 + head*32 + ks*8 + tig] * scale;
        float a1 = qkv[tok1*384 + head*32 + ks*8 + tig] * scale;
        float a2 = qkv[tok0*384 + head*32 + ks*8 + tig + 4] * scale;
        float a3 = qkv[tok1*384 + head*32 + ks*8 + tig + 4] * scale;
        tf32_split(a0, qhi[ks][0], qlo[ks][0]);
        tf32_split(a1, qhi[ks][1], qlo[ks][1]);
        tf32_split(a2, qhi[ks][2], qlo[ks][2]);
        tf32_split(a3, qhi[ks][3], qlo[ks][3]);
    }

    float acc[15][4];
    #pragma unroll
    for (int nt = 0; nt < 15; nt++)
        #pragma unroll
        for (int i = 0; i < 4; i++) acc[nt][i] = 0.f;

    #pragma unroll
    for (int nt = 0; nt < 15; nt++) {
        int nrow = n_base + nt*8 + gid;
        #pragma unroll
        for (int ks = 0; ks < 4; ks++) {
            float b0 = Ks[nrow*KST + ks*8 + tig];
            float b1 = Ks[nrow*KST + ks*8 + tig + 4];
            uint32_t bh[2], bl[2];
            tf32_split(b0, bh[0], bl[0]);
            tf32_split(b1, bh[1], bl[1]);
            mma_tf32(acc[nt], qhi[ks], bh);
            mma_tf32(acc[nt], qhi[ks], bl);
            mma_tf32(acc[nt], qlo[ks], bh);
        }
    }

    int bh0c = kh0 - hq0 + 6;
    int bh1c = kh0 - hq1 + 6;
    int bwc  = kw0 - wq + 6;
    float mx0 = -1e30f, mx1 = -1e30f;
    #pragma unroll
    for (int nt = 0; nt < 15; nt++) {
        #pragma unroll
        for (int cc = 0; cc < 2; cc++) {
            int n = n_base + nt*8 + 2*tig + cc;
            int kr = n / 14;
            int kc = n - kr*14;
            bool vw = (unsigned)(kc - ws) <= 6u;
            bool v0 = vw && (unsigned)(kr - rel0) <= 6u;
            bool v1 = vw && (unsigned)(kr - rel1) <= 6u;
            float s0 = v0 ? acc[nt][cc]   + rb[(bh0c+kr)*13 + bwc + kc] : -1e30f;
            float s1 = v1 ? acc[nt][2+cc] + rb[(bh1c+kr)*13 + bwc + kc] : -1e30f;
            acc[nt][cc]   = s0;
            acc[nt][2+cc] = s1;
            mx0 = fmaxf(mx0, s0);
            mx1 = fmaxf(mx1, s1);
        }
    }
    mx0 = fmaxf(mx0, __shfl_xor_sync(0xffffffffu, mx0, 1));
    mx0 = fmaxf(mx0, __shfl_xor_sync(0xffffffffu, mx0, 2));
    mx1 = fmaxf(mx1, __shfl_xor_sync(0xffffffffu, mx1, 1));
    mx1 = fmaxf(mx1, __shfl_xor_sync(0xffffffffu, mx1, 2));

    float sum0 = 0.f, sum1 = 0.f;
    #pragma unroll
    for (int nt = 0; nt < 15; nt++) {
        #pragma unroll
        for (int cc = 0; cc < 2; cc++) {
            float e0 = __expf(acc[nt][cc]   - mx0);
            float e1 = __expf(acc[nt][2+cc] - mx1);
            acc[nt][cc]   = e0;
            acc[nt][2+cc] = e1;
            sum0 += e0;
            sum1 += e1;
        }
    }
    sum0 += __shfl_xor_sync(0xffffffffu, sum0, 1);
    sum0 += __shfl_xor_sync(0xffffffffu, sum0, 2);
    sum1 += __shfl_xor_sync(0xffffffffu, sum1, 1);
    sum1 += __shfl_xor_sync(0xffffffffu, sum1, 2);
    float inv0 = 1.0f / sum0;
    float inv1 = 1.0f / sum1;

    float* Pw = Ps + warp * 16 * PST;
    #pragma unroll
    for (int nt = 0; nt < 15; nt++) {
        int c = nt*8 + 2*tig;
        Pw[gid*PST + c]       = acc[nt][0];
        Pw[gid*PST + c + 1]   = acc[nt][1];
        Pw[(gid+8)*PST + c]     = acc[nt][2];
        Pw[(gid+8)*PST + c + 1] = acc[nt][3];
    }
    __syncwarp();

    float o[4][4];
    #pragma unroll
    for (int nt = 0; nt < 4; nt++)
        #pragma unroll
        for (int i = 0; i < 4; i++) o[nt][i] = 0.f;

    #pragma unroll
    for (int kt = 0; kt < 15; kt++) {
        float a0 = Pw[gid*PST + kt*8 + tig];
        float a1 = Pw[(gid+8)*PST + kt*8 + tig];
        float a2 = Pw[gid*PST + kt*8 + tig + 4];
        float a3 = Pw[(gid+8)*PST + kt*8 + tig + 4];
        uint32_t ph[4], pl[4];
        tf32_split(a0, ph[0], pl[0]);
        tf32_split(a1, ph[1], pl[1]);
        tf32_split(a2, ph[2], pl[2]);
        tf32_split(a3, ph[3], pl[3]);
        int kg = n_base + kt*8;
        #pragma unroll
        for (int nt = 0; nt < 4; nt++) {
            float b0 = Vt[(nt*8+gid)*VST + kg + tig];
            float b1 = Vt[(nt*8+gid)*VST + kg + tig + 4];
            uint32_t vh[2], vl[2];
            tf32_split(b0, vh[0], vl[0]);
            tf32_split(b1, vh[1], vl[1]);
            mma_tf32(o[nt], ph, vh);
            mma_tf32(o[nt], ph, vl);
            mma_tf32(o[nt], pl, vh);
        }
    }

    #pragma unroll
    for (int nt = 0; nt < 4; nt++) {
        int d = head*32 + nt*8 + 2*tig;
        float2 s0; s0.x = o[nt][0]*inv0; s0.y = o[nt][1]*inv0;
        float2 s1; s1.x = o[nt][2]*inv1; s1.y = o[nt][3]*inv1;
        *reinterpret_cast<float2*>(&attn_out[tok0*128 + d]) = s0;
        *reinterpret_cast<float2*>(&attn_out[tok1*128 + d]) = s1;
    }
}

// ---------------------------------------------------------------------------
// Transpose in: x (B,C,D,H,W) -> t (N=B*D*H*W, C)
// ---------------------------------------------------------------------------
__global__ void t_in_kernel(const float* __restrict__ x, float* __restrict__ t) {
    __shared__ float sm[16][17];
    int bz = blockIdx.z;
    int b = bz / (D_*H_);
    int rem = bz % (D_*H_);
    int d = rem / H_;
    int h = rem % H_;
    int w = blockIdx.x*16 + threadIdx.x;
    int c = blockIdx.y*16 + threadIdx.y;
    sm[threadIdx.y][threadIdx.x] =
        x[(( (long)b*C_ + c)*D_ + d)*(H_*W_) + h*W_ + w];
    __syncthreads();
    int c2 = blockIdx.y*16 + threadIdx.x;
    int w2 = blockIdx.x*16 + threadIdx.y;
    t[((((b*D_ + d)*H_ + h)*W_ + w2) * (long)C_) + c2] = sm[threadIdx.x][threadIdx.y];
}

// ---------------------------------------------------------------------------
// Transpose out: t (N, C) -> out (B,C,D,H,W)
// ---------------------------------------------------------------------------
__global__ void t_out_kernel(const float* __restrict__ t, float* __restrict__ out) {
    __shared__ float sm[16][17];
    int bz = blockIdx.z;
    int b = bz / (D_*H_);
    int rem = bz % (D_*H_);
    int d = rem / H_;
    int h = rem % H_;
    int w_l = blockIdx.x*16 + threadIdx.y;
    int c_l = blockIdx.y*16 + threadIdx.x;
    sm[threadIdx.y][threadIdx.x] =
        t[((((b*D_ + d)*H_ + h)*W_ + w_l) * (long)C_) + c_l];
    __syncthreads();
    int c_s = blockIdx.y*16 + threadIdx.y;
    int w_s = blockIdx.x*16 + threadIdx.x;
    out[(((long)b*C_ + c_s)*D_ + d)*(H_*W_) + h*W_ + w_s] = sm[threadIdx.x][threadIdx.y];
}

// ---------------------------------------------------------------------------
// LayerNorm over C=128
// ---------------------------------------------------------------------------
__global__ void ln_kernel(const float* __restrict__ in,
                          const float* __restrict__ w,
                          const float* __restrict__ b,
                          float* __restrict__ out) {
    int n = blockIdx.x;
    int tid = threadIdx.x;
    float v = in[(long)n*128 + tid];
    float s = v, s2 = v*v;
    #pragma unroll
    for (int o = 16; o > 0; o >>= 1) {
        s  += __shfl_xor_sync(0xffffffffu, s,  o);
        s2 += __shfl_xor_sync(0xffffffffu, s2, o);
    }
    __shared__ float sh[8];
    int warp = tid >> 5, lane = tid & 31;
    if (lane == 0) { sh[warp] = s; sh[4+warp] = s2; }
    __syncthreads();
    s  = sh[0]+sh[1]+sh[2]+sh[3];
    s2 = sh[4]+sh[5]+sh[6]+sh[7];
    float m   = s  * (1.0f/128.0f);
    float var = s2 * (1.0f/128.0f) - m*m;
    float inv = rsqrtf(var + 1e-5f);
    out[(long)n*128 + tid] = (v - m) * inv * w[tid] + b[tid];
}

// ---------------------------------------------------------------------------
// Launch
// ---------------------------------------------------------------------------
extern "C" void kernel_launch(void* const* d_in, const int* in_sizes, int n_in,
                              void* d_out, int out_size) {
    const float* x      = (const float*)d_in[0];
    const float* n1w    = (const float*)d_in[1];
    const float* n1b    = (const float*)d_in[2];
    const float* qkv_w  = (const float*)d_in[3];
    const float* qkv_b  = (const float*)d_in[4];
    const float* rpb    = (const float*)d_in[5];
    const float* proj_w = (const float*)d_in[6];
    const float* proj_b = (const float*)d_in[7];
    const float* n2w    = (const float*)d_in[8];
    const float* n2b    = (const float*)d_in[9];
    const float* fc1_w  = (const float*)d_in[10];
    const float* fc1_b  = (const float*)d_in[11];
    const float* fc2_w  = (const float*)d_in[12];
    const float* fc2_b  = (const float*)d_in[13];
    float* out = (float*)d_out;

    float *t_p, *ln_p, *qkv_p, *attn_p, *h1_p;
    cudaGetSymbolAddress((void**)&t_p,    g_t);
    cudaGetSymbolAddress((void**)&ln_p,   g_ln);
    cudaGetSymbolAddress((void**)&qkv_p,  g_qkv);
    cudaGetSymbolAddress((void**)&attn_p, g_attn);
    cudaGetSymbolAddress((void**)&h1_p,   g_h1);

    int attn_smem = (NKP*KST + 32*VST + 4*16*PST + 169) * (int)sizeof(float);
    cudaFuncSetAttribute(attn_mma_kernel, cudaFuncAttributeMaxDynamicSharedMemorySize, attn_smem);

    dim3 tb(16, 16);
    dim3 tg(W_/16, C_/16, B_*D_*H_);

    // 1. transpose in
    t_in_kernel<<<tg, tb>>>(x, t_p);
    // 2. LN1
    ln_kernel<<<NTOK, 128>>>(t_p, n1w, n1b, ln_p);
    // 3. qkv = ln1 @ qkv_w^T + b   (M=384, K=128)
    gemm_mma_kernel<0><<<dim3(384/64, NTOK/128), 256>>>(ln_p, qkv_w, qkv_b, qkv_p, 384, 128);
    // 4. neighborhood attention (tensor-core)
    attn_mma_kernel<<<dim3(36, NHEAD, B_*D_), 128, attn_smem>>>(qkv_p, rpb, attn_p);
    // 5. t += attn @ proj_w^T + b  (M=128, K=128)
    gemm_mma_kernel<2><<<dim3(128/64, NTOK/128), 256>>>(attn_p, proj_w, proj_b, t_p, 128, 128);
    // 6. LN2
    ln_kernel<<<NTOK, 128>>>(t_p, n2w, n2b, ln_p);
    // 7. h1 = gelu(ln2 @ fc1_w^T + b)  (M=256, K=128)
    gemm_mma_kernel<1><<<dim3(256/64, NTOK/128), 256>>>(ln_p, fc1_w, fc1_b, h1_p, 256, 128);
    // 8. t += h1 @ fc2_w^T + b     (M=128, K=256)
    gemm_mma_kernel<2><<<dim3(128/64, NTOK/128), 256>>>(h1_p, fc2_w, fc2_b, t_p, 128, 256);
    // 9. transpose out
    t_out_kernel<<<tg, tb>>>(t_p, out);
}

// round 7
// speedup vs baseline: 2.1604x; 1.0781x over previous
#include <cuda_runtime.h>
#include <cuda_bf16.h>
#include <math.h>
#include <stdint.h>

// Problem constants
#define B_  2
#define C_  128
#define D_  4
#define H_  48
#define W_  48
#define NTOK (B_*D_*H_*W_)   // 18432
#define NHEAD 4
#define HD 32
#define KW 7

// Scratch (device globals — no allocation allowed)
__device__ float g_t   [NTOK*128];
__device__ float g_ln  [NTOK*128];
__device__ float g_qkv [NTOK*384];
__device__ float g_attn[NTOK*128];
__device__ float g_h1  [NTOK*256];

// ===========================================================================
// Warp-level MMA helpers
// ===========================================================================
__device__ __forceinline__ void mma_bf16(float* c, const uint32_t* a, const uint32_t* b) {
    asm volatile(
        "mma.sync.aligned.m16n8k16.row.col.f32.bf16.bf16.f32 "
        "{%0,%1,%2,%3}, {%4,%5,%6,%7}, {%8,%9}, {%0,%1,%2,%3};"
        : "+f"(c[0]), "+f"(c[1]), "+f"(c[2]), "+f"(c[3])
        : "r"(a[0]), "r"(a[1]), "r"(a[2]), "r"(a[3]), "r"(b[0]), "r"(b[1]));
}

// Split a float2 (consecutive k pair) into packed bf16x2 hi and lo registers.
__device__ __forceinline__ void bf16_split2(float x0, float x1, uint32_t& hi, uint32_t& lo) {
    __nv_bfloat162 h = __floats2bfloat162_rn(x0, x1);
    float h0 = __bfloat162float(h.x);
    float h1 = __bfloat162float(h.y);
    __nv_bfloat162 l = __floats2bfloat162_rn(x0 - h0, x1 - h1);
    hi = *reinterpret_cast<uint32_t*>(&h);
    lo = *reinterpret_cast<uint32_t*>(&l);
}

// ===========================================================================
// Tensor-core GEMM (bf16 3-term split, m16n8k16)  — unchanged from R6
// ===========================================================================
#define GSTR 20

template<int EPI>
__global__ void __launch_bounds__(256, 2)
gemm_mma_kernel(const float* __restrict__ A,
                const float* __restrict__ Wt,
                const float* __restrict__ bias,
                float* __restrict__ out,
                int M, int K) {
    __shared__ uint32_t AsH[128 * GSTR];
    __shared__ uint32_t AsL[128 * GSTR];
    __shared__ uint32_t BsH[64 * GSTR];
    __shared__ uint32_t BsL[64 * GSTR];

    int tid = threadIdx.x;
    int wid = tid >> 5, lane = tid & 31;
    int warp_m = wid & 3;
    int warp_n = wid >> 2;
    int gid = lane >> 2;
    int tig = lane & 3;

    int n0 = blockIdx.y * 128;
    int m0 = blockIdx.x * 64;

    float acc[2][4][4];
    #pragma unroll
    for (int mt = 0; mt < 2; mt++)
        #pragma unroll
        for (int nt = 0; nt < 4; nt++)
            #pragma unroll
            for (int i = 0; i < 4; i++) acc[mt][nt][i] = 0.f;

    for (int k0 = 0; k0 < K; k0 += 32) {
        #pragma unroll
        for (int i = 0; i < 4; i++) {
            int idx = i * 256 + tid;
            int row = idx >> 3, c4 = idx & 7;
            float4 v = *reinterpret_cast<const float4*>(A + (long)(n0 + row) * K + k0 + c4 * 4);
            uint32_t h0, l0, h1, l1;
            bf16_split2(v.x, v.y, h0, l0);
            bf16_split2(v.z, v.w, h1, l1);
            int o = row * GSTR + c4 * 2;
            AsH[o] = h0; AsH[o + 1] = h1;
            AsL[o] = l0; AsL[o + 1] = l1;
        }
        #pragma unroll
        for (int i = 0; i < 2; i++) {
            int idx = i * 256 + tid;
            int row = idx >> 3, c4 = idx & 7;
            float4 v = *reinterpret_cast<const float4*>(Wt + (long)(m0 + row) * K + k0 + c4 * 4);
            uint32_t h0, l0, h1, l1;
            bf16_split2(v.x, v.y, h0, l0);
            bf16_split2(v.z, v.w, h1, l1);
            int o = row * GSTR + c4 * 2;
            BsH[o] = h0; BsH[o + 1] = h1;
            BsL[o] = l0; BsL[o + 1] = l1;
        }
        __syncthreads();

        #pragma unroll
        for (int ks = 0; ks < 2; ks++) {
            int jc = ks * 8;
            uint32_t ahi[2][4], alo[2][4];
            #pragma unroll
            for (int mt = 0; mt < 2; mt++) {
                int r = warp_m * 32 + mt * 16 + gid;
                int o0 = r * GSTR + jc + tig;
                int o1 = (r + 8) * GSTR + jc + tig;
                ahi[mt][0] = AsH[o0];     ahi[mt][1] = AsH[o1];
                ahi[mt][2] = AsH[o0 + 4]; ahi[mt][3] = AsH[o1 + 4];
                alo[mt][0] = AsL[o0];     alo[mt][1] = AsL[o1];
                alo[mt][2] = AsL[o0 + 4]; alo[mt][3] = AsL[o1 + 4];
            }
            uint32_t bhi[4][2], blo[4][2];
            #pragma unroll
            for (int nt = 0; nt < 4; nt++) {
                int br = warp_n * 32 + nt * 8 + gid;
                int o = br * GSTR + jc + tig;
                bhi[nt][0] = BsH[o]; bhi[nt][1] = BsH[o + 4];
                blo[nt][0] = BsL[o]; blo[nt][1] = BsL[o + 4];
            }
            #pragma unroll
            for (int mt = 0; mt < 2; mt++)
                #pragma unroll
                for (int nt = 0; nt < 4; nt++) {
                    mma_bf16(acc[mt][nt], ahi[mt], bhi[nt]);
                    mma_bf16(acc[mt][nt], alo[mt], bhi[nt]);
                    mma_bf16(acc[mt][nt], ahi[mt], blo[nt]);
                }
        }
        __syncthreads();
    }

    int row_base = n0 + warp_m * 32;
    int col_base = m0 + warp_n * 32;
    #pragma unroll
    for (int nt = 0; nt < 4; nt++) {
        int col = col_base + nt * 8 + 2 * tig;
        float b0 = bias[col], b1 = bias[col + 1];
        #pragma unroll
        for (int mt = 0; mt < 2; mt++) {
            #pragma unroll
            for (int half = 0; half < 2; half++) {
                int r = row_base + mt * 16 + gid + half * 8;
                float v0 = acc[mt][nt][half * 2 + 0] + b0;
                float v1 = acc[mt][nt][half * 2 + 1] + b1;
                if (EPI == 1) {
                    v0 = 0.5f * v0 * (1.0f + erff(v0 * 0.70710678118654752f));
                    v1 = 0.5f * v1 * (1.0f + erff(v1 * 0.70710678118654752f));
                }
                float2* dst = reinterpret_cast<float2*>(out + (long)r * M + col);
                if (EPI == 2) {
                    float2 old = *dst;
                    v0 += old.x; v1 += old.y;
                }
                float2 st; st.x = v0; st.y = v1;
                *dst = st;
            }
        }
    }
}

// ===========================================================================
// Tensor-core neighborhood attention, bf16 3-term split everywhere.
// grid = (36 tiles, NHEAD, B*D); block = 128 (4 warps), 3 CTAs/SM.
// K/V pre-split hi/lo bf16 pairs at staging; P split once on smem spill.
// P region aliases the dead K region after a block-wide sync.
// ===========================================================================
#define AGSTR 20    // K row stride in u32 pairs (16 data + 4 pad)
#define VSTP  116   // V^T row stride in key-pairs (112 data + 4 pad)
#define PSTP  68    // P row stride in key-pairs (64 data + 4 pad)

// u32 layout: KsH[4480] KsL[4480] VtH[3712] VtL[3712] rb[169]
#define ATTN_SMEM_U32 (2*224*AGSTR + 2*32*VSTP + 170)

__global__ void __launch_bounds__(128, 3)
attn_mma_kernel(const float* __restrict__ qkv,
                const float* __restrict__ rpb,
                float* __restrict__ attn_out) {
    extern __shared__ uint32_t smu[];
    uint32_t* KsH = smu;
    uint32_t* KsL = KsH + 224*AGSTR;
    uint32_t* VtH = KsL + 224*AGSTR;
    uint32_t* VtL = VtH + 32*VSTP;
    float*    rb  = reinterpret_cast<float*>(VtL + 32*VSTP);

    int tile = blockIdx.x, head = blockIdx.y, bd = blockIdx.z;
    int h0 = (tile / 6) * 8;
    int w0 = (tile % 6) * 8;
    int kh0 = min(max(h0 - 3, 0), H_ - KW);
    int kw0 = min(max(w0 - 3, 0), W_ - KW);
    int tid = threadIdx.x;

    // ---- Stage K (pre-split bf16 pairs along dims)
    for (int e = tid; e < 196*8; e += 128) {
        int key = e >> 3, d4 = e & 7;
        int kr = key / 14, kc = key % 14;
        int gh = min(kh0 + kr, H_-1);
        int gw = min(kw0 + kc, W_-1);
        const float* base = qkv + ((long)(bd*H_ + gh)*W_ + gw)*384 + head*32 + d4*4 + 128;
        float4 k4 = *reinterpret_cast<const float4*>(base);
        uint32_t h0_, l0_, h1_, l1_;
        bf16_split2(k4.x, k4.y, h0_, l0_);
        bf16_split2(k4.z, k4.w, h1_, l1_);
        int o = key*AGSTR + d4*2;
        KsH[o] = h0_; KsH[o+1] = h1_;
        KsL[o] = l0_; KsL[o+1] = l1_;
    }
    // ---- Stage V^T (pre-split bf16 pairs along keys)
    for (int e = tid; e < 98*8; e += 128) {
        int kp = e >> 3, d4 = e & 7;
        int keyA = 2*kp, keyB = 2*kp + 1;
        int ghA = min(kh0 + keyA/14, H_-1), gwA = min(kw0 + keyA%14, W_-1);
        int ghB = min(kh0 + keyB/14, H_-1), gwB = min(kw0 + keyB%14, W_-1);
        float4 va = *reinterpret_cast<const float4*>(
            qkv + ((long)(bd*H_ + ghA)*W_ + gwA)*384 + head*32 + d4*4 + 256);
        float4 vb = *reinterpret_cast<const float4*>(
            qkv + ((long)(bd*H_ + ghB)*W_ + gwB)*384 + head*32 + d4*4 + 256);
        uint32_t h_, l_;
        bf16_split2(va.x, vb.x, h_, l_); VtH[(d4*4+0)*VSTP + kp] = h_; VtL[(d4*4+0)*VSTP + kp] = l_;
        bf16_split2(va.y, vb.y, h_, l_); VtH[(d4*4+1)*VSTP + kp] = h_; VtL[(d4*4+1)*VSTP + kp] = l_;
        bf16_split2(va.z, vb.z, h_, l_); VtH[(d4*4+2)*VSTP + kp] = h_; VtL[(d4*4+2)*VSTP + kp] = l_;
        bf16_split2(va.w, vb.w, h_, l_); VtH[(d4*4+3)*VSTP + kp] = h_; VtL[(d4*4+3)*VSTP + kp] = l_;
    }
    // zero V pad pairs 98..111 (keys 196..223) so 0*garbage can't be NaN
    for (int e = tid; e < 32*14; e += 128) {
        int dm = e / 14, kp = 98 + (e % 14);
        VtH[dm*VSTP + kp] = 0; VtL[dm*VSTP + kp] = 0;
    }
    for (int i = tid; i < 169; i += 128) rb[i] = rpb[head*169 + i];
    __syncthreads();

    int warp = tid >> 5, lane = tid & 31;
    int gid = lane >> 2, tig = lane & 3;

    int hq0 = h0 + 2*warp;
    int hq1 = hq0 + 1;
    int wq  = w0 + gid;
    long tok0 = (long)(bd*H_ + hq0)*W_ + wq;
    long tok1 = tok0 + W_;
    int rel0 = min(max(hq0-3, 0), H_-KW) - kh0;
    int rel1 = min(max(hq1-3, 0), H_-KW) - kh0;
    int ws   = min(max(wq-3, 0), W_-KW) - kw0;
    int n_base = ((min(rel0, rel1) * 14) >> 3) * 8;

    // ---- Q fragments (scaled, bf16 split, pairs along k)
    const float scale = 0.17677669529663687f;
    uint32_t qh[2][4], ql[2][4];
    #pragma unroll
    for (int ks = 0; ks < 2; ks++) {
        const float* q0p = qkv + tok0*384 + head*32 + ks*16 + 2*tig;
        const float* q1p = qkv + tok1*384 + head*32 + ks*16 + 2*tig;
        float2 a = *reinterpret_cast<const float2*>(q0p);
        float2 b = *reinterpret_cast<const float2*>(q1p);
        float2 c = *reinterpret_cast<const float2*>(q0p + 8);
        float2 d = *reinterpret_cast<const float2*>(q1p + 8);
        bf16_split2(a.x*scale, a.y*scale, qh[ks][0], ql[ks][0]);
        bf16_split2(b.x*scale, b.y*scale, qh[ks][1], ql[ks][1]);
        bf16_split2(c.x*scale, c.y*scale, qh[ks][2], ql[ks][2]);
        bf16_split2(d.x*scale, d.y*scale, qh[ks][3], ql[ks][3]);
    }

    // ---- Scores: 15 n-tiles x 2 k16-tiles x 3 terms
    float acc[15][4];
    #pragma unroll
    for (int nt = 0; nt < 15; nt++)
        #pragma unroll
        for (int i = 0; i < 4; i++) acc[nt][i] = 0.f;

    #pragma unroll
    for (int nt = 0; nt < 15; nt++) {
        int key = n_base + nt*8 + gid;
        #pragma unroll
        for (int ks = 0; ks < 2; ks++) {
            int o = key*AGSTR + ks*8 + tig;
            uint32_t bh[2] = { KsH[o], KsH[o + 4] };
            uint32_t bl[2] = { KsL[o], KsL[o + 4] };
            mma_bf16(acc[nt], qh[ks], bh);
            mma_bf16(acc[nt], ql[ks], bh);
            mma_bf16(acc[nt], qh[ks], bl);
        }
    }

    // ---- Bias + mask + softmax
    int bh0c = kh0 - hq0 + 6;
    int bh1c = kh0 - hq1 + 6;
    int bwc  = kw0 - wq + 6;
    float mx0 = -1e30f, mx1 = -1e30f;
    #pragma unroll
    for (int nt = 0; nt < 15; nt++) {
        #pragma unroll
        for (int cc = 0; cc < 2; cc++) {
            int n = n_base + nt*8 + 2*tig + cc;
            int kr = n / 14;
            int kc = n - kr*14;
            bool vw = (unsigned)(kc - ws) <= 6u;
            bool v0 = vw && (unsigned)(kr - rel0) <= 6u;
            bool v1 = vw && (unsigned)(kr - rel1) <= 6u;
            float s0 = v0 ? acc[nt][cc]   + rb[(bh0c+kr)*13 + bwc + kc] : -1e30f;
            float s1 = v1 ? acc[nt][2+cc] + rb[(bh1c+kr)*13 + bwc + kc] : -1e30f;
            acc[nt][cc]   = s0;
            acc[nt][2+cc] = s1;
            mx0 = fmaxf(mx0, s0);
            mx1 = fmaxf(mx1, s1);
        }
    }
    mx0 = fmaxf(mx0, __shfl_xor_sync(0xffffffffu, mx0, 1));
    mx0 = fmaxf(mx0, __shfl_xor_sync(0xffffffffu, mx0, 2));
    mx1 = fmaxf(mx1, __shfl_xor_sync(0xffffffffu, mx1, 1));
    mx1 = fmaxf(mx1, __shfl_xor_sync(0xffffffffu, mx1, 2));

    float sum0 = 0.f, sum1 = 0.f;
    #pragma unroll
    for (int nt = 0; nt < 15; nt++) {
        #pragma unroll
        for (int cc = 0; cc < 2; cc++) {
            float e0 = __expf(acc[nt][cc]   - mx0);
            float e1 = __expf(acc[nt][2+cc] - mx1);
            acc[nt][cc]   = e0;
            acc[nt][2+cc] = e1;
            sum0 += e0;
            sum1 += e1;
        }
    }
    sum0 += __shfl_xor_sync(0xffffffffu, sum0, 1);
    sum0 += __shfl_xor_sync(0xffffffffu, sum0, 2);
    sum1 += __shfl_xor_sync(0xffffffffu, sum1, 1);
    sum1 += __shfl_xor_sync(0xffffffffu, sum1, 2);
    float inv0 = 1.0f / sum0;
    float inv1 = 1.0f / sum1;

    // ---- All warps done reading Ks; alias P over it, split once to bf16
    __syncthreads();
    uint32_t* PwH = smu + warp * (16 * PSTP * 2);
    uint32_t* PwL = PwH + 16 * PSTP;
    #pragma unroll
    for (int nt = 0; nt < 15; nt++) {
        uint32_t h_, l_;
        bf16_split2(acc[nt][0], acc[nt][1], h_, l_);
        PwH[gid*PSTP + nt*4 + tig] = h_;
        PwL[gid*PSTP + nt*4 + tig] = l_;
        bf16_split2(acc[nt][2], acc[nt][3], h_, l_);
        PwH[(gid+8)*PSTP + nt*4 + tig] = h_;
        PwL[(gid+8)*PSTP + nt*4 + tig] = l_;
    }
    // zero pad pairs 60..63 (cols 120..127)
    PwH[gid*PSTP + 60 + tig] = 0;     PwL[gid*PSTP + 60 + tig] = 0;
    PwH[(gid+8)*PSTP + 60 + tig] = 0; PwL[(gid+8)*PSTP + 60 + tig] = 0;
    __syncwarp();

    // ---- PV: 8 k16-tiles x 4 n-tiles (dims) x 3 terms
    int nb2 = n_base >> 1;
    float o[4][4];
    #pragma unroll
    for (int nt = 0; nt < 4; nt++)
        #pragma unroll
        for (int i = 0; i < 4; i++) o[nt][i] = 0.f;

    #pragma unroll
    for (int kt = 0; kt < 8; kt++) {
        int p0 = gid*PSTP + kt*8 + tig;
        int p1 = (gid+8)*PSTP + kt*8 + tig;
        uint32_t ph[4] = { PwH[p0], PwH[p1], PwH[p0 + 4], PwH[p1 + 4] };
        uint32_t pl[4] = { PwL[p0], PwL[p1], PwL[p0 + 4], PwL[p1 + 4] };
        #pragma unroll
        for (int nt = 0; nt < 4; nt++) {
            int vr = (nt*8 + gid)*VSTP + nb2 + kt*8 + tig;
            uint32_t vh[2] = { VtH[vr], VtH[vr + 4] };
            uint32_t vl[2] = { VtL[vr], VtL[vr + 4] };
            mma_bf16(o[nt], ph, vh);
            mma_bf16(o[nt], pl, vh);
            mma_bf16(o[nt], ph, vl);
        }
    }

    // ---- Output (normalize per row)
    #pragma unroll
    for (int nt = 0; nt < 4; nt++) {
        int d = head*32 + nt*8 + 2*tig;
        float2 s0; s0.x = o[nt][0]*inv0; s0.y = o[nt][1]*inv0;
        float2 s1; s1.x = o[nt][2]*inv1; s1.y = o[nt][3]*inv1;
        *reinterpret_cast<float2*>(&attn_out[tok0*128 + d]) = s0;
        *reinterpret_cast<float2*>(&attn_out[tok1*128 + d]) = s1;
    }
}

// ---------------------------------------------------------------------------
// Transpose in: x (B,C,D,H,W) -> t (N=B*D*H*W, C)
// ---------------------------------------------------------------------------
__global__ void t_in_kernel(const float* __restrict__ x, float* __restrict__ t) {
    __shared__ float sm[16][17];
    int bz = blockIdx.z;
    int b = bz / (D_*H_);
    int rem = bz % (D_*H_);
    int d = rem / H_;
    int h = rem % H_;
    int w = blockIdx.x*16 + threadIdx.x;
    int c = blockIdx.y*16 + threadIdx.y;
    sm[threadIdx.y][threadIdx.x] =
        x[(( (long)b*C_ + c)*D_ + d)*(H_*W_) + h*W_ + w];
    __syncthreads();
    int c2 = blockIdx.y*16 + threadIdx.x;
    int w2 = blockIdx.x*16 + threadIdx.y;
    t[((((b*D_ + d)*H_ + h)*W_ + w2) * (long)C_) + c2] = sm[threadIdx.x][threadIdx.y];
}

// ---------------------------------------------------------------------------
// Transpose out: t (N, C) -> out (B,C,D,H,W)
// ---------------------------------------------------------------------------
__global__ void t_out_kernel(const float* __restrict__ t, float* __restrict__ out) {
    __shared__ float sm[16][17];
    int bz = blockIdx.z;
    int b = bz / (D_*H_);
    int rem = bz % (D_*H_);
    int d = rem / H_;
    int h = rem % H_;
    int w_l = blockIdx.x*16 + threadIdx.y;
    int c_l = blockIdx.y*16 + threadIdx.x;
    sm[threadIdx.y][threadIdx.x] =
        t[((((b*D_ + d)*H_ + h)*W_ + w_l) * (long)C_) + c_l];
    __syncthreads();
    int c_s = blockIdx.y*16 + threadIdx.y;
    int w_s = blockIdx.x*16 + threadIdx.x;
    out[(((long)b*C_ + c_s)*D_ + d)*(H_*W_) + h*W_ + w_s] = sm[threadIdx.x][threadIdx.y];
}

// ---------------------------------------------------------------------------
// LayerNorm over C=128
// ---------------------------------------------------------------------------
__global__ void ln_kernel(const float* __restrict__ in,
                          const float* __restrict__ w,
                          const float* __restrict__ b,
                          float* __restrict__ out) {
    int n = blockIdx.x;
    int tid = threadIdx.x;
    float v = in[(long)n*128 + tid];
    float s = v, s2 = v*v;
    #pragma unroll
    for (int o = 16; o > 0; o >>= 1) {
        s  += __shfl_xor_sync(0xffffffffu, s,  o);
        s2 += __shfl_xor_sync(0xffffffffu, s2, o);
    }
    __shared__ float sh[8];
    int warp = tid >> 5, lane = tid & 31;
    if (lane == 0) { sh[warp] = s; sh[4+warp] = s2; }
    __syncthreads();
    s  = sh[0]+sh[1]+sh[2]+sh[3];
    s2 = sh[4]+sh[5]+sh[6]+sh[7];
    float m   = s  * (1.0f/128.0f);
    float var = s2 * (1.0f/128.0f) - m*m;
    float inv = rsqrtf(var + 1e-5f);
    out[(long)n*128 + tid] = (v - m) * inv * w[tid] + b[tid];
}

// ---------------------------------------------------------------------------
// Launch
// ---------------------------------------------------------------------------
extern "C" void kernel_launch(void* const* d_in, const int* in_sizes, int n_in,
                              void* d_out, int out_size) {
    const float* x      = (const float*)d_in[0];
    const float* n1w    = (const float*)d_in[1];
    const float* n1b    = (const float*)d_in[2];
    const float* qkv_w  = (const float*)d_in[3];
    const float* qkv_b  = (const float*)d_in[4];
    const float* rpb    = (const float*)d_in[5];
    const float* proj_w = (const float*)d_in[6];
    const float* proj_b = (const float*)d_in[7];
    const float* n2w    = (const float*)d_in[8];
    const float* n2b    = (const float*)d_in[9];
    const float* fc1_w  = (const float*)d_in[10];
    const float* fc1_b  = (const float*)d_in[11];
    const float* fc2_w  = (const float*)d_in[12];
    const float* fc2_b  = (const float*)d_in[13];
    float* out = (float*)d_out;

    float *t_p, *ln_p, *qkv_p, *attn_p, *h1_p;
    cudaGetSymbolAddress((void**)&t_p,    g_t);
    cudaGetSymbolAddress((void**)&ln_p,   g_ln);
    cudaGetSymbolAddress((void**)&qkv_p,  g_qkv);
    cudaGetSymbolAddress((void**)&attn_p, g_attn);
    cudaGetSymbolAddress((void**)&h1_p,   g_h1);

    int attn_smem = ATTN_SMEM_U32 * (int)sizeof(uint32_t);
    cudaFuncSetAttribute(attn_mma_kernel, cudaFuncAttributeMaxDynamicSharedMemorySize, attn_smem);

    dim3 tb(16, 16);
    dim3 tg(W_/16, C_/16, B_*D_*H_);

    // 1. transpose in
    t_in_kernel<<<tg, tb>>>(x, t_p);
    // 2. LN1
    ln_kernel<<<NTOK, 128>>>(t_p, n1w, n1b, ln_p);
    // 3. qkv = ln1 @ qkv_w^T + b   (M=384, K=128)
    gemm_mma_kernel<0><<<dim3(384/64, NTOK/128), 256>>>(ln_p, qkv_w, qkv_b, qkv_p, 384, 128);
    // 4. neighborhood attention (tensor-core, bf16)
    attn_mma_kernel<<<dim3(36, NHEAD, B_*D_), 128, attn_smem>>>(qkv_p, rpb, attn_p);
    // 5. t += attn @ proj_w^T + b  (M=128, K=128)
    gemm_mma_kernel<2><<<dim3(128/64, NTOK/128), 256>>>(attn_p, proj_w, proj_b, t_p, 128, 128);
    // 6. LN2
    ln_kernel<<<NTOK, 128>>>(t_p, n2w, n2b, ln_p);
    // 7. h1 = gelu(ln2 @ fc1_w^T + b)  (M=256, K=128)
    gemm_mma_kernel<1><<<dim3(256/64, NTOK/128), 256>>>(ln_p, fc1_w, fc1_b, h1_p, 256, 128);
    // 8. t += h1 @ fc2_w^T + b     (M=128, K=256)
    gemm_mma_kernel<2><<<dim3(128/64, NTOK/128), 256>>>(h1_p, fc2_w, fc2_b, t_p, 128, 256);
    // 9. transpose out
    t_out_kernel<<<tg, tb>>>(t_p, out);
}

// round 8
// speedup vs baseline: 2.1895x; 1.0135x over previous
#include <cuda_runtime.h>
#include <cuda_bf16.h>
#include <math.h>
#include <stdint.h>

// Problem constants
#define B_  2
#define C_  128
#define D_  4
#define H_  48
#define W_  48
#define NTOK (B_*D_*H_*W_)   // 18432
#define NHEAD 4
#define HD 32
#define KW 7

// Scratch (device globals — no allocation allowed)
__device__ float  g_t   [NTOK*128];
__device__ float  g_qkv [NTOK*384];
__device__ float  g_attn[NTOK*128];
__device__ float  g_h1  [NTOK*256];
__device__ float2 g_st  [NTOK];
// Pre-split weights (bf16x2 hi/lo packed k-pairs, row-major)
// qkv @0 (24576), proj @24576 (8192), fc1 @32768 (16384), fc2 @49152 (16384)
__device__ uint32_t g_wh[65536];
__device__ uint32_t g_wl[65536];

// ===========================================================================
// Warp-level MMA helpers
// ===========================================================================
__device__ __forceinline__ void mma_bf16(float* c, const uint32_t* a, const uint32_t* b) {
    asm volatile(
        "mma.sync.aligned.m16n8k16.row.col.f32.bf16.bf16.f32 "
        "{%0,%1,%2,%3}, {%4,%5,%6,%7}, {%8,%9}, {%0,%1,%2,%3};"
        : "+f"(c[0]), "+f"(c[1]), "+f"(c[2]), "+f"(c[3])
        : "r"(a[0]), "r"(a[1]), "r"(a[2]), "r"(a[3]), "r"(b[0]), "r"(b[1]));
}

__device__ __forceinline__ void bf16_split2(float x0, float x1, uint32_t& hi, uint32_t& lo) {
    __nv_bfloat162 h = __floats2bfloat162_rn(x0, x1);
    float h0 = __bfloat162float(h.x);
    float h1 = __bfloat162float(h.y);
    __nv_bfloat162 l = __floats2bfloat162_rn(x0 - h0, x1 - h1);
    hi = *reinterpret_cast<uint32_t*>(&h);
    lo = *reinterpret_cast<uint32_t*>(&l);
}

// ===========================================================================
// Weight pre-split: all 4 weight matrices -> g_wh/g_wl (one pass)
// ===========================================================================
__global__ void wsplit_kernel(const float* __restrict__ qkv_w,
                              const float* __restrict__ proj_w,
                              const float* __restrict__ fc1_w,
                              const float* __restrict__ fc2_w) {
    int i = blockIdx.x * 256 + threadIdx.x;   // pair index, 0..65535
    const float* src;
    int li;
    if (i < 24576)      { src = qkv_w;  li = i; }
    else if (i < 32768) { src = proj_w; li = i - 24576; }
    else if (i < 49152) { src = fc1_w;  li = i - 32768; }
    else                { src = fc2_w;  li = i - 49152; }
    float2 v = *reinterpret_cast<const float2*>(src + 2 * li);
    uint32_t h, l;
    bf16_split2(v.x, v.y, h, l);
    g_wh[i] = h;
    g_wl[i] = l;
}

// ===========================================================================
// LayerNorm stats: per token mean + rstd (float2)
// ===========================================================================
__global__ void ln_stats_kernel(const float* __restrict__ in, float2* __restrict__ st) {
    int n = blockIdx.x;
    int tid = threadIdx.x;
    float v = in[(long)n*128 + tid];
    float s = v, s2 = v*v;
    #pragma unroll
    for (int o = 16; o > 0; o >>= 1) {
        s  += __shfl_xor_sync(0xffffffffu, s,  o);
        s2 += __shfl_xor_sync(0xffffffffu, s2, o);
    }
    __shared__ float sh[8];
    int warp = tid >> 5, lane = tid & 31;
    if (lane == 0) { sh[warp] = s; sh[4+warp] = s2; }
    __syncthreads();
    if (tid == 0) {
        s  = sh[0]+sh[1]+sh[2]+sh[3];
        s2 = sh[4]+sh[5]+sh[6]+sh[7];
        float m   = s  * (1.0f/128.0f);
        float var = s2 * (1.0f/128.0f) - m*m;
        st[n] = make_float2(m, rsqrtf(var + 1e-5f));
    }
}

// ===========================================================================
// Tensor-core GEMM (bf16 3-term split, m16n8k16), software-pipelined.
// out[NTOK,M] = LN?(A)[NTOK,K] @ W[M,K]^T + bias (+epilogue)
// Block = 256 thr (8 warps): 128 tokens x 64 out cols. Warp = 32x32.
// B comes pre-split from g_wh/g_wl.
// EPI: 0 bias, 1 bias+GELU, 2 bias+residual into out,
//      3 bias + residual from resid + direct transposed store to (B,C,D,H,W).
// LNA: apply layernorm (stats + lnw/lnb) to A rows during staging.
// ===========================================================================
#define GSTR 20

template<int EPI, bool LNA>
__global__ void __launch_bounds__(256, 2)
gemm_mma_kernel(const float* __restrict__ A,
                const uint32_t* __restrict__ WH,
                const uint32_t* __restrict__ WL,
                const float* __restrict__ bias,
                const float2* __restrict__ stats,
                const float* __restrict__ lnw,
                const float* __restrict__ lnb,
                float* __restrict__ out,
                const float* __restrict__ resid,
                int M, int K) {
    __shared__ uint32_t AsH[128 * GSTR];
    __shared__ uint32_t AsL[128 * GSTR];
    __shared__ uint32_t BsH[64 * GSTR];
    __shared__ uint32_t BsL[64 * GSTR];

    int tid = threadIdx.x;
    int wid = tid >> 5, lane = tid & 31;
    int warp_m = wid & 3;
    int warp_n = wid >> 2;
    int gid = lane >> 2;
    int tig = lane & 3;

    int n0 = blockIdx.y * 128;
    int m0 = blockIdx.x * 64;
    int Kp = K >> 1;
    int nch = K >> 5;

    float acc[2][4][4];
    #pragma unroll
    for (int mt = 0; mt < 2; mt++)
        #pragma unroll
        for (int nt = 0; nt < 4; nt++)
            #pragma unroll
            for (int i = 0; i < 4; i++) acc[mt][nt][i] = 0.f;

    // Prefetch registers
    float4 aV[4];
    uint2  bHv[2], bLv[2];

    // ---- load chunk 0
    {
        int k0 = 0;
        #pragma unroll
        for (int i = 0; i < 4; i++) {
            int idx = i * 256 + tid;
            int row = idx >> 3, c4 = idx & 7;
            float4 v = *reinterpret_cast<const float4*>(A + (long)(n0 + row) * K + k0 + c4 * 4);
            if (LNA) {
                float2 st = stats[n0 + row];
                float4 w4 = *reinterpret_cast<const float4*>(lnw + k0 + c4 * 4);
                float4 b4 = *reinterpret_cast<const float4*>(lnb + k0 + c4 * 4);
                v.x = (v.x - st.x) * st.y * w4.x + b4.x;
                v.y = (v.y - st.x) * st.y * w4.y + b4.y;
                v.z = (v.z - st.x) * st.y * w4.z + b4.z;
                v.w = (v.w - st.x) * st.y * w4.w + b4.w;
            }
            aV[i] = v;
        }
        #pragma unroll
        for (int i = 0; i < 2; i++) {
            int idx = i * 256 + tid;
            int row = idx >> 3, q = idx & 7;
            long go = (long)(m0 + row) * Kp + q * 2;
            bHv[i] = *reinterpret_cast<const uint2*>(WH + go);
            bLv[i] = *reinterpret_cast<const uint2*>(WL + go);
        }
    }

    for (int ch = 0; ch < nch; ch++) {
        // ---- store prefetched chunk to smem
        #pragma unroll
        for (int i = 0; i < 4; i++) {
            int idx = i * 256 + tid;
            int row = idx >> 3, c4 = idx & 7;
            uint32_t h0, l0, h1, l1;
            bf16_split2(aV[i].x, aV[i].y, h0, l0);
            bf16_split2(aV[i].z, aV[i].w, h1, l1);
            int o = row * GSTR + c4 * 2;
            AsH[o] = h0; AsH[o + 1] = h1;
            AsL[o] = l0; AsL[o + 1] = l1;
        }
        #pragma unroll
        for (int i = 0; i < 2; i++) {
            int idx = i * 256 + tid;
            int row = idx >> 3, q = idx & 7;
            *reinterpret_cast<uint2*>(&BsH[row * GSTR + q * 2]) = bHv[i];
            *reinterpret_cast<uint2*>(&BsL[row * GSTR + q * 2]) = bLv[i];
        }
        __syncthreads();

        // ---- prefetch next chunk (overlaps with mma below)
        if (ch + 1 < nch) {
            int k0 = (ch + 1) * 32;
            #pragma unroll
            for (int i = 0; i < 4; i++) {
                int idx = i * 256 + tid;
                int row = idx >> 3, c4 = idx & 7;
                float4 v = *reinterpret_cast<const float4*>(A + (long)(n0 + row) * K + k0 + c4 * 4);
                if (LNA) {
                    float2 st = stats[n0 + row];
                    float4 w4 = *reinterpret_cast<const float4*>(lnw + k0 + c4 * 4);
                    float4 b4 = *reinterpret_cast<const float4*>(lnb + k0 + c4 * 4);
                    v.x = (v.x - st.x) * st.y * w4.x + b4.x;
                    v.y = (v.y - st.x) * st.y * w4.y + b4.y;
                    v.z = (v.z - st.x) * st.y * w4.z + b4.z;
                    v.w = (v.w - st.x) * st.y * w4.w + b4.w;
                }
                aV[i] = v;
            }
            int kp0 = (ch + 1) * 16;
            #pragma unroll
            for (int i = 0; i < 2; i++) {
                int idx = i * 256 + tid;
                int row = idx >> 3, q = idx & 7;
                long go = (long)(m0 + row) * Kp + kp0 + q * 2;
                bHv[i] = *reinterpret_cast<const uint2*>(WH + go);
                bLv[i] = *reinterpret_cast<const uint2*>(WL + go);
            }
        }

        // ---- compute
        #pragma unroll
        for (int ks = 0; ks < 2; ks++) {
            int jc = ks * 8;
            uint32_t ahi[2][4], alo[2][4];
            #pragma unroll
            for (int mt = 0; mt < 2; mt++) {
                int r = warp_m * 32 + mt * 16 + gid;
                int o0 = r * GSTR + jc + tig;
                int o1 = (r + 8) * GSTR + jc + tig;
                ahi[mt][0] = AsH[o0];     ahi[mt][1] = AsH[o1];
                ahi[mt][2] = AsH[o0 + 4]; ahi[mt][3] = AsH[o1 + 4];
                alo[mt][0] = AsL[o0];     alo[mt][1] = AsL[o1];
                alo[mt][2] = AsL[o0 + 4]; alo[mt][3] = AsL[o1 + 4];
            }
            uint32_t bhi[4][2], blo[4][2];
            #pragma unroll
            for (int nt = 0; nt < 4; nt++) {
                int br = warp_n * 32 + nt * 8 + gid;
                int o = br * GSTR + jc + tig;
                bhi[nt][0] = BsH[o]; bhi[nt][1] = BsH[o + 4];
                blo[nt][0] = BsL[o]; blo[nt][1] = BsL[o + 4];
            }
            #pragma unroll
            for (int mt = 0; mt < 2; mt++)
                #pragma unroll
                for (int nt = 0; nt < 4; nt++) {
                    mma_bf16(acc[mt][nt], ahi[mt], bhi[nt]);
                    mma_bf16(acc[mt][nt], alo[mt], bhi[nt]);
                    mma_bf16(acc[mt][nt], ahi[mt], blo[nt]);
                }
        }
        __syncthreads();
    }

    // ---- epilogue
    int row_base = n0 + warp_m * 32;
    int col_base = m0 + warp_n * 32;
    #pragma unroll
    for (int nt = 0; nt < 4; nt++) {
        int col = col_base + nt * 8 + 2 * tig;
        float b0 = bias[col], b1 = bias[col + 1];
        #pragma unroll
        for (int mt = 0; mt < 2; mt++) {
            #pragma unroll
            for (int half = 0; half < 2; half++) {
                int r = row_base + mt * 16 + gid + half * 8;
                float v0 = acc[mt][nt][half * 2 + 0] + b0;
                float v1 = acc[mt][nt][half * 2 + 1] + b1;
                if (EPI == 1) {
                    v0 = 0.5f * v0 * (1.0f + erff(v0 * 0.70710678118654752f));
                    v1 = 0.5f * v1 * (1.0f + erff(v1 * 0.70710678118654752f));
                }
                if (EPI == 3) {
                    // residual + direct transposed store to (B,C,D,H,W)
                    float2 rv = *reinterpret_cast<const float2*>(resid + (long)r * 128 + col);
                    v0 += rv.x; v1 += rv.y;
                    long o = (long)r + (r >= 9216 ? 1170432L : 0L) + (long)col * 9216;
                    out[o]        = v0;
                    out[o + 9216] = v1;
                } else {
                    float2* dst = reinterpret_cast<float2*>(out + (long)r * M + col);
                    if (EPI == 2) {
                        float2 old = *dst;
                        v0 += old.x; v1 += old.y;
                    }
                    float2 st; st.x = v0; st.y = v1;
                    *dst = st;
                }
            }
        }
    }
}

// ===========================================================================
// Tensor-core neighborhood attention (unchanged from R7)
// ===========================================================================
#define AGSTR 20
#define VSTP  116
#define PSTP  68
#define ATTN_SMEM_U32 (2*224*AGSTR + 2*32*VSTP + 170)

__global__ void __launch_bounds__(128, 3)
attn_mma_kernel(const float* __restrict__ qkv,
                const float* __restrict__ rpb,
                float* __restrict__ attn_out) {
    extern __shared__ uint32_t smu[];
    uint32_t* KsH = smu;
    uint32_t* KsL = KsH + 224*AGSTR;
    uint32_t* VtH = KsL + 224*AGSTR;
    uint32_t* VtL = VtH + 32*VSTP;
    float*    rb  = reinterpret_cast<float*>(VtL + 32*VSTP);

    int tile = blockIdx.x, head = blockIdx.y, bd = blockIdx.z;
    int h0 = (tile / 6) * 8;
    int w0 = (tile % 6) * 8;
    int kh0 = min(max(h0 - 3, 0), H_ - KW);
    int kw0 = min(max(w0 - 3, 0), W_ - KW);
    int tid = threadIdx.x;

    for (int e = tid; e < 196*8; e += 128) {
        int key = e >> 3, d4 = e & 7;
        int kr = key / 14, kc = key % 14;
        int gh = min(kh0 + kr, H_-1);
        int gw = min(kw0 + kc, W_-1);
        const float* base = qkv + ((long)(bd*H_ + gh)*W_ + gw)*384 + head*32 + d4*4 + 128;
        float4 k4 = *reinterpret_cast<const float4*>(base);
        uint32_t h0_, l0_, h1_, l1_;
        bf16_split2(k4.x, k4.y, h0_, l0_);
        bf16_split2(k4.z, k4.w, h1_, l1_);
        int o = key*AGSTR + d4*2;
        KsH[o] = h0_; KsH[o+1] = h1_;
        KsL[o] = l0_; KsL[o+1] = l1_;
    }
    for (int e = tid; e < 98*8; e += 128) {
        int kp = e >> 3, d4 = e & 7;
        int keyA = 2*kp, keyB = 2*kp + 1;
        int ghA = min(kh0 + keyA/14, H_-1), gwA = min(kw0 + keyA%14, W_-1);
        int ghB = min(kh0 + keyB/14, H_-1), gwB = min(kw0 + keyB%14, W_-1);
        float4 va = *reinterpret_cast<const float4*>(
            qkv + ((long)(bd*H_ + ghA)*W_ + gwA)*384 + head*32 + d4*4 + 256);
        float4 vb = *reinterpret_cast<const float4*>(
            qkv + ((long)(bd*H_ + ghB)*W_ + gwB)*384 + head*32 + d4*4 + 256);
        uint32_t h_, l_;
        bf16_split2(va.x, vb.x, h_, l_); VtH[(d4*4+0)*VSTP + kp] = h_; VtL[(d4*4+0)*VSTP + kp] = l_;
        bf16_split2(va.y, vb.y, h_, l_); VtH[(d4*4+1)*VSTP + kp] = h_; VtL[(d4*4+1)*VSTP + kp] = l_;
        bf16_split2(va.z, vb.z, h_, l_); VtH[(d4*4+2)*VSTP + kp] = h_; VtL[(d4*4+2)*VSTP + kp] = l_;
        bf16_split2(va.w, vb.w, h_, l_); VtH[(d4*4+3)*VSTP + kp] = h_; VtL[(d4*4+3)*VSTP + kp] = l_;
    }
    for (int e = tid; e < 32*14; e += 128) {
        int dm = e / 14, kp = 98 + (e % 14);
        VtH[dm*VSTP + kp] = 0; VtL[dm*VSTP + kp] = 0;
    }
    for (int i = tid; i < 169; i += 128) rb[i] = rpb[head*169 + i];
    __syncthreads();

    int warp = tid >> 5, lane = tid & 31;
    int gid = lane >> 2, tig = lane & 3;

    int hq0 = h0 + 2*warp;
    int hq1 = hq0 + 1;
    int wq  = w0 + gid;
    long tok0 = (long)(bd*H_ + hq0)*W_ + wq;
    long tok1 = tok0 + W_;
    int rel0 = min(max(hq0-3, 0), H_-KW) - kh0;
    int rel1 = min(max(hq1-3, 0), H_-KW) - kh0;
    int ws   = min(max(wq-3, 0), W_-KW) - kw0;
    int n_base = ((min(rel0, rel1) * 14) >> 3) * 8;

    const float scale = 0.17677669529663687f;
    uint32_t qh[2][4], ql[2][4];
    #pragma unroll
    for (int ks = 0; ks < 2; ks++) {
        const float* q0p = qkv + tok0*384 + head*32 + ks*16 + 2*tig;
        const float* q1p = qkv + tok1*384 + head*32 + ks*16 + 2*tig;
        float2 a = *reinterpret_cast<const float2*>(q0p);
        float2 b = *reinterpret_cast<const float2*>(q1p);
        float2 c = *reinterpret_cast<const float2*>(q0p + 8);
        float2 d = *reinterpret_cast<const float2*>(q1p + 8);
        bf16_split2(a.x*scale, a.y*scale, qh[ks][0], ql[ks][0]);
        bf16_split2(b.x*scale, b.y*scale, qh[ks][1], ql[ks][1]);
        bf16_split2(c.x*scale, c.y*scale, qh[ks][2], ql[ks][2]);
        bf16_split2(d.x*scale, d.y*scale, qh[ks][3], ql[ks][3]);
    }

    float acc[15][4];
    #pragma unroll
    for (int nt = 0; nt < 15; nt++)
        #pragma unroll
        for (int i = 0; i < 4; i++) acc[nt][i] = 0.f;

    #pragma unroll
    for (int nt = 0; nt < 15; nt++) {
        int key = n_base + nt*8 + gid;
        #pragma unroll
        for (int ks = 0; ks < 2; ks++) {
            int o = key*AGSTR + ks*8 + tig;
            uint32_t bh[2] = { KsH[o], KsH[o + 4] };
            uint32_t bl[2] = { KsL[o], KsL[o + 4] };
            mma_bf16(acc[nt], qh[ks], bh);
            mma_bf16(acc[nt], ql[ks], bh);
            mma_bf16(acc[nt], qh[ks], bl);
        }
    }

    int bh0c = kh0 - hq0 + 6;
    int bh1c = kh0 - hq1 + 6;
    int bwc  = kw0 - wq + 6;
    float mx0 = -1e30f, mx1 = -1e30f;
    #pragma unroll
    for (int nt = 0; nt < 15; nt++) {
        #pragma unroll
        for (int cc = 0; cc < 2; cc++) {
            int n = n_base + nt*8 + 2*tig + cc;
            int kr = n / 14;
            int kc = n - kr*14;
            bool vw = (unsigned)(kc - ws) <= 6u;
            bool v0 = vw && (unsigned)(kr - rel0) <= 6u;
            bool v1 = vw && (unsigned)(kr - rel1) <= 6u;
            float s0 = v0 ? acc[nt][cc]   + rb[(bh0c+kr)*13 + bwc + kc] : -1e30f;
            float s1 = v1 ? acc[nt][2+cc] + rb[(bh1c+kr)*13 + bwc + kc] : -1e30f;
            acc[nt][cc]   = s0;
            acc[nt][2+cc] = s1;
            mx0 = fmaxf(mx0, s0);
            mx1 = fmaxf(mx1, s1);
        }
    }
    mx0 = fmaxf(mx0, __shfl_xor_sync(0xffffffffu, mx0, 1));
    mx0 = fmaxf(mx0, __shfl_xor_sync(0xffffffffu, mx0, 2));
    mx1 = fmaxf(mx1, __shfl_xor_sync(0xffffffffu, mx1, 1));
    mx1 = fmaxf(mx1, __shfl_xor_sync(0xffffffffu, mx1, 2));

    float sum0 = 0.f, sum1 = 0.f;
    #pragma unroll
    for (int nt = 0; nt < 15; nt++) {
        #pragma unroll
        for (int cc = 0; cc < 2; cc++) {
            float e0 = __expf(acc[nt][cc]   - mx0);
            float e1 = __expf(acc[nt][2+cc] - mx1);
            acc[nt][cc]   = e0;
            acc[nt][2+cc] = e1;
            sum0 += e0;
            sum1 += e1;
        }
    }
    sum0 += __shfl_xor_sync(0xffffffffu, sum0, 1);
    sum0 += __shfl_xor_sync(0xffffffffu, sum0, 2);
    sum1 += __shfl_xor_sync(0xffffffffu, sum1, 1);
    sum1 += __shfl_xor_sync(0xffffffffu, sum1, 2);
    float inv0 = 1.0f / sum0;
    float inv1 = 1.0f / sum1;

    __syncthreads();
    uint32_t* PwH = smu + warp * (16 * PSTP * 2);
    uint32_t* PwL = PwH + 16 * PSTP;
    #pragma unroll
    for (int nt = 0; nt < 15; nt++) {
        uint32_t h_, l_;
        bf16_split2(acc[nt][0], acc[nt][1], h_, l_);
        PwH[gid*PSTP + nt*4 + tig] = h_;
        PwL[gid*PSTP + nt*4 + tig] = l_;
        bf16_split2(acc[nt][2], acc[nt][3], h_, l_);
        PwH[(gid+8)*PSTP + nt*4 + tig] = h_;
        PwL[(gid+8)*PSTP + nt*4 + tig] = l_;
    }
    PwH[gid*PSTP + 60 + tig] = 0;     PwL[gid*PSTP + 60 + tig] = 0;
    PwH[(gid+8)*PSTP + 60 + tig] = 0; PwL[(gid+8)*PSTP + 60 + tig] = 0;
    __syncwarp();

    int nb2 = n_base >> 1;
    float o[4][4];
    #pragma unroll
    for (int nt = 0; nt < 4; nt++)
        #pragma unroll
        for (int i = 0; i < 4; i++) o[nt][i] = 0.f;

    #pragma unroll
    for (int kt = 0; kt < 8; kt++) {
        int p0 = gid*PSTP + kt*8 + tig;
        int p1 = (gid+8)*PSTP + kt*8 + tig;
        uint32_t ph[4] = { PwH[p0], PwH[p1], PwH[p0 + 4], PwH[p1 + 4] };
        uint32_t pl[4] = { PwL[p0], PwL[p1], PwL[p0 + 4], PwL[p1 + 4] };
        #pragma unroll
        for (int nt = 0; nt < 4; nt++) {
            int vr = (nt*8 + gid)*VSTP + nb2 + kt*8 + tig;
            uint32_t vh[2] = { VtH[vr], VtH[vr + 4] };
            uint32_t vl[2] = { VtL[vr], VtL[vr + 4] };
            mma_bf16(o[nt], ph, vh);
            mma_bf16(o[nt], pl, vh);
            mma_bf16(o[nt], ph, vl);
        }
    }

    #pragma unroll
    for (int nt = 0; nt < 4; nt++) {
        int d = head*32 + nt*8 + 2*tig;
        float2 s0; s0.x = o[nt][0]*inv0; s0.y = o[nt][1]*inv0;
        float2 s1; s1.x = o[nt][2]*inv1; s1.y = o[nt][3]*inv1;
        *reinterpret_cast<float2*>(&attn_out[tok0*128 + d]) = s0;
        *reinterpret_cast<float2*>(&attn_out[tok1*128 + d]) = s1;
    }
}

// ---------------------------------------------------------------------------
// Transpose in: x (B,C,D,H,W) -> t (N=B*D*H*W, C)
// ---------------------------------------------------------------------------
__global__ void t_in_kernel(const float* __restrict__ x, float* __restrict__ t) {
    __shared__ float sm[16][17];
    int bz = blockIdx.z;
    int b = bz / (D_*H_);
    int rem = bz % (D_*H_);
    int d = rem / H_;
    int h = rem % H_;
    int w = blockIdx.x*16 + threadIdx.x;
    int c = blockIdx.y*16 + threadIdx.y;
    sm[threadIdx.y][threadIdx.x] =
        x[(( (long)b*C_ + c)*D_ + d)*(H_*W_) + h*W_ + w];
    __syncthreads();
    int c2 = blockIdx.y*16 + threadIdx.x;
    int w2 = blockIdx.x*16 + threadIdx.y;
    t[((((b*D_ + d)*H_ + h)*W_ + w2) * (long)C_) + c2] = sm[threadIdx.x][threadIdx.y];
}

// ---------------------------------------------------------------------------
// Launch
// ---------------------------------------------------------------------------
extern "C" void kernel_launch(void* const* d_in, const int* in_sizes, int n_in,
                              void* d_out, int out_size) {
    const float* x      = (const float*)d_in[0];
    const float* n1w    = (const float*)d_in[1];
    const float* n1b    = (const float*)d_in[2];
    const float* qkv_w  = (const float*)d_in[3];
    const float* qkv_b  = (const float*)d_in[4];
    const float* rpb    = (const float*)d_in[5];
    const float* proj_w = (const float*)d_in[6];
    const float* proj_b = (const float*)d_in[7];
    const float* n2w    = (const float*)d_in[8];
    const float* n2b    = (const float*)d_in[9];
    const float* fc1_w  = (const float*)d_in[10];
    const float* fc1_b  = (const float*)d_in[11];
    const float* fc2_w  = (const float*)d_in[12];
    const float* fc2_b  = (const float*)d_in[13];
    float* out = (float*)d_out;

    float *t_p, *qkv_p, *attn_p, *h1_p;
    float2* st_p;
    uint32_t *wh_p, *wl_p;
    cudaGetSymbolAddress((void**)&t_p,    g_t);
    cudaGetSymbolAddress((void**)&qkv_p,  g_qkv);
    cudaGetSymbolAddress((void**)&attn_p, g_attn);
    cudaGetSymbolAddress((void**)&h1_p,   g_h1);
    cudaGetSymbolAddress((void**)&st_p,   g_st);
    cudaGetSymbolAddress((void**)&wh_p,   g_wh);
    cudaGetSymbolAddress((void**)&wl_p,   g_wl);

    int attn_smem = ATTN_SMEM_U32 * (int)sizeof(uint32_t);
    cudaFuncSetAttribute(attn_mma_kernel, cudaFuncAttributeMaxDynamicSharedMemorySize, attn_smem);

    dim3 tb(16, 16);
    dim3 tg(W_/16, C_/16, B_*D_*H_);

    // 0. pre-split all weights to bf16 hi/lo
    wsplit_kernel<<<256, 256>>>(qkv_w, proj_w, fc1_w, fc2_w);
    // 1. transpose in
    t_in_kernel<<<tg, tb>>>(x, t_p);
    // 2. LN1 stats
    ln_stats_kernel<<<NTOK, 128>>>(t_p, st_p);
    // 3. qkv = LN1(t) @ qkv_w^T + b   (M=384, K=128)
    gemm_mma_kernel<0, true><<<dim3(384/64, NTOK/128), 256>>>(
        t_p, wh_p, wl_p, qkv_b, st_p, n1w, n1b, qkv_p, t_p, 384, 128);
    // 4. neighborhood attention
    attn_mma_kernel<<<dim3(36, NHEAD, B_*D_), 128, attn_smem>>>(qkv_p, rpb, attn_p);
    // 5. t += attn @ proj_w^T + b     (M=128, K=128)
    gemm_mma_kernel<2, false><<<dim3(128/64, NTOK/128), 256>>>(
        attn_p, wh_p + 24576, wl_p + 24576, proj_b, st_p, n1w, n1b, t_p, t_p, 128, 128);
    // 6. LN2 stats
    ln_stats_kernel<<<NTOK, 128>>>(t_p, st_p);
    // 7. h1 = gelu(LN2(t) @ fc1_w^T + b)  (M=256, K=128)
    gemm_mma_kernel<1, true><<<dim3(256/64, NTOK/128), 256>>>(
        t_p, wh_p + 32768, wl_p + 32768, fc1_b, st_p, n2w, n2b, h1_p, t_p, 256, 128);
    // 8. out = transpose(t + h1 @ fc2_w^T + b)   (M=128, K=256)
    gemm_mma_kernel<3, false><<<dim3(128/64, NTOK/128), 256>>>(
        h1_p, wh_p + 49152, wl_p + 49152, fc2_b, st_p, n2w, n2b, out, t_p, 128, 256);
}

// round 9
// speedup vs baseline: 2.4210x; 1.1057x over previous
#include <cuda_runtime.h>
#include <cuda_bf16.h>
#include <math.h>
#include <stdint.h>

// Problem constants
#define B_  2
#define C_  128
#define D_  4
#define H_  48
#define W_  48
#define NTOK (B_*D_*H_*W_)   // 18432
#define NHEAD 4
#define HD 32
#define KW 7

// Scratch (device globals — no allocation allowed)
__device__ float  g_t   [NTOK*128];
__device__ float  g_qkv [NTOK*384];
__device__ float  g_attn[NTOK*128];
__device__ float  g_h1  [NTOK*256];
__device__ float2 g_st  [NTOK];
// Pre-split weights (bf16x2 hi/lo packed k-pairs, PERMUTED within 8-pair groups)
// qkv @0 (24576), proj @24576 (8192), fc1 @32768 (16384), fc2 @49152 (16384)
__device__ uint32_t g_wh[65536];
__device__ uint32_t g_wl[65536];

// ===========================================================================
// Warp-level MMA helpers
// ===========================================================================
__device__ __forceinline__ void mma_bf16(float* c, const uint32_t* a, const uint32_t* b) {
    asm volatile(
        "mma.sync.aligned.m16n8k16.row.col.f32.bf16.bf16.f32 "
        "{%0,%1,%2,%3}, {%4,%5,%6,%7}, {%8,%9}, {%0,%1,%2,%3};"
        : "+f"(c[0]), "+f"(c[1]), "+f"(c[2]), "+f"(c[3])
        : "r"(a[0]), "r"(a[1]), "r"(a[2]), "r"(a[3]), "r"(b[0]), "r"(b[1]));
}

__device__ __forceinline__ void bf16_split2(float x0, float x1, uint32_t& hi, uint32_t& lo) {
    __nv_bfloat162 h = __floats2bfloat162_rn(x0, x1);
    float h0 = __bfloat162float(h.x);
    float h1 = __bfloat162float(h.y);
    __nv_bfloat162 l = __floats2bfloat162_rn(x0 - h0, x1 - h1);
    hi = *reinterpret_cast<uint32_t*>(&h);
    lo = *reinterpret_cast<uint32_t*>(&l);
}

// ===========================================================================
// Weight pre-split + permute: logical pair j within 8-group -> phys
// (t -> 2t, t+4 -> 2t+1) so fragment pairs (t, t+4) are adjacent.
// ===========================================================================
__global__ void wsplit_kernel(const float* __restrict__ qkv_w,
                              const float* __restrict__ proj_w,
                              const float* __restrict__ fc1_w,
                              const float* __restrict__ fc2_w) {
    int i = blockIdx.x * 256 + threadIdx.x;   // logical pair index 0..65535
    const float* src;
    int li;
    if (i < 24576)      { src = qkv_w;  li = i; }
    else if (i < 32768) { src = proj_w; li = i - 24576; }
    else if (i < 49152) { src = fc1_w;  li = i - 32768; }
    else                { src = fc2_w;  li = i - 49152; }
    float2 v = *reinterpret_cast<const float2*>(src + 2 * li);
    uint32_t h, l;
    bf16_split2(v.x, v.y, h, l);
    int jj = i & 7;
    int qp = (jj < 4) ? (jj << 1) : (((jj - 4) << 1) | 1);
    int dst = (i & ~7) | qp;
    g_wh[dst] = h;
    g_wl[dst] = l;
}

// ===========================================================================
// LayerNorm stats: warp per token
// ===========================================================================
__global__ void ln_stats_kernel(const float* __restrict__ in, float2* __restrict__ st) {
    int n = blockIdx.x * 8 + (threadIdx.x >> 5);
    int lane = threadIdx.x & 31;
    float4 v = *reinterpret_cast<const float4*>(in + (long)n*128 + lane*4);
    float s  = v.x + v.y + v.z + v.w;
    float s2 = v.x*v.x + v.y*v.y + v.z*v.z + v.w*v.w;
    #pragma unroll
    for (int o = 16; o > 0; o >>= 1) {
        s  += __shfl_xor_sync(0xffffffffu, s,  o);
        s2 += __shfl_xor_sync(0xffffffffu, s2, o);
    }
    if (lane == 0) {
        float m   = s  * (1.0f/128.0f);
        float var = s2 * (1.0f/128.0f) - m*m;
        st[n] = make_float2(m, rsqrtf(var + 1e-5f));
    }
}

// ===========================================================================
// Tensor-core GEMM (bf16 3-term split, m16n8k16), double-buffered pipeline.
// out[NTOK,M] = LN?(A)[NTOK,K] @ W[M,K]^T + bias (+epilogue)
// Block = 256 thr (8 warps): 128 tokens x 64 out cols. Warp = 32x32.
// Permuted pair layout, stride 24 u32: fragment loads are conflict-free LDS.64.
// EPI: 0 bias, 1 bias+GELU, 2 bias+residual into out,
//      3 bias + residual + direct transposed store to (B,C,D,H,W).
// ===========================================================================
#define GSTR 24
#define STAGE_U32 9216   // A: 128*24*2 = 6144 ; B: 64*24*2 = 3072
#define GEMM_SMEM (2 * STAGE_U32 * 4)

template<int EPI, bool LNA>
__global__ void __launch_bounds__(256, 2)
gemm_mma_kernel(const float* __restrict__ A,
                const uint32_t* __restrict__ WH,
                const uint32_t* __restrict__ WL,
                const float* __restrict__ bias,
                const float2* __restrict__ stats,
                const float* __restrict__ lnw,
                const float* __restrict__ lnb,
                float* __restrict__ out,
                const float* __restrict__ resid,
                int M, int K) {
    extern __shared__ uint32_t smg[];

    int tid = threadIdx.x;
    int wid = tid >> 5, lane = tid & 31;
    int warp_m = wid & 3;
    int warp_n = wid >> 2;
    int gid = lane >> 2;
    int tig = lane & 3;

    int n0 = blockIdx.y * 128;
    int m0 = blockIdx.x * 64;
    int Kp = K >> 1;
    int nch = K >> 5;

    // Staging coords
    int a_row = tid >> 3;         // with i*32 offset: rows 0..127
    int c4    = tid & 7;          // float4 column within 32-k chunk
    int w4 = c4 & 3;
    int ph0 = ((c4 & 4) << 1) + ((w4 < 2) ? (w4 * 4) : (w4 * 4 - 7)); // phys of pair 2*c4
    int b_row = tid >> 3;         // with i*32: rows 0..63
    int q8    = tid & 7;          // uint2 column

    float acc[2][4][4];
    #pragma unroll
    for (int mt = 0; mt < 2; mt++)
        #pragma unroll
        for (int nt = 0; nt < 4; nt++)
            #pragma unroll
            for (int i = 0; i < 4; i++) acc[mt][nt][i] = 0.f;

    float4 aV[4];
    uint2  bHv[2], bLv[2];

    // ---- load chunk 0 into regs
    #pragma unroll
    for (int i = 0; i < 4; i++) {
        int row = a_row + i * 32;
        float4 v = *reinterpret_cast<const float4*>(A + (long)(n0 + row) * K + c4 * 4);
        if (LNA) {
            float2 st = stats[n0 + row];
            float4 w4v = *reinterpret_cast<const float4*>(lnw + c4 * 4);
            float4 b4v = *reinterpret_cast<const float4*>(lnb + c4 * 4);
            v.x = (v.x - st.x) * st.y * w4v.x + b4v.x;
            v.y = (v.y - st.x) * st.y * w4v.y + b4v.y;
            v.z = (v.z - st.x) * st.y * w4v.z + b4v.z;
            v.w = (v.w - st.x) * st.y * w4v.w + b4v.w;
        }
        aV[i] = v;
    }
    #pragma unroll
    for (int i = 0; i < 2; i++) {
        int row = b_row + i * 32;
        long go = (long)(m0 + row) * Kp + q8 * 2;
        bHv[i] = *reinterpret_cast<const uint2*>(WH + go);
        bLv[i] = *reinterpret_cast<const uint2*>(WL + go);
    }
    // ---- store chunk 0 to stage 0
    {
        uint32_t* AH = smg;
        uint32_t* AL = AH + 3072;
        uint32_t* BH = AH + 6144;
        uint32_t* BL = AH + 7680;
        #pragma unroll
        for (int i = 0; i < 4; i++) {
            int row = a_row + i * 32;
            uint32_t h0, l0, h1, l1;
            bf16_split2(aV[i].x, aV[i].y, h0, l0);
            bf16_split2(aV[i].z, aV[i].w, h1, l1);
            int o = row * GSTR + ph0;
            AH[o] = h0; AH[o + 2] = h1;
            AL[o] = l0; AL[o + 2] = l1;
        }
        #pragma unroll
        for (int i = 0; i < 2; i++) {
            int row = b_row + i * 32;
            *reinterpret_cast<uint2*>(&BH[row * GSTR + q8 * 2]) = bHv[i];
            *reinterpret_cast<uint2*>(&BL[row * GSTR + q8 * 2]) = bLv[i];
        }
    }
    __syncthreads();

    for (int ch = 0; ch < nch; ch++) {
        // ---- issue next chunk LDGs (latency covered by compute below)
        if (ch + 1 < nch) {
            int k0 = (ch + 1) * 32;
            #pragma unroll
            for (int i = 0; i < 4; i++) {
                int row = a_row + i * 32;
                float4 v = *reinterpret_cast<const float4*>(A + (long)(n0 + row) * K + k0 + c4 * 4);
                if (LNA) {
                    float2 st = stats[n0 + row];
                    float4 w4v = *reinterpret_cast<const float4*>(lnw + k0 + c4 * 4);
                    float4 b4v = *reinterpret_cast<const float4*>(lnb + k0 + c4 * 4);
                    v.x = (v.x - st.x) * st.y * w4v.x + b4v.x;
                    v.y = (v.y - st.x) * st.y * w4v.y + b4v.y;
                    v.z = (v.z - st.x) * st.y * w4v.z + b4v.z;
                    v.w = (v.w - st.x) * st.y * w4v.w + b4v.w;
                }
                aV[i] = v;
            }
            int kp0 = (ch + 1) * 16;
            #pragma unroll
            for (int i = 0; i < 2; i++) {
                int row = b_row + i * 32;
                long go = (long)(m0 + row) * Kp + kp0 + q8 * 2;
                bHv[i] = *reinterpret_cast<const uint2*>(WH + go);
                bLv[i] = *reinterpret_cast<const uint2*>(WL + go);
            }
        }

        // ---- compute from stage ch&1
        {
            uint32_t* AH = smg + (ch & 1) * STAGE_U32;
            uint32_t* AL = AH + 3072;
            uint32_t* BH = AH + 6144;
            uint32_t* BL = AH + 7680;
            #pragma unroll
            for (int ks = 0; ks < 2; ks++) {
                int jc = ks * 8 + 2 * tig;
                uint32_t ahi[2][4], alo[2][4];
                #pragma unroll
                for (int mt = 0; mt < 2; mt++) {
                    int r = warp_m * 32 + mt * 16 + gid;
                    uint2 h0 = *reinterpret_cast<uint2*>(&AH[r * GSTR + jc]);
                    uint2 h1 = *reinterpret_cast<uint2*>(&AH[(r + 8) * GSTR + jc]);
                    uint2 l0 = *reinterpret_cast<uint2*>(&AL[r * GSTR + jc]);
                    uint2 l1 = *reinterpret_cast<uint2*>(&AL[(r + 8) * GSTR + jc]);
                    ahi[mt][0] = h0.x; ahi[mt][1] = h1.x; ahi[mt][2] = h0.y; ahi[mt][3] = h1.y;
                    alo[mt][0] = l0.x; alo[mt][1] = l1.x; alo[mt][2] = l0.y; alo[mt][3] = l1.y;
                }
                uint32_t bhi[4][2], blo[4][2];
                #pragma unroll
                for (int nt = 0; nt < 4; nt++) {
                    int br = warp_n * 32 + nt * 8 + gid;
                    uint2 bh = *reinterpret_cast<uint2*>(&BH[br * GSTR + jc]);
                    uint2 bl = *reinterpret_cast<uint2*>(&BL[br * GSTR + jc]);
                    bhi[nt][0] = bh.x; bhi[nt][1] = bh.y;
                    blo[nt][0] = bl.x; blo[nt][1] = bl.y;
                }
                #pragma unroll
                for (int mt = 0; mt < 2; mt++)
                    #pragma unroll
                    for (int nt = 0; nt < 4; nt++) {
                        mma_bf16(acc[mt][nt], ahi[mt], bhi[nt]);
                        mma_bf16(acc[mt][nt], alo[mt], bhi[nt]);
                        mma_bf16(acc[mt][nt], ahi[mt], blo[nt]);
                    }
            }
        }

        // ---- split + store next chunk into other stage
        if (ch + 1 < nch) {
            uint32_t* AH = smg + ((ch + 1) & 1) * STAGE_U32;
            uint32_t* AL = AH + 3072;
            uint32_t* BH = AH + 6144;
            uint32_t* BL = AH + 7680;
            #pragma unroll
            for (int i = 0; i < 4; i++) {
                int row = a_row + i * 32;
                uint32_t h0, l0, h1, l1;
                bf16_split2(aV[i].x, aV[i].y, h0, l0);
                bf16_split2(aV[i].z, aV[i].w, h1, l1);
                int o = row * GSTR + ph0;
                AH[o] = h0; AH[o + 2] = h1;
                AL[o] = l0; AL[o + 2] = l1;
            }
            #pragma unroll
            for (int i = 0; i < 2; i++) {
                int row = b_row + i * 32;
                *reinterpret_cast<uint2*>(&BH[row * GSTR + q8 * 2]) = bHv[i];
                *reinterpret_cast<uint2*>(&BL[row * GSTR + q8 * 2]) = bLv[i];
            }
        }
        __syncthreads();
    }

    // ---- epilogue
    int row_base = n0 + warp_m * 32;
    int col_base = m0 + warp_n * 32;
    #pragma unroll
    for (int nt = 0; nt < 4; nt++) {
        int col = col_base + nt * 8 + 2 * tig;
        float b0 = bias[col], b1 = bias[col + 1];
        #pragma unroll
        for (int mt = 0; mt < 2; mt++) {
            #pragma unroll
            for (int half = 0; half < 2; half++) {
                int r = row_base + mt * 16 + gid + half * 8;
                float v0 = acc[mt][nt][half * 2 + 0] + b0;
                float v1 = acc[mt][nt][half * 2 + 1] + b1;
                if (EPI == 1) {
                    v0 = 0.5f * v0 * (1.0f + erff(v0 * 0.70710678118654752f));
                    v1 = 0.5f * v1 * (1.0f + erff(v1 * 0.70710678118654752f));
                }
                if (EPI == 3) {
                    float2 rv = *reinterpret_cast<const float2*>(resid + (long)r * 128 + col);
                    v0 += rv.x; v1 += rv.y;
                    long o = (long)r + (r >= 9216 ? 1170432L : 0L) + (long)col * 9216;
                    out[o]        = v0;
                    out[o + 9216] = v1;
                } else {
                    float2* dst = reinterpret_cast<float2*>(out + (long)r * M + col);
                    if (EPI == 2) {
                        float2 old = *dst;
                        v0 += old.x; v1 += old.y;
                    }
                    float2 st; st.x = v0; st.y = v1;
                    *dst = st;
                }
            }
        }
    }
}

// ===========================================================================
// Tensor-core neighborhood attention (unchanged from R7/R8)
// ===========================================================================
#define AGSTR 20
#define VSTP  116
#define PSTP  68
#define ATTN_SMEM_U32 (2*224*AGSTR + 2*32*VSTP + 170)

__global__ void __launch_bounds__(128, 3)
attn_mma_kernel(const float* __restrict__ qkv,
                const float* __restrict__ rpb,
                float* __restrict__ attn_out) {
    extern __shared__ uint32_t smu[];
    uint32_t* KsH = smu;
    uint32_t* KsL = KsH + 224*AGSTR;
    uint32_t* VtH = KsL + 224*AGSTR;
    uint32_t* VtL = VtH + 32*VSTP;
    float*    rb  = reinterpret_cast<float*>(VtL + 32*VSTP);

    int tile = blockIdx.x, head = blockIdx.y, bd = blockIdx.z;
    int h0 = (tile / 6) * 8;
    int w0 = (tile % 6) * 8;
    int kh0 = min(max(h0 - 3, 0), H_ - KW);
    int kw0 = min(max(w0 - 3, 0), W_ - KW);
    int tid = threadIdx.x;

    for (int e = tid; e < 196*8; e += 128) {
        int key = e >> 3, d4 = e & 7;
        int kr = key / 14, kc = key % 14;
        int gh = min(kh0 + kr, H_-1);
        int gw = min(kw0 + kc, W_-1);
        const float* base = qkv + ((long)(bd*H_ + gh)*W_ + gw)*384 + head*32 + d4*4 + 128;
        float4 k4 = *reinterpret_cast<const float4*>(base);
        uint32_t h0_, l0_, h1_, l1_;
        bf16_split2(k4.x, k4.y, h0_, l0_);
        bf16_split2(k4.z, k4.w, h1_, l1_);
        int o = key*AGSTR + d4*2;
        KsH[o] = h0_; KsH[o+1] = h1_;
        KsL[o] = l0_; KsL[o+1] = l1_;
    }
    for (int e = tid; e < 98*8; e += 128) {
        int kp = e >> 3, d4 = e & 7;
        int keyA = 2*kp, keyB = 2*kp + 1;
        int ghA = min(kh0 + keyA/14, H_-1), gwA = min(kw0 + keyA%14, W_-1);
        int ghB = min(kh0 + keyB/14, H_-1), gwB = min(kw0 + keyB%14, W_-1);
        float4 va = *reinterpret_cast<const float4*>(
            qkv + ((long)(bd*H_ + ghA)*W_ + gwA)*384 + head*32 + d4*4 + 256);
        float4 vb = *reinterpret_cast<const float4*>(
            qkv + ((long)(bd*H_ + ghB)*W_ + gwB)*384 + head*32 + d4*4 + 256);
        uint32_t h_, l_;
        bf16_split2(va.x, vb.x, h_, l_); VtH[(d4*4+0)*VSTP + kp] = h_; VtL[(d4*4+0)*VSTP + kp] = l_;
        bf16_split2(va.y, vb.y, h_, l_); VtH[(d4*4+1)*VSTP + kp] = h_; VtL[(d4*4+1)*VSTP + kp] = l_;
        bf16_split2(va.z, vb.z, h_, l_); VtH[(d4*4+2)*VSTP + kp] = h_; VtL[(d4*4+2)*VSTP + kp] = l_;
        bf16_split2(va.w, vb.w, h_, l_); VtH[(d4*4+3)*VSTP + kp] = h_; VtL[(d4*4+3)*VSTP + kp] = l_;
    }
    for (int e = tid; e < 32*14; e += 128) {
        int dm = e / 14, kp = 98 + (e % 14);
        VtH[dm*VSTP + kp] = 0; VtL[dm*VSTP + kp] = 0;
    }
    for (int i = tid; i < 169; i += 128) rb[i] = rpb[head*169 + i];
    __syncthreads();

    int warp = tid >> 5, lane = tid & 31;
    int gid = lane >> 2, tig = lane & 3;

    int hq0 = h0 + 2*warp;
    int hq1 = hq0 + 1;
    int wq  = w0 + gid;
    long tok0 = (long)(bd*H_ + hq0)*W_ + wq;
    long tok1 = tok0 + W_;
    int rel0 = min(max(hq0-3, 0), H_-KW) - kh0;
    int rel1 = min(max(hq1-3, 0), H_-KW) - kh0;
    int ws   = min(max(wq-3, 0), W_-KW) - kw0;
    int n_base = ((min(rel0, rel1) * 14) >> 3) * 8;

    const float scale = 0.17677669529663687f;
    uint32_t qh[2][4], ql[2][4];
    #pragma unroll
    for (int ks = 0; ks < 2; ks++) {
        const float* q0p = qkv + tok0*384 + head*32 + ks*16 + 2*tig;
        const float* q1p = qkv + tok1*384 + head*32 + ks*16 + 2*tig;
        float2 a = *reinterpret_cast<const float2*>(q0p);
        float2 b = *reinterpret_cast<const float2*>(q1p);
        float2 c = *reinterpret_cast<const float2*>(q0p + 8);
        float2 d = *reinterpret_cast<const float2*>(q1p + 8);
        bf16_split2(a.x*scale, a.y*scale, qh[ks][0], ql[ks][0]);
        bf16_split2(b.x*scale, b.y*scale, qh[ks][1], ql[ks][1]);
        bf16_split2(c.x*scale, c.y*scale, qh[ks][2], ql[ks][2]);
        bf16_split2(d.x*scale, d.y*scale, qh[ks][3], ql[ks][3]);
    }

    float acc[15][4];
    #pragma unroll
    for (int nt = 0; nt < 15; nt++)
        #pragma unroll
        for (int i = 0; i < 4; i++) acc[nt][i] = 0.f;

    #pragma unroll
    for (int nt = 0; nt < 15; nt++) {
        int key = n_base + nt*8 + gid;
        #pragma unroll
        for (int ks = 0; ks < 2; ks++) {
            int o = key*AGSTR + ks*8 + tig;
            uint32_t bh[2] = { KsH[o], KsH[o + 4] };
            uint32_t bl[2] = { KsL[o], KsL[o + 4] };
            mma_bf16(acc[nt], qh[ks], bh);
            mma_bf16(acc[nt], ql[ks], bh);
            mma_bf16(acc[nt], qh[ks], bl);
        }
    }

    int bh0c = kh0 - hq0 + 6;
    int bh1c = kh0 - hq1 + 6;
    int bwc  = kw0 - wq + 6;
    float mx0 = -1e30f, mx1 = -1e30f;
    #pragma unroll
    for (int nt = 0; nt < 15; nt++) {
        #pragma unroll
        for (int cc = 0; cc < 2; cc++) {
            int n = n_base + nt*8 + 2*tig + cc;
            int kr = n / 14;
            int kc = n - kr*14;
            bool vw = (unsigned)(kc - ws) <= 6u;
            bool v0 = vw && (unsigned)(kr - rel0) <= 6u;
            bool v1 = vw && (unsigned)(kr - rel1) <= 6u;
            float s0 = v0 ? acc[nt][cc]   + rb[(bh0c+kr)*13 + bwc + kc] : -1e30f;
            float s1 = v1 ? acc[nt][2+cc] + rb[(bh1c+kr)*13 + bwc + kc] : -1e30f;
            acc[nt][cc]   = s0;
            acc[nt][2+cc] = s1;
            mx0 = fmaxf(mx0, s0);
            mx1 = fmaxf(mx1, s1);
        }
    }
    mx0 = fmaxf(mx0, __shfl_xor_sync(0xffffffffu, mx0, 1));
    mx0 = fmaxf(mx0, __shfl_xor_sync(0xffffffffu, mx0, 2));
    mx1 = fmaxf(mx1, __shfl_xor_sync(0xffffffffu, mx1, 1));
    mx1 = fmaxf(mx1, __shfl_xor_sync(0xffffffffu, mx1, 2));

    float sum0 = 0.f, sum1 = 0.f;
    #pragma unroll
    for (int nt = 0; nt < 15; nt++) {
        #pragma unroll
        for (int cc = 0; cc < 2; cc++) {
            float e0 = __expf(acc[nt][cc]   - mx0);
            float e1 = __expf(acc[nt][2+cc] - mx1);
            acc[nt][cc]   = e0;
            acc[nt][2+cc] = e1;
            sum0 += e0;
            sum1 += e1;
        }
    }
    sum0 += __shfl_xor_sync(0xffffffffu, sum0, 1);
    sum0 += __shfl_xor_sync(0xffffffffu, sum0, 2);
    sum1 += __shfl_xor_sync(0xffffffffu, sum1, 1);
    sum1 += __shfl_xor_sync(0xffffffffu, sum1, 2);
    float inv0 = 1.0f / sum0;
    float inv1 = 1.0f / sum1;

    __syncthreads();
    uint32_t* PwH = smu + warp * (16 * PSTP * 2);
    uint32_t* PwL = PwH + 16 * PSTP;
    #pragma unroll
    for (int nt = 0; nt < 15; nt++) {
        uint32_t h_, l_;
        bf16_split2(acc[nt][0], acc[nt][1], h_, l_);
        PwH[gid*PSTP + nt*4 + tig] = h_;
        PwL[gid*PSTP + nt*4 + tig] = l_;
        bf16_split2(acc[nt][2], acc[nt][3], h_, l_);
        PwH[(gid+8)*PSTP + nt*4 + tig] = h_;
        PwL[(gid+8)*PSTP + nt*4 + tig] = l_;
    }
    PwH[gid*PSTP + 60 + tig] = 0;     PwL[gid*PSTP + 60 + tig] = 0;
    PwH[(gid+8)*PSTP + 60 + tig] = 0; PwL[(gid+8)*PSTP + 60 + tig] = 0;
    __syncwarp();

    int nb2 = n_base >> 1;
    float o[4][4];
    #pragma unroll
    for (int nt = 0; nt < 4; nt++)
        #pragma unroll
        for (int i = 0; i < 4; i++) o[nt][i] = 0.f;

    #pragma unroll
    for (int kt = 0; kt < 8; kt++) {
        int p0 = gid*PSTP + kt*8 + tig;
        int p1 = (gid+8)*PSTP + kt*8 + tig;
        uint32_t ph[4] = { PwH[p0], PwH[p1], PwH[p0 + 4], PwH[p1 + 4] };
        uint32_t pl[4] = { PwL[p0], PwL[p1], PwL[p0 + 4], PwL[p1 + 4] };
        #pragma unroll
        for (int nt = 0; nt < 4; nt++) {
            int vr = (nt*8 + gid)*VSTP + nb2 + kt*8 + tig;
            uint32_t vh[2] = { VtH[vr], VtH[vr + 4] };
            uint32_t vl[2] = { VtL[vr], VtL[vr + 4] };
            mma_bf16(o[nt], ph, vh);
            mma_bf16(o[nt], pl, vh);
            mma_bf16(o[nt], ph, vl);
        }
    }

    #pragma unroll
    for (int nt = 0; nt < 4; nt++) {
        int d = head*32 + nt*8 + 2*tig;
        float2 s0; s0.x = o[nt][0]*inv0; s0.y = o[nt][1]*inv0;
        float2 s1; s1.x = o[nt][2]*inv1; s1.y = o[nt][3]*inv1;
        *reinterpret_cast<float2*>(&attn_out[tok0*128 + d]) = s0;
        *reinterpret_cast<float2*>(&attn_out[tok1*128 + d]) = s1;
    }
}

// ---------------------------------------------------------------------------
// Transpose in: x (B,C,D,H,W) -> t (N=B*D*H*W, C)
// ---------------------------------------------------------------------------
__global__ void t_in_kernel(const float* __restrict__ x, float* __restrict__ t) {
    __shared__ float sm[16][17];
    int bz = blockIdx.z;
    int b = bz / (D_*H_);
    int rem = bz % (D_*H_);
    int d = rem / H_;
    int h = rem % H_;
    int w = blockIdx.x*16 + threadIdx.x;
    int c = blockIdx.y*16 + threadIdx.y;
    sm[threadIdx.y][threadIdx.x] =
        x[(( (long)b*C_ + c)*D_ + d)*(H_*W_) + h*W_ + w];
    __syncthreads();
    int c2 = blockIdx.y*16 + threadIdx.x;
    int w2 = blockIdx.x*16 + threadIdx.y;
    t[((((b*D_ + d)*H_ + h)*W_ + w2) * (long)C_) + c2] = sm[threadIdx.x][threadIdx.y];
}

// ---------------------------------------------------------------------------
// Launch
// ---------------------------------------------------------------------------
extern "C" void kernel_launch(void* const* d_in, const int* in_sizes, int n_in,
                              void* d_out, int out_size) {
    const float* x      = (const float*)d_in[0];
    const float* n1w    = (const float*)d_in[1];
    const float* n1b    = (const float*)d_in[2];
    const float* qkv_w  = (const float*)d_in[3];
    const float* qkv_b  = (const float*)d_in[4];
    const float* rpb    = (const float*)d_in[5];
    const float* proj_w = (const float*)d_in[6];
    const float* proj_b = (const float*)d_in[7];
    const float* n2w    = (const float*)d_in[8];
    const float* n2b    = (const float*)d_in[9];
    const float* fc1_w  = (const float*)d_in[10];
    const float* fc1_b  = (const float*)d_in[11];
    const float* fc2_w  = (const float*)d_in[12];
    const float* fc2_b  = (const float*)d_in[13];
    float* out = (float*)d_out;

    float *t_p, *qkv_p, *attn_p, *h1_p;
    float2* st_p;
    uint32_t *wh_p, *wl_p;
    cudaGetSymbolAddress((void**)&t_p,    g_t);
    cudaGetSymbolAddress((void**)&qkv_p,  g_qkv);
    cudaGetSymbolAddress((void**)&attn_p, g_attn);
    cudaGetSymbolAddress((void**)&h1_p,   g_h1);
    cudaGetSymbolAddress((void**)&st_p,   g_st);
    cudaGetSymbolAddress((void**)&wh_p,   g_wh);
    cudaGetSymbolAddress((void**)&wl_p,   g_wl);

    int attn_smem = ATTN_SMEM_U32 * (int)sizeof(uint32_t);
    cudaFuncSetAttribute(attn_mma_kernel, cudaFuncAttributeMaxDynamicSharedMemorySize, attn_smem);
    cudaFuncSetAttribute(gemm_mma_kernel<0,true >, cudaFuncAttributeMaxDynamicSharedMemorySize, GEMM_SMEM);
    cudaFuncSetAttribute(gemm_mma_kernel<1,true >, cudaFuncAttributeMaxDynamicSharedMemorySize, GEMM_SMEM);
    cudaFuncSetAttribute(gemm_mma_kernel<2,false>, cudaFuncAttributeMaxDynamicSharedMemorySize, GEMM_SMEM);
    cudaFuncSetAttribute(gemm_mma_kernel<3,false>, cudaFuncAttributeMaxDynamicSharedMemorySize, GEMM_SMEM);

    dim3 tb(16, 16);
    dim3 tg(W_/16, C_/16, B_*D_*H_);

    // 0. pre-split + permute all weights to bf16 hi/lo
    wsplit_kernel<<<256, 256>>>(qkv_w, proj_w, fc1_w, fc2_w);
    // 1. transpose in
    t_in_kernel<<<tg, tb>>>(x, t_p);
    // 2. LN1 stats
    ln_stats_kernel<<<NTOK/8, 256>>>(t_p, st_p);
    // 3. qkv = LN1(t) @ qkv_w^T + b   (M=384, K=128)
    gemm_mma_kernel<0, true><<<dim3(384/64, NTOK/128), 256, GEMM_SMEM>>>(
        t_p, wh_p, wl_p, qkv_b, st_p, n1w, n1b, qkv_p, t_p, 384, 128);
    // 4. neighborhood attention
    attn_mma_kernel<<<dim3(36, NHEAD, B_*D_), 128, attn_smem>>>(qkv_p, rpb, attn_p);
    // 5. t += attn @ proj_w^T + b     (M=128, K=128)
    gemm_mma_kernel<2, false><<<dim3(128/64, NTOK/128), 256, GEMM_SMEM>>>(
        attn_p, wh_p + 24576, wl_p + 24576, proj_b, st_p, n1w, n1b, t_p, t_p, 128, 128);
    // 6. LN2 stats
    ln_stats_kernel<<<NTOK/8, 256>>>(t_p, st_p);
    // 7. h1 = gelu(LN2(t) @ fc1_w^T + b)  (M=256, K=128)
    gemm_mma_kernel<1, true><<<dim3(256/64, NTOK/128), 256, GEMM_SMEM>>>(
        t_p, wh_p + 32768, wl_p + 32768, fc1_b, st_p, n2w, n2b, h1_p, t_p, 256, 128);
    // 8. out = transpose(t + h1 @ fc2_w^T + b)   (M=128, K=256)
    gemm_mma_kernel<3, false><<<dim3(128/64, NTOK/128), 256, GEMM_SMEM>>>(
        h1_p, wh_p + 49152, wl_p + 49152, fc2_b, st_p, n2w, n2b, out, t_p, 128, 256);
}

// round 10
// speedup vs baseline: 2.5186x; 1.0403x over previous
#include <cuda_runtime.h>
#include <cuda_bf16.h>
#include <math.h>
#include <stdint.h>

// Problem constants
#define B_  2
#define C_  128
#define D_  4
#define H_  48
#define W_  48
#define NTOK (B_*D_*H_*W_)   // 18432
#define NHEAD 4
#define HD 32
#define KW 7

// Scratch (device globals — no allocation allowed)
__device__ float    g_t   [NTOK*128];
__device__ float    g_qkv [NTOK*384];
__device__ float    g_h1d [4];              // dummy keep-alive
__device__ uint32_t g_ah  [NTOK*64];        // pre-split activations (hi), 64 pairs/row
__device__ uint32_t g_al  [NTOK*64];
__device__ uint32_t g_bh  [NTOK*128];       // pre-split h1 (hi), 128 pairs/row
__device__ uint32_t g_bl  [NTOK*128];
// Pre-split weights (bf16x2 hi/lo packed k-pairs, PERMUTED within 8-pair groups)
__device__ uint32_t g_wh[65536];
__device__ uint32_t g_wl[65536];

#define PERMJ(j) ((j) < 4 ? 2*(j) : 2*(j)-7)

// ===========================================================================
// Helpers
// ===========================================================================
__device__ __forceinline__ void mma_bf16(float* c, const uint32_t* a, const uint32_t* b) {
    asm volatile(
        "mma.sync.aligned.m16n8k16.row.col.f32.bf16.bf16.f32 "
        "{%0,%1,%2,%3}, {%4,%5,%6,%7}, {%8,%9}, {%0,%1,%2,%3};"
        : "+f"(c[0]), "+f"(c[1]), "+f"(c[2]), "+f"(c[3])
        : "r"(a[0]), "r"(a[1]), "r"(a[2]), "r"(a[3]), "r"(b[0]), "r"(b[1]));
}

__device__ __forceinline__ void bf16_split2(float x0, float x1, uint32_t& hi, uint32_t& lo) {
    __nv_bfloat162 h = __floats2bfloat162_rn(x0, x1);
    float h0 = __bfloat162float(h.x);
    float h1 = __bfloat162float(h.y);
    __nv_bfloat162 l = __floats2bfloat162_rn(x0 - h0, x1 - h1);
    hi = *reinterpret_cast<uint32_t*>(&h);
    lo = *reinterpret_cast<uint32_t*>(&l);
}

#define CP_ASYNC16(dst_u32, src_ptr) \
    asm volatile("cp.async.cg.shared.global [%0], [%1], 16;" \
        :: "r"(dst_u32), "l"(__cvta_generic_to_global(src_ptr)) : "memory")
#define CP_COMMIT() asm volatile("cp.async.commit_group;" ::: "memory")
#define CP_WAIT1()  asm volatile("cp.async.wait_group 1;" ::: "memory")
#define CP_WAIT0()  asm volatile("cp.async.wait_group 0;" ::: "memory")

// ===========================================================================
// Weight pre-split + permute (pair j in 8-group -> PERMJ(j))
// ===========================================================================
__global__ void wsplit_kernel(const float* __restrict__ qkv_w,
                              const float* __restrict__ proj_w,
                              const float* __restrict__ fc1_w,
                              const float* __restrict__ fc2_w) {
    int i = blockIdx.x * 256 + threadIdx.x;
    const float* src;
    int li;
    if (i < 24576)      { src = qkv_w;  li = i; }
    else if (i < 32768) { src = proj_w; li = i - 24576; }
    else if (i < 49152) { src = fc1_w;  li = i - 32768; }
    else                { src = fc2_w;  li = i - 49152; }
    float2 v = *reinterpret_cast<const float2*>(src + 2 * li);
    uint32_t h, l;
    bf16_split2(v.x, v.y, h, l);
    int dst = (i & ~7) | PERMJ(i & 7);
    g_wh[dst] = h;
    g_wl[dst] = l;
}

// ===========================================================================
// Fused LN + split + permute: warp per token -> g_ah/g_al
// ===========================================================================
__global__ void ln_prep_kernel(const float* __restrict__ in,
                               const float* __restrict__ w,
                               const float* __restrict__ b,
                               uint32_t* __restrict__ ah,
                               uint32_t* __restrict__ al) {
    int n = blockIdx.x * 8 + (threadIdx.x >> 5);
    int lane = threadIdx.x & 31;
    float4 v = *reinterpret_cast<const float4*>(in + (long)n*128 + lane*4);
    float s  = v.x + v.y + v.z + v.w;
    float s2 = v.x*v.x + v.y*v.y + v.z*v.z + v.w*v.w;
    #pragma unroll
    for (int o = 16; o > 0; o >>= 1) {
        s  += __shfl_xor_sync(0xffffffffu, s,  o);
        s2 += __shfl_xor_sync(0xffffffffu, s2, o);
    }
    float m    = s  * (1.0f/128.0f);
    float rstd = rsqrtf(s2 * (1.0f/128.0f) - m*m + 1e-5f);
    float4 wv = *reinterpret_cast<const float4*>(w + lane*4);
    float4 bv = *reinterpret_cast<const float4*>(b + lane*4);
    float y0 = (v.x - m) * rstd * wv.x + bv.x;
    float y1 = (v.y - m) * rstd * wv.y + bv.y;
    float y2 = (v.z - m) * rstd * wv.z + bv.z;
    float y3 = (v.w - m) * rstd * wv.w + bv.w;
    uint32_t h0, l0, h1, l1;
    bf16_split2(y0, y1, h0, l0);
    bf16_split2(y2, y3, h1, l1);
    int p0 = 2*lane, p1 = 2*lane + 1;
    int i0 = (p0 & ~7) | PERMJ(p0 & 7);
    int i1 = (p1 & ~7) | PERMJ(p1 & 7);
    long base = (long)n * 64;
    ah[base + i0] = h0; ah[base + i1] = h1;
    al[base + i0] = l0; al[base + i1] = l1;
}

// ===========================================================================
// Tensor-core GEMM: cp.async 3-stage ring, pre-split A and B.
// out[NTOK,M] = A[NTOK,K] @ W[M,K]^T + bias (+epilogue)
// Block = 256 thr (8 warps): 128 tokens x 64 out cols. Warp = 32x32.
// EPI: 0 bias fp32 out; 2 bias+residual into out;
//      3 bias+residual(resid)+transposed store; 4 bias+GELU+split to outH/outL.
// ===========================================================================
#define GSTR 24
#define STAGE_U32 9216
#define NSTAGE 3
#define GEMM_SMEM (NSTAGE * STAGE_U32 * 4)

template<int EPI>
__global__ void __launch_bounds__(256, 2)
gemm_cp_kernel(const uint32_t* __restrict__ AHg,
               const uint32_t* __restrict__ ALg,
               const uint32_t* __restrict__ WH,
               const uint32_t* __restrict__ WL,
               const float* __restrict__ bias,
               float* __restrict__ out,
               uint32_t* __restrict__ outH,
               uint32_t* __restrict__ outL,
               const float* __restrict__ resid,
               int M, int K) {
    extern __shared__ uint32_t smg[];
    uint32_t smb = (uint32_t)__cvta_generic_to_shared(smg);

    int tid = threadIdx.x;
    int wid = tid >> 5, lane = tid & 31;
    int warp_m = wid & 3;
    int warp_n = wid >> 2;
    int gid = lane >> 2;
    int tig = lane & 3;

    int n0 = blockIdx.y * 128;
    int m0 = blockIdx.x * 64;
    int Kp = K >> 1;
    int nch = K >> 5;

    float acc[2][4][4];
    #pragma unroll
    for (int mt = 0; mt < 2; mt++)
        #pragma unroll
        for (int nt = 0; nt < 4; nt++)
            #pragma unroll
            for (int i = 0; i < 4; i++) acc[mt][nt][i] = 0.f;

    // cp.async staging: A = 512 16B segs (2/thread per buf), B = 256 (1/thread per buf)
    int a_row0 = tid >> 2,        a_q0 = tid & 3;
    int a_row1 = (tid + 256) >> 2, a_q1 = a_row1 & 0; // computed below properly
    a_row1 = (tid + 256) >> 2;  a_q1 = (tid + 256) & 3;
    int b_row = tid >> 2, b_q = tid & 3;

    auto issue = [&](int ch, int s) {
        uint32_t base = smb + (uint32_t)(s * STAGE_U32) * 4u;
        long ka = (long)ch * 16;
        // A hi/lo: rows a_row0, a_row1
        CP_ASYNC16(base + (a_row0*GSTR + a_q0*4)*4,        AHg + (long)(n0 + a_row0)*Kp + ka + a_q0*4);
        CP_ASYNC16(base + (a_row1*GSTR + a_q1*4)*4,        AHg + (long)(n0 + a_row1)*Kp + ka + a_q1*4);
        CP_ASYNC16(base + (3072 + a_row0*GSTR + a_q0*4)*4, ALg + (long)(n0 + a_row0)*Kp + ka + a_q0*4);
        CP_ASYNC16(base + (3072 + a_row1*GSTR + a_q1*4)*4, ALg + (long)(n0 + a_row1)*Kp + ka + a_q1*4);
        // B hi/lo
        CP_ASYNC16(base + (6144 + b_row*GSTR + b_q*4)*4,   WH + (long)(m0 + b_row)*Kp + ka + b_q*4);
        CP_ASYNC16(base + (7680 + b_row*GSTR + b_q*4)*4,   WL + (long)(m0 + b_row)*Kp + ka + b_q*4);
        CP_COMMIT();
    };

    issue(0, 0);
    issue(1, 1);

    int cs = 0;
    for (int ch = 0; ch < nch; ch++) {
        if (ch + 2 < nch) { CP_WAIT1(); } else { CP_WAIT0(); }
        __syncthreads();

        uint32_t* AH = smg + cs * STAGE_U32;
        uint32_t* AL = AH + 3072;
        uint32_t* BH = AH + 6144;
        uint32_t* BL = AH + 7680;
        #pragma unroll
        for (int ks = 0; ks < 2; ks++) {
            int jc = ks * 8 + 2 * tig;
            uint32_t ahi[2][4], alo[2][4];
            #pragma unroll
            for (int mt = 0; mt < 2; mt++) {
                int r = warp_m * 32 + mt * 16 + gid;
                uint2 h0 = *reinterpret_cast<uint2*>(&AH[r * GSTR + jc]);
                uint2 h1 = *reinterpret_cast<uint2*>(&AH[(r + 8) * GSTR + jc]);
                uint2 l0 = *reinterpret_cast<uint2*>(&AL[r * GSTR + jc]);
                uint2 l1 = *reinterpret_cast<uint2*>(&AL[(r + 8) * GSTR + jc]);
                ahi[mt][0] = h0.x; ahi[mt][1] = h1.x; ahi[mt][2] = h0.y; ahi[mt][3] = h1.y;
                alo[mt][0] = l0.x; alo[mt][1] = l1.x; alo[mt][2] = l0.y; alo[mt][3] = l1.y;
            }
            uint32_t bhi[4][2], blo[4][2];
            #pragma unroll
            for (int nt = 0; nt < 4; nt++) {
                int br = warp_n * 32 + nt * 8 + gid;
                uint2 bh = *reinterpret_cast<uint2*>(&BH[br * GSTR + jc]);
                uint2 bl = *reinterpret_cast<uint2*>(&BL[br * GSTR + jc]);
                bhi[nt][0] = bh.x; bhi[nt][1] = bh.y;
                blo[nt][0] = bl.x; blo[nt][1] = bl.y;
            }
            #pragma unroll
            for (int mt = 0; mt < 2; mt++)
                #pragma unroll
                for (int nt = 0; nt < 4; nt++) {
                    mma_bf16(acc[mt][nt], ahi[mt], bhi[nt]);
                    mma_bf16(acc[mt][nt], alo[mt], bhi[nt]);
                    mma_bf16(acc[mt][nt], ahi[mt], blo[nt]);
                }
        }

        if (ch + 2 < nch) {
            int s2 = cs + 2; if (s2 >= 3) s2 -= 3;
            issue(ch + 2, s2);
        }
        cs = (cs + 1 == 3) ? 0 : cs + 1;
    }

    // ---- epilogue
    int row_base = n0 + warp_m * 32;
    int col_base = m0 + warp_n * 32;
    #pragma unroll
    for (int nt = 0; nt < 4; nt++) {
        int col = col_base + nt * 8 + 2 * tig;
        float b0 = bias[col], b1 = bias[col + 1];
        #pragma unroll
        for (int mt = 0; mt < 2; mt++) {
            #pragma unroll
            for (int half = 0; half < 2; half++) {
                int r = row_base + mt * 16 + gid + half * 8;
                float v0 = acc[mt][nt][half * 2 + 0] + b0;
                float v1 = acc[mt][nt][half * 2 + 1] + b1;
                if (EPI == 4) {
                    v0 = 0.5f * v0 * (1.0f + erff(v0 * 0.70710678118654752f));
                    v1 = 0.5f * v1 * (1.0f + erff(v1 * 0.70710678118654752f));
                    uint32_t h_, l_;
                    bf16_split2(v0, v1, h_, l_);
                    int p = col >> 1;
                    int idx = (p & ~7) | PERMJ(p & 7);
                    outH[(long)r * 128 + idx] = h_;
                    outL[(long)r * 128 + idx] = l_;
                } else if (EPI == 3) {
                    float2 rv = *reinterpret_cast<const float2*>(resid + (long)r * 128 + col);
                    v0 += rv.x; v1 += rv.y;
                    long o = (long)r + (r >= 9216 ? 1170432L : 0L) + (long)col * 9216;
                    out[o]        = v0;
                    out[o + 9216] = v1;
                } else {
                    float2* dst = reinterpret_cast<float2*>(out + (long)r * M + col);
                    if (EPI == 2) {
                        float2 old = *dst;
                        v0 += old.x; v1 += old.y;
                    }
                    float2 st; st.x = v0; st.y = v1;
                    *dst = st;
                }
            }
        }
    }
}

// ===========================================================================
// Tensor-core neighborhood attention (R7 core; epilogue writes pre-split)
// ===========================================================================
#define AGSTR 20
#define VSTP  116
#define PSTP  68
#define ATTN_SMEM_U32 (2*224*AGSTR + 2*32*VSTP + 170)

__global__ void __launch_bounds__(128, 3)
attn_mma_kernel(const float* __restrict__ qkv,
                const float* __restrict__ rpb,
                uint32_t* __restrict__ outH,
                uint32_t* __restrict__ outL) {
    extern __shared__ uint32_t smu[];
    uint32_t* KsH = smu;
    uint32_t* KsL = KsH + 224*AGSTR;
    uint32_t* VtH = KsL + 224*AGSTR;
    uint32_t* VtL = VtH + 32*VSTP;
    float*    rb  = reinterpret_cast<float*>(VtL + 32*VSTP);

    int tile = blockIdx.x, head = blockIdx.y, bd = blockIdx.z;
    int h0 = (tile / 6) * 8;
    int w0 = (tile % 6) * 8;
    int kh0 = min(max(h0 - 3, 0), H_ - KW);
    int kw0 = min(max(w0 - 3, 0), W_ - KW);
    int tid = threadIdx.x;

    for (int e = tid; e < 196*8; e += 128) {
        int key = e >> 3, d4 = e & 7;
        int kr = key / 14, kc = key % 14;
        int gh = min(kh0 + kr, H_-1);
        int gw = min(kw0 + kc, W_-1);
        const float* base = qkv + ((long)(bd*H_ + gh)*W_ + gw)*384 + head*32 + d4*4 + 128;
        float4 k4 = *reinterpret_cast<const float4*>(base);
        uint32_t h0_, l0_, h1_, l1_;
        bf16_split2(k4.x, k4.y, h0_, l0_);
        bf16_split2(k4.z, k4.w, h1_, l1_);
        int o = key*AGSTR + d4*2;
        KsH[o] = h0_; KsH[o+1] = h1_;
        KsL[o] = l0_; KsL[o+1] = l1_;
    }
    for (int e = tid; e < 98*8; e += 128) {
        int kp = e >> 3, d4 = e & 7;
        int keyA = 2*kp, keyB = 2*kp + 1;
        int ghA = min(kh0 + keyA/14, H_-1), gwA = min(kw0 + keyA%14, W_-1);
        int ghB = min(kh0 + keyB/14, H_-1), gwB = min(kw0 + keyB%14, W_-1);
        float4 va = *reinterpret_cast<const float4*>(
            qkv + ((long)(bd*H_ + ghA)*W_ + gwA)*384 + head*32 + d4*4 + 256);
        float4 vb = *reinterpret_cast<const float4*>(
            qkv + ((long)(bd*H_ + ghB)*W_ + gwB)*384 + head*32 + d4*4 + 256);
        uint32_t h_, l_;
        bf16_split2(va.x, vb.x, h_, l_); VtH[(d4*4+0)*VSTP + kp] = h_; VtL[(d4*4+0)*VSTP + kp] = l_;
        bf16_split2(va.y, vb.y, h_, l_); VtH[(d4*4+1)*VSTP + kp] = h_; VtL[(d4*4+1)*VSTP + kp] = l_;
        bf16_split2(va.z, vb.z, h_, l_); VtH[(d4*4+2)*VSTP + kp] = h_; VtL[(d4*4+2)*VSTP + kp] = l_;
        bf16_split2(va.w, vb.w, h_, l_); VtH[(d4*4+3)*VSTP + kp] = h_; VtL[(d4*4+3)*VSTP + kp] = l_;
    }
    for (int e = tid; e < 32*14; e += 128) {
        int dm = e / 14, kp = 98 + (e % 14);
        VtH[dm*VSTP + kp] = 0; VtL[dm*VSTP + kp] = 0;
    }
    for (int i = tid; i < 169; i += 128) rb[i] = rpb[head*169 + i];
    __syncthreads();

    int warp = tid >> 5, lane = tid & 31;
    int gid = lane >> 2, tig = lane & 3;

    int hq0 = h0 + 2*warp;
    int hq1 = hq0 + 1;
    int wq  = w0 + gid;
    long tok0 = (long)(bd*H_ + hq0)*W_ + wq;
    long tok1 = tok0 + W_;
    int rel0 = min(max(hq0-3, 0), H_-KW) - kh0;
    int rel1 = min(max(hq1-3, 0), H_-KW) - kh0;
    int ws   = min(max(wq-3, 0), W_-KW) - kw0;
    int n_base = ((min(rel0, rel1) * 14) >> 3) * 8;

    const float scale = 0.17677669529663687f;
    uint32_t qh[2][4], ql[2][4];
    #pragma unroll
    for (int ks = 0; ks < 2; ks++) {
        const float* q0p = qkv + tok0*384 + head*32 + ks*16 + 2*tig;
        const float* q1p = qkv + tok1*384 + head*32 + ks*16 + 2*tig;
        float2 a = *reinterpret_cast<const float2*>(q0p);
        float2 b = *reinterpret_cast<const float2*>(q1p);
        float2 c = *reinterpret_cast<const float2*>(q0p + 8);
        float2 d = *reinterpret_cast<const float2*>(q1p + 8);
        bf16_split2(a.x*scale, a.y*scale, qh[ks][0], ql[ks][0]);
        bf16_split2(b.x*scale, b.y*scale, qh[ks][1], ql[ks][1]);
        bf16_split2(c.x*scale, c.y*scale, qh[ks][2], ql[ks][2]);
        bf16_split2(d.x*scale, d.y*scale, qh[ks][3], ql[ks][3]);
    }

    float acc[15][4];
    #pragma unroll
    for (int nt = 0; nt < 15; nt++)
        #pragma unroll
        for (int i = 0; i < 4; i++) acc[nt][i] = 0.f;

    #pragma unroll
    for (int nt = 0; nt < 15; nt++) {
        int key = n_base + nt*8 + gid;
        #pragma unroll
        for (int ks = 0; ks < 2; ks++) {
            int o = key*AGSTR + ks*8 + tig;
            uint32_t bh[2] = { KsH[o], KsH[o + 4] };
            uint32_t bl[2] = { KsL[o], KsL[o + 4] };
            mma_bf16(acc[nt], qh[ks], bh);
            mma_bf16(acc[nt], ql[ks], bh);
            mma_bf16(acc[nt], qh[ks], bl);
        }
    }

    int bh0c = kh0 - hq0 + 6;
    int bh1c = kh0 - hq1 + 6;
    int bwc  = kw0 - wq + 6;
    float mx0 = -1e30f, mx1 = -1e30f;
    #pragma unroll
    for (int nt = 0; nt < 15; nt++) {
        #pragma unroll
        for (int cc = 0; cc < 2; cc++) {
            int n = n_base + nt*8 + 2*tig + cc;
            int kr = n / 14;
            int kc = n - kr*14;
            bool vw = (unsigned)(kc - ws) <= 6u;
            bool v0 = vw && (unsigned)(kr - rel0) <= 6u;
            bool v1 = vw && (unsigned)(kr - rel1) <= 6u;
            float s0 = v0 ? acc[nt][cc]   + rb[(bh0c+kr)*13 + bwc + kc] : -1e30f;
            float s1 = v1 ? acc[nt][2+cc] + rb[(bh1c+kr)*13 + bwc + kc] : -1e30f;
            acc[nt][cc]   = s0;
            acc[nt][2+cc] = s1;
            mx0 = fmaxf(mx0, s0);
            mx1 = fmaxf(mx1, s1);
        }
    }
    mx0 = fmaxf(mx0, __shfl_xor_sync(0xffffffffu, mx0, 1));
    mx0 = fmaxf(mx0, __shfl_xor_sync(0xffffffffu, mx0, 2));
    mx1 = fmaxf(mx1, __shfl_xor_sync(0xffffffffu, mx1, 1));
    mx1 = fmaxf(mx1, __shfl_xor_sync(0xffffffffu, mx1, 2));

    float sum0 = 0.f, sum1 = 0.f;
    #pragma unroll
    for (int nt = 0; nt < 15; nt++) {
        #pragma unroll
        for (int cc = 0; cc < 2; cc++) {
            float e0 = __expf(acc[nt][cc]   - mx0);
            float e1 = __expf(acc[nt][2+cc] - mx1);
            acc[nt][cc]   = e0;
            acc[nt][2+cc] = e1;
            sum0 += e0;
            sum1 += e1;
        }
    }
    sum0 += __shfl_xor_sync(0xffffffffu, sum0, 1);
    sum0 += __shfl_xor_sync(0xffffffffu, sum0, 2);
    sum1 += __shfl_xor_sync(0xffffffffu, sum1, 1);
    sum1 += __shfl_xor_sync(0xffffffffu, sum1, 2);
    float inv0 = 1.0f / sum0;
    float inv1 = 1.0f / sum1;

    __syncthreads();
    uint32_t* PwH = smu + warp * (16 * PSTP * 2);
    uint32_t* PwL = PwH + 16 * PSTP;
    #pragma unroll
    for (int nt = 0; nt < 15; nt++) {
        uint32_t h_, l_;
        bf16_split2(acc[nt][0], acc[nt][1], h_, l_);
        PwH[gid*PSTP + nt*4 + tig] = h_;
        PwL[gid*PSTP + nt*4 + tig] = l_;
        bf16_split2(acc[nt][2], acc[nt][3], h_, l_);
        PwH[(gid+8)*PSTP + nt*4 + tig] = h_;
        PwL[(gid+8)*PSTP + nt*4 + tig] = l_;
    }
    PwH[gid*PSTP + 60 + tig] = 0;     PwL[gid*PSTP + 60 + tig] = 0;
    PwH[(gid+8)*PSTP + 60 + tig] = 0; PwL[(gid+8)*PSTP + 60 + tig] = 0;
    __syncwarp();

    int nb2 = n_base >> 1;
    float o[4][4];
    #pragma unroll
    for (int nt = 0; nt < 4; nt++)
        #pragma unroll
        for (int i = 0; i < 4; i++) o[nt][i] = 0.f;

    #pragma unroll
    for (int kt = 0; kt < 8; kt++) {
        int p0 = gid*PSTP + kt*8 + tig;
        int p1 = (gid+8)*PSTP + kt*8 + tig;
        uint32_t ph[4] = { PwH[p0], PwH[p1], PwH[p0 + 4], PwH[p1 + 4] };
        uint32_t pl[4] = { PwL[p0], PwL[p1], PwL[p0 + 4], PwL[p1 + 4] };
        #pragma unroll
        for (int nt = 0; nt < 4; nt++) {
            int vr = (nt*8 + gid)*VSTP + nb2 + kt*8 + tig;
            uint32_t vh[2] = { VtH[vr], VtH[vr + 4] };
            uint32_t vl[2] = { VtL[vr], VtL[vr + 4] };
            mma_bf16(o[nt], ph, vh);
            mma_bf16(o[nt], pl, vh);
            mma_bf16(o[nt], ph, vl);
        }
    }

    // ---- epilogue: write pre-split, pre-permuted pairs
    #pragma unroll
    for (int nt = 0; nt < 4; nt++) {
        int d = head*32 + nt*8 + 2*tig;
        int p = d >> 1;
        int idx = (p & ~7) | PERMJ(p & 7);
        uint32_t h_, l_;
        bf16_split2(o[nt][0]*inv0, o[nt][1]*inv0, h_, l_);
        outH[tok0*64 + idx] = h_;
        outL[tok0*64 + idx] = l_;
        bf16_split2(o[nt][2]*inv1, o[nt][3]*inv1, h_, l_);
        outH[tok1*64 + idx] = h_;
        outL[tok1*64 + idx] = l_;
    }
}

// ---------------------------------------------------------------------------
// Transpose in: x (B,C,D,H,W) -> t (N=B*D*H*W, C)
// ---------------------------------------------------------------------------
__global__ void t_in_kernel(const float* __restrict__ x, float* __restrict__ t) {
    __shared__ float sm[16][17];
    int bz = blockIdx.z;
    int b = bz / (D_*H_);
    int rem = bz % (D_*H_);
    int d = rem / H_;
    int h = rem % H_;
    int w = blockIdx.x*16 + threadIdx.x;
    int c = blockIdx.y*16 + threadIdx.y;
    sm[threadIdx.y][threadIdx.x] =
        x[(( (long)b*C_ + c)*D_ + d)*(H_*W_) + h*W_ + w];
    __syncthreads();
    int c2 = blockIdx.y*16 + threadIdx.x;
    int w2 = blockIdx.x*16 + threadIdx.y;
    t[((((b*D_ + d)*H_ + h)*W_ + w2) * (long)C_) + c2] = sm[threadIdx.x][threadIdx.y];
}

// ---------------------------------------------------------------------------
// Launch
// ---------------------------------------------------------------------------
extern "C" void kernel_launch(void* const* d_in, const int* in_sizes, int n_in,
                              void* d_out, int out_size) {
    const float* x      = (const float*)d_in[0];
    const float* n1w    = (const float*)d_in[1];
    const float* n1b    = (const float*)d_in[2];
    const float* qkv_w  = (const float*)d_in[3];
    const float* qkv_b  = (const float*)d_in[4];
    const float* rpb    = (const float*)d_in[5];
    const float* proj_w = (const float*)d_in[6];
    const float* proj_b = (const float*)d_in[7];
    const float* n2w    = (const float*)d_in[8];
    const float* n2b    = (const float*)d_in[9];
    const float* fc1_w  = (const float*)d_in[10];
    const float* fc1_b  = (const float*)d_in[11];
    const float* fc2_w  = (const float*)d_in[12];
    const float* fc2_b  = (const float*)d_in[13];
    float* out = (float*)d_out;

    float *t_p, *qkv_p;
    uint32_t *wh_p, *wl_p, *ah_p, *al_p, *bh_p, *bl_p;
    cudaGetSymbolAddress((void**)&t_p,   g_t);
    cudaGetSymbolAddress((void**)&qkv_p, g_qkv);
    cudaGetSymbolAddress((void**)&wh_p,  g_wh);
    cudaGetSymbolAddress((void**)&wl_p,  g_wl);
    cudaGetSymbolAddress((void**)&ah_p,  g_ah);
    cudaGetSymbolAddress((void**)&al_p,  g_al);
    cudaGetSymbolAddress((void**)&bh_p,  g_bh);
    cudaGetSymbolAddress((void**)&bl_p,  g_bl);

    int attn_smem = ATTN_SMEM_U32 * (int)sizeof(uint32_t);
    cudaFuncSetAttribute(attn_mma_kernel, cudaFuncAttributeMaxDynamicSharedMemorySize, attn_smem);
    cudaFuncSetAttribute(gemm_cp_kernel<0>, cudaFuncAttributeMaxDynamicSharedMemorySize, GEMM_SMEM);
    cudaFuncSetAttribute(gemm_cp_kernel<2>, cudaFuncAttributeMaxDynamicSharedMemorySize, GEMM_SMEM);
    cudaFuncSetAttribute(gemm_cp_kernel<3>, cudaFuncAttributeMaxDynamicSharedMemorySize, GEMM_SMEM);
    cudaFuncSetAttribute(gemm_cp_kernel<4>, cudaFuncAttributeMaxDynamicSharedMemorySize, GEMM_SMEM);

    dim3 tb(16, 16);
    dim3 tg(W_/16, C_/16, B_*D_*H_);

    // 0. pre-split weights
    wsplit_kernel<<<256, 256>>>(qkv_w, proj_w, fc1_w, fc2_w);
    // 1. transpose in
    t_in_kernel<<<tg, tb>>>(x, t_p);
    // 2. LN1 + split
    ln_prep_kernel<<<NTOK/8, 256>>>(t_p, n1w, n1b, ah_p, al_p);
    // 3. qkv = LN1(t) @ qkv_w^T + b   (M=384, K=128)
    gemm_cp_kernel<0><<<dim3(6, NTOK/128), 256, GEMM_SMEM>>>(
        ah_p, al_p, wh_p, wl_p, qkv_b, qkv_p, nullptr, nullptr, nullptr, 384, 128);
    // 4. neighborhood attention -> pre-split out
    attn_mma_kernel<<<dim3(36, NHEAD, B_*D_), 128, attn_smem>>>(qkv_p, rpb, ah_p, al_p);
    // 5. t += attn @ proj_w^T + b     (M=128, K=128)
    gemm_cp_kernel<2><<<dim3(2, NTOK/128), 256, GEMM_SMEM>>>(
        ah_p, al_p, wh_p + 24576, wl_p + 24576, proj_b, t_p, nullptr, nullptr, nullptr, 128, 128);
    // 6. LN2 + split
    ln_prep_kernel<<<NTOK/8, 256>>>(t_p, n2w, n2b, ah_p, al_p);
    // 7. h1 = gelu(LN2(t) @ fc1_w^T + b) -> pre-split  (M=256, K=128)
    gemm_cp_kernel<4><<<dim3(4, NTOK/128), 256, GEMM_SMEM>>>(
        ah_p, al_p, wh_p + 32768, wl_p + 32768, fc1_b, nullptr, bh_p, bl_p, nullptr, 256, 128);
    // 8. out = transpose(t + h1 @ fc2_w^T + b)   (M=128, K=256)
    gemm_cp_kernel<3><<<dim3(2, NTOK/128), 256, GEMM_SMEM>>>(
        bh_p, bl_p, wh_p + 49152, wl_p + 49152, fc2_b, out, nullptr, nullptr, t_p, 128, 256);
}

// round 11
// speedup vs baseline: 2.5229x; 1.0017x over previous
#include <cuda_runtime.h>
#include <cuda_bf16.h>
#include <math.h>
#include <stdint.h>

// Problem constants
#define B_  2
#define C_  128
#define D_  4
#define H_  48
#define W_  48
#define NTOK (B_*D_*H_*W_)   // 18432
#define NHEAD 4
#define HD 32
#define KW 7

// Scratch (device globals — no allocation allowed)
__device__ float    g_t    [NTOK*128];
__device__ uint32_t g_qkvh [NTOK*192];   // pre-split qkv: Q[0:64) K[64:128) V[128:192) pairs
__device__ uint32_t g_qkvl [NTOK*192];
__device__ uint32_t g_ah   [NTOK*64];    // pre-split activations (attn out / ln out)
__device__ uint32_t g_al   [NTOK*64];
__device__ uint32_t g_bh   [NTOK*128];   // pre-split h1
__device__ uint32_t g_bl   [NTOK*128];
// Pre-split weights (bf16x2 hi/lo packed k-pairs, PERMUTED within 8-pair groups)
__device__ uint32_t g_wh[65536];
__device__ uint32_t g_wl[65536];

#define PERMJ(j) ((j) < 4 ? 2*(j) : 2*(j)-7)

// ===========================================================================
// Helpers
// ===========================================================================
__device__ __forceinline__ void mma_bf16(float* c, const uint32_t* a, const uint32_t* b) {
    asm volatile(
        "mma.sync.aligned.m16n8k16.row.col.f32.bf16.bf16.f32 "
        "{%0,%1,%2,%3}, {%4,%5,%6,%7}, {%8,%9}, {%0,%1,%2,%3};"
        : "+f"(c[0]), "+f"(c[1]), "+f"(c[2]), "+f"(c[3])
        : "r"(a[0]), "r"(a[1]), "r"(a[2]), "r"(a[3]), "r"(b[0]), "r"(b[1]));
}

__device__ __forceinline__ void bf16_split2(float x0, float x1, uint32_t& hi, uint32_t& lo) {
    __nv_bfloat162 h = __floats2bfloat162_rn(x0, x1);
    float h0 = __bfloat162float(h.x);
    float h1 = __bfloat162float(h.y);
    __nv_bfloat162 l = __floats2bfloat162_rn(x0 - h0, x1 - h1);
    hi = *reinterpret_cast<uint32_t*>(&h);
    lo = *reinterpret_cast<uint32_t*>(&l);
}

#define CP_ASYNC16(dst_u32, src_ptr) \
    asm volatile("cp.async.cg.shared.global [%0], [%1], 16;" \
        :: "r"(dst_u32), "l"(__cvta_generic_to_global(src_ptr)) : "memory")
#define CP_COMMIT() asm volatile("cp.async.commit_group;" ::: "memory")
#define CP_WAIT1()  asm volatile("cp.async.wait_group 1;" ::: "memory")
#define CP_WAIT0()  asm volatile("cp.async.wait_group 0;" ::: "memory")

// ===========================================================================
// Weight pre-split + permute
// ===========================================================================
__global__ void wsplit_kernel(const float* __restrict__ qkv_w,
                              const float* __restrict__ proj_w,
                              const float* __restrict__ fc1_w,
                              const float* __restrict__ fc2_w) {
    int i = blockIdx.x * 256 + threadIdx.x;
    const float* src;
    int li;
    if (i < 24576)      { src = qkv_w;  li = i; }
    else if (i < 32768) { src = proj_w; li = i - 24576; }
    else if (i < 49152) { src = fc1_w;  li = i - 32768; }
    else                { src = fc2_w;  li = i - 49152; }
    float2 v = *reinterpret_cast<const float2*>(src + 2 * li);
    uint32_t h, l;
    bf16_split2(v.x, v.y, h, l);
    int dst = (i & ~7) | PERMJ(i & 7);
    g_wh[dst] = h;
    g_wl[dst] = l;
}

// ===========================================================================
// Fused LN + split + permute: warp per token -> ah/al
// ===========================================================================
__global__ void ln_prep_kernel(const float* __restrict__ in,
                               const float* __restrict__ w,
                               const float* __restrict__ b,
                               uint32_t* __restrict__ ah,
                               uint32_t* __restrict__ al) {
    int n = blockIdx.x * 8 + (threadIdx.x >> 5);
    int lane = threadIdx.x & 31;
    float4 v = *reinterpret_cast<const float4*>(in + (long)n*128 + lane*4);
    float s  = v.x + v.y + v.z + v.w;
    float s2 = v.x*v.x + v.y*v.y + v.z*v.z + v.w*v.w;
    #pragma unroll
    for (int o = 16; o > 0; o >>= 1) {
        s  += __shfl_xor_sync(0xffffffffu, s,  o);
        s2 += __shfl_xor_sync(0xffffffffu, s2, o);
    }
    float m    = s  * (1.0f/128.0f);
    float rstd = rsqrtf(s2 * (1.0f/128.0f) - m*m + 1e-5f);
    float4 wv = *reinterpret_cast<const float4*>(w + lane*4);
    float4 bv = *reinterpret_cast<const float4*>(b + lane*4);
    float y0 = (v.x - m) * rstd * wv.x + bv.x;
    float y1 = (v.y - m) * rstd * wv.y + bv.y;
    float y2 = (v.z - m) * rstd * wv.z + bv.z;
    float y3 = (v.w - m) * rstd * wv.w + bv.w;
    uint32_t h0, l0, h1, l1;
    bf16_split2(y0, y1, h0, l0);
    bf16_split2(y2, y3, h1, l1);
    int p0 = 2*lane, p1 = 2*lane + 1;
    int i0 = (p0 & ~7) | PERMJ(p0 & 7);
    int i1 = (p1 & ~7) | PERMJ(p1 & 7);
    long base = (long)n * 64;
    ah[base + i0] = h0; ah[base + i1] = h1;
    al[base + i0] = l0; al[base + i1] = l1;
}

// ===========================================================================
// Tensor-core GEMM: cp.async 3-stage ring, pre-split A and B.
// EPI: 0 bias fp32; 2 bias+residual; 3 bias+residual+transposed store;
//      4 bias+GELU+split; 5 qkv split epilogue (Q scaled+perm, K perm, V logical)
// ===========================================================================
#define GSTR 24
#define STAGE_U32 9216
#define GEMM_SMEM (3 * STAGE_U32 * 4)

template<int EPI>
__global__ void __launch_bounds__(256, 2)
gemm_cp_kernel(const uint32_t* __restrict__ AHg,
               const uint32_t* __restrict__ ALg,
               const uint32_t* __restrict__ WH,
               const uint32_t* __restrict__ WL,
               const float* __restrict__ bias,
               float* __restrict__ out,
               uint32_t* __restrict__ outH,
               uint32_t* __restrict__ outL,
               const float* __restrict__ resid,
               int M, int K) {
    extern __shared__ uint32_t smg[];
    uint32_t smb = (uint32_t)__cvta_generic_to_shared(smg);

    int tid = threadIdx.x;
    int wid = tid >> 5, lane = tid & 31;
    int warp_m = wid & 3;
    int warp_n = wid >> 2;
    int gid = lane >> 2;
    int tig = lane & 3;

    int n0 = blockIdx.y * 128;
    int m0 = blockIdx.x * 64;
    int Kp = K >> 1;
    int nch = K >> 5;

    float acc[2][4][4];
    #pragma unroll
    for (int mt = 0; mt < 2; mt++)
        #pragma unroll
        for (int nt = 0; nt < 4; nt++)
            #pragma unroll
            for (int i = 0; i < 4; i++) acc[mt][nt][i] = 0.f;

    int a_row0 = tid >> 2,         a_q0 = tid & 3;
    int a_row1 = (tid + 256) >> 2, a_q1 = (tid + 256) & 3;
    int b_row = tid >> 2, b_q = tid & 3;

    auto issue = [&](int ch, int s) {
        uint32_t base = smb + (uint32_t)(s * STAGE_U32) * 4u;
        long ka = (long)ch * 16;
        CP_ASYNC16(base + (a_row0*GSTR + a_q0*4)*4,        AHg + (long)(n0 + a_row0)*Kp + ka + a_q0*4);
        CP_ASYNC16(base + (a_row1*GSTR + a_q1*4)*4,        AHg + (long)(n0 + a_row1)*Kp + ka + a_q1*4);
        CP_ASYNC16(base + (3072 + a_row0*GSTR + a_q0*4)*4, ALg + (long)(n0 + a_row0)*Kp + ka + a_q0*4);
        CP_ASYNC16(base + (3072 + a_row1*GSTR + a_q1*4)*4, ALg + (long)(n0 + a_row1)*Kp + ka + a_q1*4);
        CP_ASYNC16(base + (6144 + b_row*GSTR + b_q*4)*4,   WH + (long)(m0 + b_row)*Kp + ka + b_q*4);
        CP_ASYNC16(base + (7680 + b_row*GSTR + b_q*4)*4,   WL + (long)(m0 + b_row)*Kp + ka + b_q*4);
        CP_COMMIT();
    };

    issue(0, 0);
    issue(1, 1);

    int cs = 0;
    for (int ch = 0; ch < nch; ch++) {
        if (ch + 2 < nch) { CP_WAIT1(); } else { CP_WAIT0(); }
        __syncthreads();

        uint32_t* AH = smg + cs * STAGE_U32;
        uint32_t* AL = AH + 3072;
        uint32_t* BH = AH + 6144;
        uint32_t* BL = AH + 7680;
        #pragma unroll
        for (int ks = 0; ks < 2; ks++) {
            int jc = ks * 8 + 2 * tig;
            uint32_t ahi[2][4], alo[2][4];
            #pragma unroll
            for (int mt = 0; mt < 2; mt++) {
                int r = warp_m * 32 + mt * 16 + gid;
                uint2 h0 = *reinterpret_cast<uint2*>(&AH[r * GSTR + jc]);
                uint2 h1 = *reinterpret_cast<uint2*>(&AH[(r + 8) * GSTR + jc]);
                uint2 l0 = *reinterpret_cast<uint2*>(&AL[r * GSTR + jc]);
                uint2 l1 = *reinterpret_cast<uint2*>(&AL[(r + 8) * GSTR + jc]);
                ahi[mt][0] = h0.x; ahi[mt][1] = h1.x; ahi[mt][2] = h0.y; ahi[mt][3] = h1.y;
                alo[mt][0] = l0.x; alo[mt][1] = l1.x; alo[mt][2] = l0.y; alo[mt][3] = l1.y;
            }
            uint32_t bhi[4][2], blo[4][2];
            #pragma unroll
            for (int nt = 0; nt < 4; nt++) {
                int br = warp_n * 32 + nt * 8 + gid;
                uint2 bh = *reinterpret_cast<uint2*>(&BH[br * GSTR + jc]);
                uint2 bl = *reinterpret_cast<uint2*>(&BL[br * GSTR + jc]);
                bhi[nt][0] = bh.x; bhi[nt][1] = bh.y;
                blo[nt][0] = bl.x; blo[nt][1] = bl.y;
            }
            #pragma unroll
            for (int mt = 0; mt < 2; mt++)
                #pragma unroll
                for (int nt = 0; nt < 4; nt++) {
                    mma_bf16(acc[mt][nt], ahi[mt], bhi[nt]);
                    mma_bf16(acc[mt][nt], alo[mt], bhi[nt]);
                    mma_bf16(acc[mt][nt], ahi[mt], blo[nt]);
                }
        }

        if (ch + 2 < nch) {
            int s2 = cs + 2; if (s2 >= 3) s2 -= 3;
            issue(ch + 2, s2);
        }
        cs = (cs + 1 == 3) ? 0 : cs + 1;
    }

    // ---- epilogue
    int row_base = n0 + warp_m * 32;
    int col_base = m0 + warp_n * 32;
    #pragma unroll
    for (int nt = 0; nt < 4; nt++) {
        int col = col_base + nt * 8 + 2 * tig;
        float b0 = bias[col], b1 = bias[col + 1];
        #pragma unroll
        for (int mt = 0; mt < 2; mt++) {
            #pragma unroll
            for (int half = 0; half < 2; half++) {
                int r = row_base + mt * 16 + gid + half * 8;
                float v0 = acc[mt][nt][half * 2 + 0] + b0;
                float v1 = acc[mt][nt][half * 2 + 1] + b1;
                if (EPI == 5) {
                    // qkv epilogue: Q scaled + permuted, K permuted, V logical
                    uint32_t h_, l_;
                    int idx;
                    if (col < 128) {
                        const float sc = 0.17677669529663687f;
                        bf16_split2(v0 * sc, v1 * sc, h_, l_);
                        int p = col >> 1;
                        idx = (p & ~7) | PERMJ(p & 7);
                    } else if (col < 256) {
                        bf16_split2(v0, v1, h_, l_);
                        int p = (col - 128) >> 1;
                        idx = 64 + ((p & ~7) | PERMJ(p & 7));
                    } else {
                        bf16_split2(v0, v1, h_, l_);
                        idx = 128 + ((col - 256) >> 1);
                    }
                    outH[(long)r * 192 + idx] = h_;
                    outL[(long)r * 192 + idx] = l_;
                } else if (EPI == 4) {
                    v0 = 0.5f * v0 * (1.0f + erff(v0 * 0.70710678118654752f));
                    v1 = 0.5f * v1 * (1.0f + erff(v1 * 0.70710678118654752f));
                    uint32_t h_, l_;
                    bf16_split2(v0, v1, h_, l_);
                    int p = col >> 1;
                    int idx = (p & ~7) | PERMJ(p & 7);
                    outH[(long)r * 128 + idx] = h_;
                    outL[(long)r * 128 + idx] = l_;
                } else if (EPI == 3) {
                    float2 rv = *reinterpret_cast<const float2*>(resid + (long)r * 128 + col);
                    v0 += rv.x; v1 += rv.y;
                    long o = (long)r + (r >= 9216 ? 1170432L : 0L) + (long)col * 9216;
                    out[o]        = v0;
                    out[o + 9216] = v1;
                } else {
                    float2* dst = reinterpret_cast<float2*>(out + (long)r * M + col);
                    if (EPI == 2) {
                        float2 old = *dst;
                        v0 += old.x; v1 += old.y;
                    }
                    float2 st; st.x = v0; st.y = v1;
                    *dst = st;
                }
            }
        }
    }
}

// ===========================================================================
// Tensor-core neighborhood attention: all operands pre-split by qkv GEMM.
// Staging = pure copies (K), PRMT repack (V^T), direct fragment loads (Q).
// ===========================================================================
#define AGSTR 24
#define VSTP  116
#define PSTP  68
#define ATTN_SMEM_U32 (2*224*AGSTR + 2*32*VSTP + 170)   // 18346

__global__ void __launch_bounds__(128, 3)
attn_mma_kernel(const uint32_t* __restrict__ inH,
                const uint32_t* __restrict__ inL,
                const float* __restrict__ rpb,
                uint32_t* __restrict__ outH,
                uint32_t* __restrict__ outL) {
    extern __shared__ uint32_t smu[];
    uint32_t* KsH = smu;                    // [224][24]
    uint32_t* KsL = KsH + 224*AGSTR;
    uint32_t* VtH = KsL + 224*AGSTR;        // [32][116]
    uint32_t* VtL = VtH + 32*VSTP;
    float*    rb  = reinterpret_cast<float*>(VtL + 32*VSTP);

    int tile = blockIdx.x, head = blockIdx.y, bd = blockIdx.z;
    int h0 = (tile / 6) * 8;
    int w0 = (tile % 6) * 8;
    int kh0 = min(max(h0 - 3, 0), H_ - KW);
    int kw0 = min(max(w0 - 3, 0), W_ - KW);
    int tid = threadIdx.x;

    // ---- K: pure uint4 copies of pre-split rows (permuted pair layout)
    for (int e = tid; e < 196*4; e += 128) {
        int key = e >> 2, q = e & 3;
        int kr = key / 14, kc = key % 14;
        int gh = min(kh0 + kr, H_-1);
        int gw = min(kw0 + kc, W_-1);
        long tok = ((long)(bd*H_ + gh))*W_ + gw;
        long src = tok*192 + 64 + head*16 + q*4;
        *reinterpret_cast<uint4*>(&KsH[key*AGSTR + q*4]) = *reinterpret_cast<const uint4*>(inH + src);
        *reinterpret_cast<uint4*>(&KsL[key*AGSTR + q*4]) = *reinterpret_cast<const uint4*>(inL + src);
    }
    // zero-pad keys 196..223
    for (int e = tid; e < 28*6; e += 128) {
        int key = 196 + e / 6, q = e % 6;
        uint4 z = make_uint4(0,0,0,0);
        *reinterpret_cast<uint4*>(&KsH[key*AGSTR + q*4]) = z;
        *reinterpret_cast<uint4*>(&KsL[key*AGSTR + q*4]) = z;
    }
    // ---- V^T: PRMT repack of pre-split dim-pairs into key-pairs
    for (int e = tid; e < 98*4; e += 128) {
        int kp = e >> 2, pq = e & 3;
        int keyA = 2*kp;
        int kr = keyA / 14, kc = keyA % 14;   // pair never crosses a window row (14 even)
        int gh = min(kh0 + kr, H_-1);
        int gwA = min(kw0 + kc, W_-1);
        int gwB = min(kw0 + kc + 1, W_-1);
        long rowb = ((long)(bd*H_ + gh))*W_;
        long sA = (rowb + gwA)*192 + 128 + head*16 + pq*4;
        long sB = (rowb + gwB)*192 + 128 + head*16 + pq*4;
        uint4 HA = *reinterpret_cast<const uint4*>(inH + sA);
        uint4 HB = *reinterpret_cast<const uint4*>(inH + sB);
        uint4 LA = *reinterpret_cast<const uint4*>(inL + sA);
        uint4 LB = *reinterpret_cast<const uint4*>(inL + sB);
        uint32_t ha[4] = {HA.x, HA.y, HA.z, HA.w};
        uint32_t hb[4] = {HB.x, HB.y, HB.z, HB.w};
        uint32_t la[4] = {LA.x, LA.y, LA.z, LA.w};
        uint32_t lb[4] = {LB.x, LB.y, LB.z, LB.w};
        #pragma unroll
        for (int j = 0; j < 4; j++) {
            int pp = pq*4 + j;           // logical dim pair
            VtH[(2*pp+0)*VSTP + kp] = __byte_perm(ha[j], hb[j], 0x5410);
            VtH[(2*pp+1)*VSTP + kp] = __byte_perm(ha[j], hb[j], 0x7632);
            VtL[(2*pp+0)*VSTP + kp] = __byte_perm(la[j], lb[j], 0x5410);
            VtL[(2*pp+1)*VSTP + kp] = __byte_perm(la[j], lb[j], 0x7632);
        }
    }
    // zero V pad pairs 98..111
    for (int e = tid; e < 32*14; e += 128) {
        int dm = e / 14, kp = 98 + (e % 14);
        VtH[dm*VSTP + kp] = 0; VtL[dm*VSTP + kp] = 0;
    }
    for (int i = tid; i < 169; i += 128) rb[i] = rpb[head*169 + i];
    __syncthreads();

    int warp = tid >> 5, lane = tid & 31;
    int gid = lane >> 2, tig = lane & 3;

    int hq0 = h0 + 2*warp;
    int hq1 = hq0 + 1;
    int wq  = w0 + gid;
    long tok0 = (long)(bd*H_ + hq0)*W_ + wq;
    long tok1 = tok0 + W_;
    int rel0 = min(max(hq0-3, 0), H_-KW) - kh0;
    int rel1 = min(max(hq1-3, 0), H_-KW) - kh0;
    int ws   = min(max(wq-3, 0), W_-KW) - kw0;
    int n_base = ((min(rel0, rel1) * 14) >> 3) * 8;

    // ---- Q fragments: direct uint2 loads (pre-scaled, pre-split, permuted)
    uint32_t qh[2][4], ql[2][4];
    #pragma unroll
    for (int ks = 0; ks < 2; ks++) {
        long o0 = tok0*192 + head*16 + ks*8 + 2*tig;
        long o1 = tok1*192 + head*16 + ks*8 + 2*tig;
        uint2 h0v = *reinterpret_cast<const uint2*>(inH + o0);
        uint2 h1v = *reinterpret_cast<const uint2*>(inH + o1);
        uint2 l0v = *reinterpret_cast<const uint2*>(inL + o0);
        uint2 l1v = *reinterpret_cast<const uint2*>(inL + o1);
        qh[ks][0] = h0v.x; qh[ks][1] = h1v.x; qh[ks][2] = h0v.y; qh[ks][3] = h1v.y;
        ql[ks][0] = l0v.x; ql[ks][1] = l1v.x; ql[ks][2] = l0v.y; ql[ks][3] = l1v.y;
    }

    // ---- Scores: 15 n-tiles x 2 k16-tiles x 3 terms
    float acc[15][4];
    #pragma unroll
    for (int nt = 0; nt < 15; nt++)
        #pragma unroll
        for (int i = 0; i < 4; i++) acc[nt][i] = 0.f;

    #pragma unroll
    for (int nt = 0; nt < 15; nt++) {
        int key = n_base + nt*8 + gid;
        #pragma unroll
        for (int ks = 0; ks < 2; ks++) {
            int o = key*AGSTR + ks*8 + 2*tig;
            uint2 bhv = *reinterpret_cast<uint2*>(&KsH[o]);
            uint2 blv = *reinterpret_cast<uint2*>(&KsL[o]);
            uint32_t bh[2] = { bhv.x, bhv.y };
            uint32_t bl[2] = { blv.x, blv.y };
            mma_bf16(acc[nt], qh[ks], bh);
            mma_bf16(acc[nt], ql[ks], bh);
            mma_bf16(acc[nt], qh[ks], bl);
        }
    }

    // ---- Bias + mask + softmax
    int bh0c = kh0 - hq0 + 6;
    int bh1c = kh0 - hq1 + 6;
    int bwc  = kw0 - wq + 6;
    float mx0 = -1e30f, mx1 = -1e30f;
    #pragma unroll
    for (int nt = 0; nt < 15; nt++) {
        #pragma unroll
        for (int cc = 0; cc < 2; cc++) {
            int n = n_base + nt*8 + 2*tig + cc;
            int kr = n / 14;
            int kc = n - kr*14;
            bool vw = (unsigned)(kc - ws) <= 6u;
            bool v0 = vw && (unsigned)(kr - rel0) <= 6u;
            bool v1 = vw && (unsigned)(kr - rel1) <= 6u;
            float s0 = v0 ? acc[nt][cc]   + rb[(bh0c+kr)*13 + bwc + kc] : -1e30f;
            float s1 = v1 ? acc[nt][2+cc] + rb[(bh1c+kr)*13 + bwc + kc] : -1e30f;
            acc[nt][cc]   = s0;
            acc[nt][2+cc] = s1;
            mx0 = fmaxf(mx0, s0);
            mx1 = fmaxf(mx1, s1);
        }
    }
    mx0 = fmaxf(mx0, __shfl_xor_sync(0xffffffffu, mx0, 1));
    mx0 = fmaxf(mx0, __shfl_xor_sync(0xffffffffu, mx0, 2));
    mx1 = fmaxf(mx1, __shfl_xor_sync(0xffffffffu, mx1, 1));
    mx1 = fmaxf(mx1, __shfl_xor_sync(0xffffffffu, mx1, 2));

    float sum0 = 0.f, sum1 = 0.f;
    #pragma unroll
    for (int nt = 0; nt < 15; nt++) {
        #pragma unroll
        for (int cc = 0; cc < 2; cc++) {
            float e0 = __expf(acc[nt][cc]   - mx0);
            float e1 = __expf(acc[nt][2+cc] - mx1);
            acc[nt][cc]   = e0;
            acc[nt][2+cc] = e1;
            sum0 += e0;
            sum1 += e1;
        }
    }
    sum0 += __shfl_xor_sync(0xffffffffu, sum0, 1);
    sum0 += __shfl_xor_sync(0xffffffffu, sum0, 2);
    sum1 += __shfl_xor_sync(0xffffffffu, sum1, 1);
    sum1 += __shfl_xor_sync(0xffffffffu, sum1, 2);
    float inv0 = 1.0f / sum0;
    float inv1 = 1.0f / sum1;

    // ---- P (split once) aliased over dead K region
    __syncthreads();
    uint32_t* PwH = smu + warp * (16 * PSTP * 2);
    uint32_t* PwL = PwH + 16 * PSTP;
    #pragma unroll
    for (int nt = 0; nt < 15; nt++) {
        uint32_t h_, l_;
        bf16_split2(acc[nt][0], acc[nt][1], h_, l_);
        PwH[gid*PSTP + nt*4 + tig] = h_;
        PwL[gid*PSTP + nt*4 + tig] = l_;
        bf16_split2(acc[nt][2], acc[nt][3], h_, l_);
        PwH[(gid+8)*PSTP + nt*4 + tig] = h_;
        PwL[(gid+8)*PSTP + nt*4 + tig] = l_;
    }
    PwH[gid*PSTP + 60 + tig] = 0;     PwL[gid*PSTP + 60 + tig] = 0;
    PwH[(gid+8)*PSTP + 60 + tig] = 0; PwL[(gid+8)*PSTP + 60 + tig] = 0;
    __syncwarp();

    int nb2 = n_base >> 1;
    float o[4][4];
    #pragma unroll
    for (int nt = 0; nt < 4; nt++)
        #pragma unroll
        for (int i = 0; i < 4; i++) o[nt][i] = 0.f;

    #pragma unroll
    for (int kt = 0; kt < 8; kt++) {
        int p0 = gid*PSTP + kt*8 + tig;
        int p1 = (gid+8)*PSTP + kt*8 + tig;
        uint32_t ph[4] = { PwH[p0], PwH[p1], PwH[p0 + 4], PwH[p1 + 4] };
        uint32_t pl[4] = { PwL[p0], PwL[p1], PwL[p0 + 4], PwL[p1 + 4] };
        #pragma unroll
        for (int nt = 0; nt < 4; nt++) {
            int vr = (nt*8 + gid)*VSTP + nb2 + kt*8 + tig;
            uint32_t vh[2] = { VtH[vr], VtH[vr + 4] };
            uint32_t vl[2] = { VtL[vr], VtL[vr + 4] };
            mma_bf16(o[nt], ph, vh);
            mma_bf16(o[nt], pl, vh);
            mma_bf16(o[nt], ph, vl);
        }
    }

    // ---- epilogue: write pre-split, pre-permuted pairs for proj GEMM
    #pragma unroll
    for (int nt = 0; nt < 4; nt++) {
        int d = head*32 + nt*8 + 2*tig;
        int p = d >> 1;
        int idx = (p & ~7) | PERMJ(p & 7);
        uint32_t h_, l_;
        bf16_split2(o[nt][0]*inv0, o[nt][1]*inv0, h_, l_);
        outH[tok0*64 + idx] = h_;
        outL[tok0*64 + idx] = l_;
        bf16_split2(o[nt][2]*inv1, o[nt][3]*inv1, h_, l_);
        outH[tok1*64 + idx] = h_;
        outL[tok1*64 + idx] = l_;
    }
}

// ---------------------------------------------------------------------------
// Transpose in: x (B,C,D,H,W) -> t (N=B*D*H*W, C)
// ---------------------------------------------------------------------------
__global__ void t_in_kernel(const float* __restrict__ x, float* __restrict__ t) {
    __shared__ float sm[16][17];
    int bz = blockIdx.z;
    int b = bz / (D_*H_);
    int rem = bz % (D_*H_);
    int d = rem / H_;
    int h = rem % H_;
    int w = blockIdx.x*16 + threadIdx.x;
    int c = blockIdx.y*16 + threadIdx.y;
    sm[threadIdx.y][threadIdx.x] =
        x[(( (long)b*C_ + c)*D_ + d)*(H_*W_) + h*W_ + w];
    __syncthreads();
    int c2 = blockIdx.y*16 + threadIdx.x;
    int w2 = blockIdx.x*16 + threadIdx.y;
    t[((((b*D_ + d)*H_ + h)*W_ + w2) * (long)C_) + c2] = sm[threadIdx.x][threadIdx.y];
}

// ---------------------------------------------------------------------------
// Launch
// ---------------------------------------------------------------------------
extern "C" void kernel_launch(void* const* d_in, const int* in_sizes, int n_in,
                              void* d_out, int out_size) {
    const float* x      = (const float*)d_in[0];
    const float* n1w    = (const float*)d_in[1];
    const float* n1b    = (const float*)d_in[2];
    const float* qkv_w  = (const float*)d_in[3];
    const float* qkv_b  = (const float*)d_in[4];
    const float* rpb    = (const float*)d_in[5];
    const float* proj_w = (const float*)d_in[6];
    const float* proj_b = (const float*)d_in[7];
    const float* n2w    = (const float*)d_in[8];
    const float* n2b    = (const float*)d_in[9];
    const float* fc1_w  = (const float*)d_in[10];
    const float* fc1_b  = (const float*)d_in[11];
    const float* fc2_w  = (const float*)d_in[12];
    const float* fc2_b  = (const float*)d_in[13];
    float* out = (float*)d_out;

    float *t_p;
    uint32_t *wh_p, *wl_p, *ah_p, *al_p, *bh_p, *bl_p, *qh_p, *ql_p;
    cudaGetSymbolAddress((void**)&t_p,  g_t);
    cudaGetSymbolAddress((void**)&wh_p, g_wh);
    cudaGetSymbolAddress((void**)&wl_p, g_wl);
    cudaGetSymbolAddress((void**)&ah_p, g_ah);
    cudaGetSymbolAddress((void**)&al_p, g_al);
    cudaGetSymbolAddress((void**)&bh_p, g_bh);
    cudaGetSymbolAddress((void**)&bl_p, g_bl);
    cudaGetSymbolAddress((void**)&qh_p, g_qkvh);
    cudaGetSymbolAddress((void**)&ql_p, g_qkvl);

    int attn_smem = ATTN_SMEM_U32 * (int)sizeof(uint32_t);
    cudaFuncSetAttribute(attn_mma_kernel, cudaFuncAttributeMaxDynamicSharedMemorySize, attn_smem);
    cudaFuncSetAttribute(gemm_cp_kernel<2>, cudaFuncAttributeMaxDynamicSharedMemorySize, GEMM_SMEM);
    cudaFuncSetAttribute(gemm_cp_kernel<3>, cudaFuncAttributeMaxDynamicSharedMemorySize, GEMM_SMEM);
    cudaFuncSetAttribute(gemm_cp_kernel<4>, cudaFuncAttributeMaxDynamicSharedMemorySize, GEMM_SMEM);
    cudaFuncSetAttribute(gemm_cp_kernel<5>, cudaFuncAttributeMaxDynamicSharedMemorySize, GEMM_SMEM);

    dim3 tb(16, 16);
    dim3 tg(W_/16, C_/16, B_*D_*H_);

    // 0. pre-split weights
    wsplit_kernel<<<256, 256>>>(qkv_w, proj_w, fc1_w, fc2_w);
    // 1. transpose in
    t_in_kernel<<<tg, tb>>>(x, t_p);
    // 2. LN1 + split
    ln_prep_kernel<<<NTOK/8, 256>>>(t_p, n1w, n1b, ah_p, al_p);
    // 3. qkv GEMM -> pre-split Q(scaled)/K/V   (M=384, K=128)
    gemm_cp_kernel<5><<<dim3(6, NTOK/128), 256, GEMM_SMEM>>>(
        ah_p, al_p, wh_p, wl_p, qkv_b, nullptr, qh_p, ql_p, nullptr, 384, 128);
    // 4. neighborhood attention -> pre-split out
    attn_mma_kernel<<<dim3(36, NHEAD, B_*D_), 128, attn_smem>>>(qh_p, ql_p, rpb, ah_p, al_p);
    // 5. t += attn @ proj_w^T + b     (M=128, K=128)
    gemm_cp_kernel<2><<<dim3(2, NTOK/128), 256, GEMM_SMEM>>>(
        ah_p, al_p, wh_p + 24576, wl_p + 24576, proj_b, t_p, nullptr, nullptr, nullptr, 128, 128);
    // 6. LN2 + split
    ln_prep_kernel<<<NTOK/8, 256>>>(t_p, n2w, n2b, ah_p, al_p);
    // 7. h1 = gelu(LN2(t) @ fc1_w^T + b) -> pre-split  (M=256, K=128)
    gemm_cp_kernel<4><<<dim3(4, NTOK/128), 256, GEMM_SMEM>>>(
        ah_p, al_p, wh_p + 32768, wl_p + 32768, fc1_b, nullptr, bh_p, bl_p, nullptr, 256, 128);
    // 8. out = transpose(t + h1 @ fc2_w^T + b)   (M=128, K=256)
    gemm_cp_kernel<3><<<dim3(2, NTOK/128), 256, GEMM_SMEM>>>(
        bh_p, bl_p, wh_p + 49152, wl_p + 49152, fc2_b, out, nullptr, nullptr, t_p, 128, 256);
}

// round 12
// speedup vs baseline: 2.5235x; 1.0002x over previous
#include <cuda_runtime.h>
#include <cuda_bf16.h>
#include <math.h>
#include <stdint.h>

// Problem constants
#define B_  2
#define C_  128
#define D_  4
#define H_  48
#define W_  48
#define NTOK (B_*D_*H_*W_)   // 18432
#define NHEAD 4
#define HD 32
#define KW 7

// Scratch (device globals — no allocation allowed)
__device__ float    g_t    [NTOK*128];
__device__ uint32_t g_qkvh [NTOK*192];   // pre-split qkv: Q[0:64) K[64:128) V[128:192) pairs
__device__ uint32_t g_qkvl [NTOK*192];
__device__ uint32_t g_ah   [NTOK*64];    // pre-split activations (attn out / ln out)
__device__ uint32_t g_al   [NTOK*64];
__device__ uint32_t g_bh   [NTOK*128];   // pre-split h1
__device__ uint32_t g_bl   [NTOK*128];
// Pre-split weights (bf16x2 hi/lo packed k-pairs, PERMUTED within 8-pair groups)
__device__ uint32_t g_wh[65536];
__device__ uint32_t g_wl[65536];

#define PERMJ(j) ((j) < 4 ? 2*(j) : 2*(j)-7)

// ===========================================================================
// Helpers
// ===========================================================================
__device__ __forceinline__ void mma_bf16(float* c, const uint32_t* a, const uint32_t* b) {
    asm volatile(
        "mma.sync.aligned.m16n8k16.row.col.f32.bf16.bf16.f32 "
        "{%0,%1,%2,%3}, {%4,%5,%6,%7}, {%8,%9}, {%0,%1,%2,%3};"
        : "+f"(c[0]), "+f"(c[1]), "+f"(c[2]), "+f"(c[3])
        : "r"(a[0]), "r"(a[1]), "r"(a[2]), "r"(a[3]), "r"(b[0]), "r"(b[1]));
}

__device__ __forceinline__ void bf16_split2(float x0, float x1, uint32_t& hi, uint32_t& lo) {
    __nv_bfloat162 h = __floats2bfloat162_rn(x0, x1);
    float h0 = __bfloat162float(h.x);
    float h1 = __bfloat162float(h.y);
    __nv_bfloat162 l = __floats2bfloat162_rn(x0 - h0, x1 - h1);
    hi = *reinterpret_cast<uint32_t*>(&h);
    lo = *reinterpret_cast<uint32_t*>(&l);
}

#define CP_ASYNC16(dst_u32, src_ptr) \
    asm volatile("cp.async.cg.shared.global [%0], [%1], 16;" \
        :: "r"(dst_u32), "l"(__cvta_generic_to_global(src_ptr)) : "memory")
#define CP_COMMIT() asm volatile("cp.async.commit_group;" ::: "memory")
#define CP_WAIT1()  asm volatile("cp.async.wait_group 1;" ::: "memory")
#define CP_WAIT0()  asm volatile("cp.async.wait_group 0;" ::: "memory")

// ===========================================================================
// Weight pre-split + permute
// ===========================================================================
__global__ void wsplit_kernel(const float* __restrict__ qkv_w,
                              const float* __restrict__ proj_w,
                              const float* __restrict__ fc1_w,
                              const float* __restrict__ fc2_w) {
    int i = blockIdx.x * 256 + threadIdx.x;
    const float* src;
    int li;
    if (i < 24576)      { src = qkv_w;  li = i; }
    else if (i < 32768) { src = proj_w; li = i - 24576; }
    else if (i < 49152) { src = fc1_w;  li = i - 32768; }
    else                { src = fc2_w;  li = i - 49152; }
    float2 v = *reinterpret_cast<const float2*>(src + 2 * li);
    uint32_t h, l;
    bf16_split2(v.x, v.y, h, l);
    int dst = (i & ~7) | PERMJ(i & 7);
    g_wh[dst] = h;
    g_wl[dst] = l;
}

// ===========================================================================
// Fused LN + split + permute: warp per token -> ah/al
// ===========================================================================
__global__ void ln_prep_kernel(const float* __restrict__ in,
                               const float* __restrict__ w,
                               const float* __restrict__ b,
                               uint32_t* __restrict__ ah,
                               uint32_t* __restrict__ al) {
    int n = blockIdx.x * 8 + (threadIdx.x >> 5);
    int lane = threadIdx.x & 31;
    float4 v = *reinterpret_cast<const float4*>(in + (long)n*128 + lane*4);
    float s  = v.x + v.y + v.z + v.w;
    float s2 = v.x*v.x + v.y*v.y + v.z*v.z + v.w*v.w;
    #pragma unroll
    for (int o = 16; o > 0; o >>= 1) {
        s  += __shfl_xor_sync(0xffffffffu, s,  o);
        s2 += __shfl_xor_sync(0xffffffffu, s2, o);
    }
    float m    = s  * (1.0f/128.0f);
    float rstd = rsqrtf(s2 * (1.0f/128.0f) - m*m + 1e-5f);
    float4 wv = *reinterpret_cast<const float4*>(w + lane*4);
    float4 bv = *reinterpret_cast<const float4*>(b + lane*4);
    float y0 = (v.x - m) * rstd * wv.x + bv.x;
    float y1 = (v.y - m) * rstd * wv.y + bv.y;
    float y2 = (v.z - m) * rstd * wv.z + bv.z;
    float y3 = (v.w - m) * rstd * wv.w + bv.w;
    uint32_t h0, l0, h1, l1;
    bf16_split2(y0, y1, h0, l0);
    bf16_split2(y2, y3, h1, l1);
    int p0 = 2*lane, p1 = 2*lane + 1;
    int i0 = (p0 & ~7) | PERMJ(p0 & 7);
    int i1 = (p1 & ~7) | PERMJ(p1 & 7);
    long base = (long)n * 64;
    ah[base + i0] = h0; ah[base + i1] = h1;
    al[base + i0] = l0; al[base + i1] = l1;
}

// ===========================================================================
// Tensor-core GEMM: cp.async 2-stage ring, 3 CTAs/SM, pre-split A and B.
// EPI: 0 bias fp32; 2 bias+residual; 3 bias+residual+transposed store;
//      4 bias+GELU+split; 5 qkv split epilogue (Q scaled+perm, K perm, V logical)
// ===========================================================================
#define GSTR 24
#define STAGE_U32 9216
#define GEMM_SMEM (2 * STAGE_U32 * 4)   // 73728 B -> 3 CTAs/SM

template<int EPI>
__global__ void __launch_bounds__(256, 3)
gemm_cp_kernel(const uint32_t* __restrict__ AHg,
               const uint32_t* __restrict__ ALg,
               const uint32_t* __restrict__ WH,
               const uint32_t* __restrict__ WL,
               const float* __restrict__ bias,
               float* __restrict__ out,
               uint32_t* __restrict__ outH,
               uint32_t* __restrict__ outL,
               const float* __restrict__ resid,
               int M, int K) {
    extern __shared__ uint32_t smg[];
    uint32_t smb = (uint32_t)__cvta_generic_to_shared(smg);

    int tid = threadIdx.x;
    int wid = tid >> 5, lane = tid & 31;
    int warp_m = wid & 3;
    int warp_n = wid >> 2;
    int gid = lane >> 2;
    int tig = lane & 3;

    int n0 = blockIdx.y * 128;
    int m0 = blockIdx.x * 64;
    int Kp = K >> 1;
    int nch = K >> 5;

    float acc[2][4][4];
    #pragma unroll
    for (int mt = 0; mt < 2; mt++)
        #pragma unroll
        for (int nt = 0; nt < 4; nt++)
            #pragma unroll
            for (int i = 0; i < 4; i++) acc[mt][nt][i] = 0.f;

    int a_row0 = tid >> 2,         a_q0 = tid & 3;
    int a_row1 = (tid + 256) >> 2, a_q1 = (tid + 256) & 3;
    int b_row = tid >> 2, b_q = tid & 3;

    auto issue = [&](int ch, int s) {
        uint32_t base = smb + (uint32_t)(s * STAGE_U32) * 4u;
        long ka = (long)ch * 16;
        CP_ASYNC16(base + (a_row0*GSTR + a_q0*4)*4,        AHg + (long)(n0 + a_row0)*Kp + ka + a_q0*4);
        CP_ASYNC16(base + (a_row1*GSTR + a_q1*4)*4,        AHg + (long)(n0 + a_row1)*Kp + ka + a_q1*4);
        CP_ASYNC16(base + (3072 + a_row0*GSTR + a_q0*4)*4, ALg + (long)(n0 + a_row0)*Kp + ka + a_q0*4);
        CP_ASYNC16(base + (3072 + a_row1*GSTR + a_q1*4)*4, ALg + (long)(n0 + a_row1)*Kp + ka + a_q1*4);
        CP_ASYNC16(base + (6144 + b_row*GSTR + b_q*4)*4,   WH + (long)(m0 + b_row)*Kp + ka + b_q*4);
        CP_ASYNC16(base + (7680 + b_row*GSTR + b_q*4)*4,   WL + (long)(m0 + b_row)*Kp + ka + b_q*4);
        CP_COMMIT();
    };

    issue(0, 0);
    if (nch > 1) issue(1, 1);

    for (int ch = 0; ch < nch; ch++) {
        if (ch + 1 < nch) { CP_WAIT1(); } else { CP_WAIT0(); }
        __syncthreads();

        uint32_t* AH = smg + (ch & 1) * STAGE_U32;
        uint32_t* AL = AH + 3072;
        uint32_t* BH = AH + 6144;
        uint32_t* BL = AH + 7680;
        #pragma unroll
        for (int ks = 0; ks < 2; ks++) {
            int jc = ks * 8 + 2 * tig;
            uint32_t ahi[2][4], alo[2][4];
            #pragma unroll
            for (int mt = 0; mt < 2; mt++) {
                int r = warp_m * 32 + mt * 16 + gid;
                uint2 h0 = *reinterpret_cast<uint2*>(&AH[r * GSTR + jc]);
                uint2 h1 = *reinterpret_cast<uint2*>(&AH[(r + 8) * GSTR + jc]);
                uint2 l0 = *reinterpret_cast<uint2*>(&AL[r * GSTR + jc]);
                uint2 l1 = *reinterpret_cast<uint2*>(&AL[(r + 8) * GSTR + jc]);
                ahi[mt][0] = h0.x; ahi[mt][1] = h1.x; ahi[mt][2] = h0.y; ahi[mt][3] = h1.y;
                alo[mt][0] = l0.x; alo[mt][1] = l1.x; alo[mt][2] = l0.y; alo[mt][3] = l1.y;
            }
            uint32_t bhi[4][2], blo[4][2];
            #pragma unroll
            for (int nt = 0; nt < 4; nt++) {
                int br = warp_n * 32 + nt * 8 + gid;
                uint2 bh = *reinterpret_cast<uint2*>(&BH[br * GSTR + jc]);
                uint2 bl = *reinterpret_cast<uint2*>(&BL[br * GSTR + jc]);
                bhi[nt][0] = bh.x; bhi[nt][1] = bh.y;
                blo[nt][0] = bl.x; blo[nt][1] = bl.y;
            }
            #pragma unroll
            for (int mt = 0; mt < 2; mt++)
                #pragma unroll
                for (int nt = 0; nt < 4; nt++) {
                    mma_bf16(acc[mt][nt], ahi[mt], bhi[nt]);
                    mma_bf16(acc[mt][nt], alo[mt], bhi[nt]);
                    mma_bf16(acc[mt][nt], ahi[mt], blo[nt]);
                }
        }
        __syncthreads();   // stage (ch&1) fully consumed by all warps

        if (ch + 2 < nch) issue(ch + 2, ch & 1);
    }

    // ---- epilogue
    int row_base = n0 + warp_m * 32;
    int col_base = m0 + warp_n * 32;
    #pragma unroll
    for (int nt = 0; nt < 4; nt++) {
        int col = col_base + nt * 8 + 2 * tig;
        float b0 = bias[col], b1 = bias[col + 1];
        #pragma unroll
        for (int mt = 0; mt < 2; mt++) {
            #pragma unroll
            for (int half = 0; half < 2; half++) {
                int r = row_base + mt * 16 + gid + half * 8;
                float v0 = acc[mt][nt][half * 2 + 0] + b0;
                float v1 = acc[mt][nt][half * 2 + 1] + b1;
                if (EPI == 5) {
                    uint32_t h_, l_;
                    int idx;
                    if (col < 128) {
                        const float sc = 0.17677669529663687f;
                        bf16_split2(v0 * sc, v1 * sc, h_, l_);
                        int p = col >> 1;
                        idx = (p & ~7) | PERMJ(p & 7);
                    } else if (col < 256) {
                        bf16_split2(v0, v1, h_, l_);
                        int p = (col - 128) >> 1;
                        idx = 64 + ((p & ~7) | PERMJ(p & 7));
                    } else {
                        bf16_split2(v0, v1, h_, l_);
                        idx = 128 + ((col - 256) >> 1);
                    }
                    outH[(long)r * 192 + idx] = h_;
                    outL[(long)r * 192 + idx] = l_;
                } else if (EPI == 4) {
                    v0 = 0.5f * v0 * (1.0f + erff(v0 * 0.70710678118654752f));
                    v1 = 0.5f * v1 * (1.0f + erff(v1 * 0.70710678118654752f));
                    uint32_t h_, l_;
                    bf16_split2(v0, v1, h_, l_);
                    int p = col >> 1;
                    int idx = (p & ~7) | PERMJ(p & 7);
                    outH[(long)r * 128 + idx] = h_;
                    outL[(long)r * 128 + idx] = l_;
                } else if (EPI == 3) {
                    float2 rv = *reinterpret_cast<const float2*>(resid + (long)r * 128 + col);
                    v0 += rv.x; v1 += rv.y;
                    long o = (long)r + (r >= 9216 ? 1170432L : 0L) + (long)col * 9216;
                    out[o]        = v0;
                    out[o + 9216] = v1;
                } else {
                    float2* dst = reinterpret_cast<float2*>(out + (long)r * M + col);
                    if (EPI == 2) {
                        float2 old = *dst;
                        v0 += old.x; v1 += old.y;
                    }
                    float2 st; st.x = v0; st.y = v1;
                    *dst = st;
                }
            }
        }
    }
}

// ===========================================================================
// Tensor-core neighborhood attention (unchanged from R11)
// ===========================================================================
#define AGSTR 24
#define VSTP  116
#define PSTP  68
#define ATTN_SMEM_U32 (2*224*AGSTR + 2*32*VSTP + 170)

__global__ void __launch_bounds__(128, 3)
attn_mma_kernel(const uint32_t* __restrict__ inH,
                const uint32_t* __restrict__ inL,
                const float* __restrict__ rpb,
                uint32_t* __restrict__ outH,
                uint32_t* __restrict__ outL) {
    extern __shared__ uint32_t smu[];
    uint32_t* KsH = smu;
    uint32_t* KsL = KsH + 224*AGSTR;
    uint32_t* VtH = KsL + 224*AGSTR;
    uint32_t* VtL = VtH + 32*VSTP;
    float*    rb  = reinterpret_cast<float*>(VtL + 32*VSTP);

    int tile = blockIdx.x, head = blockIdx.y, bd = blockIdx.z;
    int h0 = (tile / 6) * 8;
    int w0 = (tile % 6) * 8;
    int kh0 = min(max(h0 - 3, 0), H_ - KW);
    int kw0 = min(max(w0 - 3, 0), W_ - KW);
    int tid = threadIdx.x;

    for (int e = tid; e < 196*4; e += 128) {
        int key = e >> 2, q = e & 3;
        int kr = key / 14, kc = key % 14;
        int gh = min(kh0 + kr, H_-1);
        int gw = min(kw0 + kc, W_-1);
        long tok = ((long)(bd*H_ + gh))*W_ + gw;
        long src = tok*192 + 64 + head*16 + q*4;
        *reinterpret_cast<uint4*>(&KsH[key*AGSTR + q*4]) = *reinterpret_cast<const uint4*>(inH + src);
        *reinterpret_cast<uint4*>(&KsL[key*AGSTR + q*4]) = *reinterpret_cast<const uint4*>(inL + src);
    }
    for (int e = tid; e < 28*6; e += 128) {
        int key = 196 + e / 6, q = e % 6;
        uint4 z = make_uint4(0,0,0,0);
        *reinterpret_cast<uint4*>(&KsH[key*AGSTR + q*4]) = z;
        *reinterpret_cast<uint4*>(&KsL[key*AGSTR + q*4]) = z;
    }
    for (int e = tid; e < 98*4; e += 128) {
        int kp = e >> 2, pq = e & 3;
        int keyA = 2*kp;
        int kr = keyA / 14, kc = keyA % 14;
        int gh = min(kh0 + kr, H_-1);
        int gwA = min(kw0 + kc, W_-1);
        int gwB = min(kw0 + kc + 1, W_-1);
        long rowb = ((long)(bd*H_ + gh))*W_;
        long sA = (rowb + gwA)*192 + 128 + head*16 + pq*4;
        long sB = (rowb + gwB)*192 + 128 + head*16 + pq*4;
        uint4 HA = *reinterpret_cast<const uint4*>(inH + sA);
        uint4 HB = *reinterpret_cast<const uint4*>(inH + sB);
        uint4 LA = *reinterpret_cast<const uint4*>(inL + sA);
        uint4 LB = *reinterpret_cast<const uint4*>(inL + sB);
        uint32_t ha[4] = {HA.x, HA.y, HA.z, HA.w};
        uint32_t hb[4] = {HB.x, HB.y, HB.z, HB.w};
        uint32_t la[4] = {LA.x, LA.y, LA.z, LA.w};
        uint32_t lb[4] = {LB.x, LB.y, LB.z, LB.w};
        #pragma unroll
        for (int j = 0; j < 4; j++) {
            int pp = pq*4 + j;
            VtH[(2*pp+0)*VSTP + kp] = __byte_perm(ha[j], hb[j], 0x5410);
            VtH[(2*pp+1)*VSTP + kp] = __byte_perm(ha[j], hb[j], 0x7632);
            VtL[(2*pp+0)*VSTP + kp] = __byte_perm(la[j], lb[j], 0x5410);
            VtL[(2*pp+1)*VSTP + kp] = __byte_perm(la[j], lb[j], 0x7632);
        }
    }
    for (int e = tid; e < 32*14; e += 128) {
        int dm = e / 14, kp = 98 + (e % 14);
        VtH[dm*VSTP + kp] = 0; VtL[dm*VSTP + kp] = 0;
    }
    for (int i = tid; i < 169; i += 128) rb[i] = rpb[head*169 + i];
    __syncthreads();

    int warp = tid >> 5, lane = tid & 31;
    int gid = lane >> 2, tig = lane & 3;

    int hq0 = h0 + 2*warp;
    int hq1 = hq0 + 1;
    int wq  = w0 + gid;
    long tok0 = (long)(bd*H_ + hq0)*W_ + wq;
    long tok1 = tok0 + W_;
    int rel0 = min(max(hq0-3, 0), H_-KW) - kh0;
    int rel1 = min(max(hq1-3, 0), H_-KW) - kh0;
    int ws   = min(max(wq-3, 0), W_-KW) - kw0;
    int n_base = ((min(rel0, rel1) * 14) >> 3) * 8;

    uint32_t qh[2][4], ql[2][4];
    #pragma unroll
    for (int ks = 0; ks < 2; ks++) {
        long o0 = tok0*192 + head*16 + ks*8 + 2*tig;
        long o1 = tok1*192 + head*16 + ks*8 + 2*tig;
        uint2 h0v = *reinterpret_cast<const uint2*>(inH + o0);
        uint2 h1v = *reinterpret_cast<const uint2*>(inH + o1);
        uint2 l0v = *reinterpret_cast<const uint2*>(inL + o0);
        uint2 l1v = *reinterpret_cast<const uint2*>(inL + o1);
        qh[ks][0] = h0v.x; qh[ks][1] = h1v.x; qh[ks][2] = h0v.y; qh[ks][3] = h1v.y;
        ql[ks][0] = l0v.x; ql[ks][1] = l1v.x; ql[ks][2] = l0v.y; ql[ks][3] = l1v.y;
    }

    float acc[15][4];
    #pragma unroll
    for (int nt = 0; nt < 15; nt++)
        #pragma unroll
        for (int i = 0; i < 4; i++) acc[nt][i] = 0.f;

    #pragma unroll
    for (int nt = 0; nt < 15; nt++) {
        int key = n_base + nt*8 + gid;
        #pragma unroll
        for (int ks = 0; ks < 2; ks++) {
            int o = key*AGSTR + ks*8 + 2*tig;
            uint2 bhv = *reinterpret_cast<uint2*>(&KsH[o]);
            uint2 blv = *reinterpret_cast<uint2*>(&KsL[o]);
            uint32_t bh[2] = { bhv.x, bhv.y };
            uint32_t bl[2] = { blv.x, blv.y };
            mma_bf16(acc[nt], qh[ks], bh);
            mma_bf16(acc[nt], ql[ks], bh);
            mma_bf16(acc[nt], qh[ks], bl);
        }
    }

    int bh0c = kh0 - hq0 + 6;
    int bh1c = kh0 - hq1 + 6;
    int bwc  = kw0 - wq + 6;
    float mx0 = -1e30f, mx1 = -1e30f;
    #pragma unroll
    for (int nt = 0; nt < 15; nt++) {
        #pragma unroll
        for (int cc = 0; cc < 2; cc++) {
            int n = n_base + nt*8 + 2*tig + cc;
            int kr = n / 14;
            int kc = n - kr*14;
            bool vw = (unsigned)(kc - ws) <= 6u;
            bool v0 = vw && (unsigned)(kr - rel0) <= 6u;
            bool v1 = vw && (unsigned)(kr - rel1) <= 6u;
            float s0 = v0 ? acc[nt][cc]   + rb[(bh0c+kr)*13 + bwc + kc] : -1e30f;
            float s1 = v1 ? acc[nt][2+cc] + rb[(bh1c+kr)*13 + bwc + kc] : -1e30f;
            acc[nt][cc]   = s0;
            acc[nt][2+cc] = s1;
            mx0 = fmaxf(mx0, s0);
            mx1 = fmaxf(mx1, s1);
        }
    }
    mx0 = fmaxf(mx0, __shfl_xor_sync(0xffffffffu, mx0, 1));
    mx0 = fmaxf(mx0, __shfl_xor_sync(0xffffffffu, mx0, 2));
    mx1 = fmaxf(mx1, __shfl_xor_sync(0xffffffffu, mx1, 1));
    mx1 = fmaxf(mx1, __shfl_xor_sync(0xffffffffu, mx1, 2));

    float sum0 = 0.f, sum1 = 0.f;
    #pragma unroll
    for (int nt = 0; nt < 15; nt++) {
        #pragma unroll
        for (int cc = 0; cc < 2; cc++) {
            float e0 = __expf(acc[nt][cc]   - mx0);
            float e1 = __expf(acc[nt][2+cc] - mx1);
            acc[nt][cc]   = e0;
            acc[nt][2+cc] = e1;
            sum0 += e0;
            sum1 += e1;
        }
    }
    sum0 += __shfl_xor_sync(0xffffffffu, sum0, 1);
    sum0 += __shfl_xor_sync(0xffffffffu, sum0, 2);
    sum1 += __shfl_xor_sync(0xffffffffu, sum1, 1);
    sum1 += __shfl_xor_sync(0xffffffffu, sum1, 2);
    float inv0 = 1.0f / sum0;
    float inv1 = 1.0f / sum1;

    __syncthreads();
    uint32_t* PwH = smu + warp * (16 * PSTP * 2);
    uint32_t* PwL = PwH + 16 * PSTP;
    #pragma unroll
    for (int nt = 0; nt < 15; nt++) {
        uint32_t h_, l_;
        bf16_split2(acc[nt][0], acc[nt][1], h_, l_);
        PwH[gid*PSTP + nt*4 + tig] = h_;
        PwL[gid*PSTP + nt*4 + tig] = l_;
        bf16_split2(acc[nt][2], acc[nt][3], h_, l_);
        PwH[(gid+8)*PSTP + nt*4 + tig] = h_;
        PwL[(gid+8)*PSTP + nt*4 + tig] = l_;
    }
    PwH[gid*PSTP + 60 + tig] = 0;     PwL[gid*PSTP + 60 + tig] = 0;
    PwH[(gid+8)*PSTP + 60 + tig] = 0; PwL[(gid+8)*PSTP + 60 + tig] = 0;
    __syncwarp();

    int nb2 = n_base >> 1;
    float o[4][4];
    #pragma unroll
    for (int nt = 0; nt < 4; nt++)
        #pragma unroll
        for (int i = 0; i < 4; i++) o[nt][i] = 0.f;

    #pragma unroll
    for (int kt = 0; kt < 8; kt++) {
        int p0 = gid*PSTP + kt*8 + tig;
        int p1 = (gid+8)*PSTP + kt*8 + tig;
        uint32_t ph[4] = { PwH[p0], PwH[p1], PwH[p0 + 4], PwH[p1 + 4] };
        uint32_t pl[4] = { PwL[p0], PwL[p1], PwL[p0 + 4], PwL[p1 + 4] };
        #pragma unroll
        for (int nt = 0; nt < 4; nt++) {
            int vr = (nt*8 + gid)*VSTP + nb2 + kt*8 + tig;
            uint32_t vh[2] = { VtH[vr], VtH[vr + 4] };
            uint32_t vl[2] = { VtL[vr], VtL[vr + 4] };
            mma_bf16(o[nt], ph, vh);
            mma_bf16(o[nt], pl, vh);
            mma_bf16(o[nt], ph, vl);
        }
    }

    #pragma unroll
    for (int nt = 0; nt < 4; nt++) {
        int d = head*32 + nt*8 + 2*tig;
        int p = d >> 1;
        int idx = (p & ~7) | PERMJ(p & 7);
        uint32_t h_, l_;
        bf16_split2(o[nt][0]*inv0, o[nt][1]*inv0, h_, l_);
        outH[tok0*64 + idx] = h_;
        outL[tok0*64 + idx] = l_;
        bf16_split2(o[nt][2]*inv1, o[nt][3]*inv1, h_, l_);
        outH[tok1*64 + idx] = h_;
        outL[tok1*64 + idx] = l_;
    }
}

// ---------------------------------------------------------------------------
// Transpose in: x (B,C,D,H,W) -> t (N=B*D*H*W, C)
// ---------------------------------------------------------------------------
__global__ void t_in_kernel(const float* __restrict__ x, float* __restrict__ t) {
    __shared__ float sm[16][17];
    int bz = blockIdx.z;
    int b = bz / (D_*H_);
    int rem = bz % (D_*H_);
    int d = rem / H_;
    int h = rem % H_;
    int w = blockIdx.x*16 + threadIdx.x;
    int c = blockIdx.y*16 + threadIdx.y;
    sm[threadIdx.y][threadIdx.x] =
        x[(( (long)b*C_ + c)*D_ + d)*(H_*W_) + h*W_ + w];
    __syncthreads();
    int c2 = blockIdx.y*16 + threadIdx.x;
    int w2 = blockIdx.x*16 + threadIdx.y;
    t[((((b*D_ + d)*H_ + h)*W_ + w2) * (long)C_) + c2] = sm[threadIdx.x][threadIdx.y];
}

// ---------------------------------------------------------------------------
// Launch
// ---------------------------------------------------------------------------
extern "C" void kernel_launch(void* const* d_in, const int* in_sizes, int n_in,
                              void* d_out, int out_size) {
    const float* x      = (const float*)d_in[0];
    const float* n1w    = (const float*)d_in[1];
    const float* n1b    = (const float*)d_in[2];
    const float* qkv_w  = (const float*)d_in[3];
    const float* qkv_b  = (const float*)d_in[4];
    const float* rpb    = (const float*)d_in[5];
    const float* proj_w = (const float*)d_in[6];
    const float* proj_b = (const float*)d_in[7];
    const float* n2w    = (const float*)d_in[8];
    const float* n2b    = (const float*)d_in[9];
    const float* fc1_w  = (const float*)d_in[10];
    const float* fc1_b  = (const float*)d_in[11];
    const float* fc2_w  = (const float*)d_in[12];
    const float* fc2_b  = (const float*)d_in[13];
    float* out = (float*)d_out;

    float *t_p;
    uint32_t *wh_p, *wl_p, *ah_p, *al_p, *bh_p, *bl_p, *qh_p, *ql_p;
    cudaGetSymbolAddress((void**)&t_p,  g_t);
    cudaGetSymbolAddress((void**)&wh_p, g_wh);
    cudaGetSymbolAddress((void**)&wl_p, g_wl);
    cudaGetSymbolAddress((void**)&ah_p, g_ah);
    cudaGetSymbolAddress((void**)&al_p, g_al);
    cudaGetSymbolAddress((void**)&bh_p, g_bh);
    cudaGetSymbolAddress((void**)&bl_p, g_bl);
    cudaGetSymbolAddress((void**)&qh_p, g_qkvh);
    cudaGetSymbolAddress((void**)&ql_p, g_qkvl);

    int attn_smem = ATTN_SMEM_U32 * (int)sizeof(uint32_t);
    cudaFuncSetAttribute(attn_mma_kernel, cudaFuncAttributeMaxDynamicSharedMemorySize, attn_smem);
    cudaFuncSetAttribute(gemm_cp_kernel<2>, cudaFuncAttributeMaxDynamicSharedMemorySize, GEMM_SMEM);
    cudaFuncSetAttribute(gemm_cp_kernel<3>, cudaFuncAttributeMaxDynamicSharedMemorySize, GEMM_SMEM);
    cudaFuncSetAttribute(gemm_cp_kernel<4>, cudaFuncAttributeMaxDynamicSharedMemorySize, GEMM_SMEM);
    cudaFuncSetAttribute(gemm_cp_kernel<5>, cudaFuncAttributeMaxDynamicSharedMemorySize, GEMM_SMEM);

    dim3 tb(16, 16);
    dim3 tg(W_/16, C_/16, B_*D_*H_);

    // 0. pre-split weights
    wsplit_kernel<<<256, 256>>>(qkv_w, proj_w, fc1_w, fc2_w);
    // 1. transpose in
    t_in_kernel<<<tg, tb>>>(x, t_p);
    // 2. LN1 + split
    ln_prep_kernel<<<NTOK/8, 256>>>(t_p, n1w, n1b, ah_p, al_p);
    // 3. qkv GEMM -> pre-split Q(scaled)/K/V   (M=384, K=128)
    gemm_cp_kernel<5><<<dim3(6, NTOK/128), 256, GEMM_SMEM>>>(
        ah_p, al_p, wh_p, wl_p, qkv_b, nullptr, qh_p, ql_p, nullptr, 384, 128);
    // 4. neighborhood attention -> pre-split out
    attn_mma_kernel<<<dim3(36, NHEAD, B_*D_), 128, attn_smem>>>(qh_p, ql_p, rpb, ah_p, al_p);
    // 5. t += attn @ proj_w^T + b     (M=128, K=128)
    gemm_cp_kernel<2><<<dim3(2, NTOK/128), 256, GEMM_SMEM>>>(
        ah_p, al_p, wh_p + 24576, wl_p + 24576, proj_b, t_p, nullptr, nullptr, nullptr, 128, 128);
    // 6. LN2 + split
    ln_prep_kernel<<<NTOK/8, 256>>>(t_p, n2w, n2b, ah_p, al_p);
    // 7. h1 = gelu(LN2(t) @ fc1_w^T + b) -> pre-split  (M=256, K=128)
    gemm_cp_kernel<4><<<dim3(4, NTOK/128), 256, GEMM_SMEM>>>(
        ah_p, al_p, wh_p + 32768, wl_p + 32768, fc1_b, nullptr, bh_p, bl_p, nullptr, 256, 128);
    // 8. out = transpose(t + h1 @ fc2_w^T + b)   (M=128, K=256)
    gemm_cp_kernel<3><<<dim3(2, NTOK/128), 256, GEMM_SMEM>>>(
        bh_p, bl_p, wh_p + 49152, wl_p + 49152, fc2_b, out, nullptr, nullptr, t_p, 128, 256);
}

// round 13
// speedup vs baseline: 4.1479x; 1.6437x over previous
#include <cuda_runtime.h>
#include <cuda_fp16.h>
#include <math.h>
#include <stdint.h>

// Problem constants
#define B_  2
#define C_  128
#define D_  4
#define H_  48
#define W_  48
#define NTOK (B_*D_*H_*W_)   // 18432
#define NHEAD 4
#define HD 32
#define KW 7

// Scratch (device globals — no allocation allowed)
__device__ float    g_t    [NTOK*128];
__device__ uint32_t g_qkvh [NTOK*192];   // fp16x2 qkv: Q[0:64) K[64:128) V[128:192) pairs
__device__ uint32_t g_ah   [NTOK*64];    // fp16x2 activations (ln out / attn out)
__device__ uint32_t g_bh   [NTOK*128];   // fp16x2 h1
// fp16x2 weights (packed k-pairs, PERMUTED within 8-pair groups)
__device__ uint32_t g_wh[65536];

#define PERMJ(j) ((j) < 4 ? 2*(j) : 2*(j)-7)

// ===========================================================================
// Helpers
// ===========================================================================
__device__ __forceinline__ void mma_fp16(float* c, const uint32_t* a, const uint32_t* b) {
    asm volatile(
        "mma.sync.aligned.m16n8k16.row.col.f32.f16.f16.f32 "
        "{%0,%1,%2,%3}, {%4,%5,%6,%7}, {%8,%9}, {%0,%1,%2,%3};"
        : "+f"(c[0]), "+f"(c[1]), "+f"(c[2]), "+f"(c[3])
        : "r"(a[0]), "r"(a[1]), "r"(a[2]), "r"(a[3]), "r"(b[0]), "r"(b[1]));
}

__device__ __forceinline__ uint32_t f22h2(float x0, float x1) {
    __half2 h = __floats2half2_rn(x0, x1);
    return *reinterpret_cast<uint32_t*>(&h);
}

#define CP_ASYNC16(dst_u32, src_ptr) \
    asm volatile("cp.async.cg.shared.global [%0], [%1], 16;" \
        :: "r"(dst_u32), "l"(__cvta_generic_to_global(src_ptr)) : "memory")
#define CP_COMMIT() asm volatile("cp.async.commit_group;" ::: "memory")
#define CP_WAIT1()  asm volatile("cp.async.wait_group 1;" ::: "memory")
#define CP_WAIT0()  asm volatile("cp.async.wait_group 0;" ::: "memory")

// ===========================================================================
// Weight convert + permute (fp16 pairs)
// ===========================================================================
__global__ void wsplit_kernel(const float* __restrict__ qkv_w,
                              const float* __restrict__ proj_w,
                              const float* __restrict__ fc1_w,
                              const float* __restrict__ fc2_w) {
    int i = blockIdx.x * 256 + threadIdx.x;
    const float* src;
    int li;
    if (i < 24576)      { src = qkv_w;  li = i; }
    else if (i < 32768) { src = proj_w; li = i - 24576; }
    else if (i < 49152) { src = fc1_w;  li = i - 32768; }
    else                { src = fc2_w;  li = i - 49152; }
    float2 v = *reinterpret_cast<const float2*>(src + 2 * li);
    int dst = (i & ~7) | PERMJ(i & 7);
    g_wh[dst] = f22h2(v.x, v.y);
}

// ===========================================================================
// Fused LN + fp16 convert + permute: warp per token -> ah
// ===========================================================================
__global__ void ln_prep_kernel(const float* __restrict__ in,
                               const float* __restrict__ w,
                               const float* __restrict__ b,
                               uint32_t* __restrict__ ah) {
    int n = blockIdx.x * 8 + (threadIdx.x >> 5);
    int lane = threadIdx.x & 31;
    float4 v = *reinterpret_cast<const float4*>(in + (long)n*128 + lane*4);
    float s  = v.x + v.y + v.z + v.w;
    float s2 = v.x*v.x + v.y*v.y + v.z*v.z + v.w*v.w;
    #pragma unroll
    for (int o = 16; o > 0; o >>= 1) {
        s  += __shfl_xor_sync(0xffffffffu, s,  o);
        s2 += __shfl_xor_sync(0xffffffffu, s2, o);
    }
    float m    = s  * (1.0f/128.0f);
    float rstd = rsqrtf(s2 * (1.0f/128.0f) - m*m + 1e-5f);
    float4 wv = *reinterpret_cast<const float4*>(w + lane*4);
    float4 bv = *reinterpret_cast<const float4*>(b + lane*4);
    float y0 = (v.x - m) * rstd * wv.x + bv.x;
    float y1 = (v.y - m) * rstd * wv.y + bv.y;
    float y2 = (v.z - m) * rstd * wv.z + bv.z;
    float y3 = (v.w - m) * rstd * wv.w + bv.w;
    int p0 = 2*lane, p1 = 2*lane + 1;
    int i0 = (p0 & ~7) | PERMJ(p0 & 7);
    int i1 = (p1 & ~7) | PERMJ(p1 & 7);
    long base = (long)n * 64;
    ah[base + i0] = f22h2(y0, y1);
    ah[base + i1] = f22h2(y2, y3);
}

// ===========================================================================
// fp16 tensor-core GEMM: cp.async 2-stage ring.
// out[NTOK,M] = A[NTOK,K] @ W[M,K]^T + bias (+epilogue)
// EPI: 0 bias fp32; 2 bias+residual; 3 bias+residual+transposed store;
//      4 bias+GELU+fp16; 5 qkv fp16 epilogue (Q scaled+perm, K perm, V logical)
// ===========================================================================
#define GSTR 24
#define STAGE_U32 4608          // A: 128*24=3072, B: 64*24=1536
#define GEMM_SMEM (2 * STAGE_U32 * 4)   // 36864 B

template<int EPI>
__global__ void __launch_bounds__(256, 3)
gemm_cp_kernel(const uint32_t* __restrict__ AHg,
               const uint32_t* __restrict__ WH,
               const float* __restrict__ bias,
               float* __restrict__ out,
               uint32_t* __restrict__ outH,
               const float* __restrict__ resid,
               int M, int K) {
    extern __shared__ uint32_t smg[];
    uint32_t smb = (uint32_t)__cvta_generic_to_shared(smg);

    int tid = threadIdx.x;
    int wid = tid >> 5, lane = tid & 31;
    int warp_m = wid & 3;
    int warp_n = wid >> 2;
    int gid = lane >> 2;
    int tig = lane & 3;

    int n0 = blockIdx.y * 128;
    int m0 = blockIdx.x * 64;
    int Kp = K >> 1;
    int nch = K >> 5;

    float acc[2][4][4];
    #pragma unroll
    for (int mt = 0; mt < 2; mt++)
        #pragma unroll
        for (int nt = 0; nt < 4; nt++)
            #pragma unroll
            for (int i = 0; i < 4; i++) acc[mt][nt][i] = 0.f;

    int a_row0 = tid >> 2,         a_q0 = tid & 3;
    int a_row1 = (tid + 256) >> 2, a_q1 = (tid + 256) & 3;
    int b_row = tid >> 2, b_q = tid & 3;

    auto issue = [&](int ch, int s) {
        uint32_t base = smb + (uint32_t)(s * STAGE_U32) * 4u;
        long ka = (long)ch * 16;
        CP_ASYNC16(base + (a_row0*GSTR + a_q0*4)*4,        AHg + (long)(n0 + a_row0)*Kp + ka + a_q0*4);
        CP_ASYNC16(base + (a_row1*GSTR + a_q1*4)*4,        AHg + (long)(n0 + a_row1)*Kp + ka + a_q1*4);
        CP_ASYNC16(base + (3072 + b_row*GSTR + b_q*4)*4,   WH + (long)(m0 + b_row)*Kp + ka + b_q*4);
        CP_COMMIT();
    };

    issue(0, 0);
    if (nch > 1) issue(1, 1);

    for (int ch = 0; ch < nch; ch++) {
        if (ch + 1 < nch) { CP_WAIT1(); } else { CP_WAIT0(); }
        __syncthreads();

        uint32_t* AH = smg + (ch & 1) * STAGE_U32;
        uint32_t* BH = AH + 3072;
        #pragma unroll
        for (int ks = 0; ks < 2; ks++) {
            int jc = ks * 8 + 2 * tig;
            uint32_t ahi[2][4];
            #pragma unroll
            for (int mt = 0; mt < 2; mt++) {
                int r = warp_m * 32 + mt * 16 + gid;
                uint2 h0 = *reinterpret_cast<uint2*>(&AH[r * GSTR + jc]);
                uint2 h1 = *reinterpret_cast<uint2*>(&AH[(r + 8) * GSTR + jc]);
                ahi[mt][0] = h0.x; ahi[mt][1] = h1.x; ahi[mt][2] = h0.y; ahi[mt][3] = h1.y;
            }
            uint32_t bhi[4][2];
            #pragma unroll
            for (int nt = 0; nt < 4; nt++) {
                int br = warp_n * 32 + nt * 8 + gid;
                uint2 bh = *reinterpret_cast<uint2*>(&BH[br * GSTR + jc]);
                bhi[nt][0] = bh.x; bhi[nt][1] = bh.y;
            }
            #pragma unroll
            for (int mt = 0; mt < 2; mt++)
                #pragma unroll
                for (int nt = 0; nt < 4; nt++)
                    mma_fp16(acc[mt][nt], ahi[mt], bhi[nt]);
        }
        __syncthreads();

        if (ch + 2 < nch) issue(ch + 2, ch & 1);
    }

    // ---- epilogue
    int row_base = n0 + warp_m * 32;
    int col_base = m0 + warp_n * 32;
    #pragma unroll
    for (int nt = 0; nt < 4; nt++) {
        int col = col_base + nt * 8 + 2 * tig;
        float b0 = bias[col], b1 = bias[col + 1];
        #pragma unroll
        for (int mt = 0; mt < 2; mt++) {
            #pragma unroll
            for (int half = 0; half < 2; half++) {
                int r = row_base + mt * 16 + gid + half * 8;
                float v0 = acc[mt][nt][half * 2 + 0] + b0;
                float v1 = acc[mt][nt][half * 2 + 1] + b1;
                if (EPI == 5) {
                    int idx;
                    if (col < 128) {
                        const float sc = 0.17677669529663687f;
                        v0 *= sc; v1 *= sc;
                        int p = col >> 1;
                        idx = (p & ~7) | PERMJ(p & 7);
                    } else if (col < 256) {
                        int p = (col - 128) >> 1;
                        idx = 64 + ((p & ~7) | PERMJ(p & 7));
                    } else {
                        idx = 128 + ((col - 256) >> 1);
                    }
                    outH[(long)r * 192 + idx] = f22h2(v0, v1);
                } else if (EPI == 4) {
                    v0 = 0.5f * v0 * (1.0f + erff(v0 * 0.70710678118654752f));
                    v1 = 0.5f * v1 * (1.0f + erff(v1 * 0.70710678118654752f));
                    int p = col >> 1;
                    int idx = (p & ~7) | PERMJ(p & 7);
                    outH[(long)r * 128 + idx] = f22h2(v0, v1);
                } else if (EPI == 3) {
                    float2 rv = *reinterpret_cast<const float2*>(resid + (long)r * 128 + col);
                    v0 += rv.x; v1 += rv.y;
                    long o = (long)r + (r >= 9216 ? 1170432L : 0L) + (long)col * 9216;
                    out[o]        = v0;
                    out[o + 9216] = v1;
                } else {
                    float2* dst = reinterpret_cast<float2*>(out + (long)r * M + col);
                    if (EPI == 2) {
                        float2 old = *dst;
                        v0 += old.x; v1 += old.y;
                    }
                    float2 st; st.x = v0; st.y = v1;
                    *dst = st;
                }
            }
        }
    }
}

// ===========================================================================
// fp16 tensor-core neighborhood attention.
// ===========================================================================
#define AGSTR 24
#define VSTP  116
#define PSTP  68
#define ATTN_SMEM_U32 (224*AGSTR + 32*VSTP + 170)   // 9258

__global__ void __launch_bounds__(128, 4)
attn_mma_kernel(const uint32_t* __restrict__ inH,
                const float* __restrict__ rpb,
                uint32_t* __restrict__ outH) {
    extern __shared__ uint32_t smu[];
    uint32_t* Ks = smu;                    // [224][24]
    uint32_t* Vt = Ks + 224*AGSTR;         // [32][116]
    float*    rb = reinterpret_cast<float*>(Vt + 32*VSTP);

    int tile = blockIdx.x, head = blockIdx.y, bd = blockIdx.z;
    int h0 = (tile / 6) * 8;
    int w0 = (tile % 6) * 8;
    int kh0 = min(max(h0 - 3, 0), H_ - KW);
    int kw0 = min(max(w0 - 3, 0), W_ - KW);
    int tid = threadIdx.x;

    // ---- K: pure uint4 copies (permuted pair layout)
    for (int e = tid; e < 196*4; e += 128) {
        int key = e >> 2, q = e & 3;
        int kr = key / 14, kc = key % 14;
        int gh = min(kh0 + kr, H_-1);
        int gw = min(kw0 + kc, W_-1);
        long tok = ((long)(bd*H_ + gh))*W_ + gw;
        long src = tok*192 + 64 + head*16 + q*4;
        *reinterpret_cast<uint4*>(&Ks[key*AGSTR + q*4]) = *reinterpret_cast<const uint4*>(inH + src);
    }
    for (int e = tid; e < 28*6; e += 128) {
        int key = 196 + e / 6, q = e % 6;
        *reinterpret_cast<uint4*>(&Ks[key*AGSTR + q*4]) = make_uint4(0,0,0,0);
    }
    // ---- V^T: PRMT repack of dim-pairs into key-pairs
    for (int e = tid; e < 98*4; e += 128) {
        int kp = e >> 2, pq = e & 3;
        int keyA = 2*kp;
        int kr = keyA / 14, kc = keyA % 14;
        int gh = min(kh0 + kr, H_-1);
        int gwA = min(kw0 + kc, W_-1);
        int gwB = min(kw0 + kc + 1, W_-1);
        long rowb = ((long)(bd*H_ + gh))*W_;
        long sA = (rowb + gwA)*192 + 128 + head*16 + pq*4;
        long sB = (rowb + gwB)*192 + 128 + head*16 + pq*4;
        uint4 HA = *reinterpret_cast<const uint4*>(inH + sA);
        uint4 HB = *reinterpret_cast<const uint4*>(inH + sB);
        uint32_t ha[4] = {HA.x, HA.y, HA.z, HA.w};
        uint32_t hb[4] = {HB.x, HB.y, HB.z, HB.w};
        #pragma unroll
        for (int j = 0; j < 4; j++) {
            int pp = pq*4 + j;
            Vt[(2*pp+0)*VSTP + kp] = __byte_perm(ha[j], hb[j], 0x5410);
            Vt[(2*pp+1)*VSTP + kp] = __byte_perm(ha[j], hb[j], 0x7632);
        }
    }
    for (int e = tid; e < 32*14; e += 128) {
        int dm = e / 14, kp = 98 + (e % 14);
        Vt[dm*VSTP + kp] = 0;
    }
    for (int i = tid; i < 169; i += 128) rb[i] = rpb[head*169 + i];
    __syncthreads();

    int warp = tid >> 5, lane = tid & 31;
    int gid = lane >> 2, tig = lane & 3;

    int hq0 = h0 + 2*warp;
    int hq1 = hq0 + 1;
    int wq  = w0 + gid;
    long tok0 = (long)(bd*H_ + hq0)*W_ + wq;
    long tok1 = tok0 + W_;
    int rel0 = min(max(hq0-3, 0), H_-KW) - kh0;
    int rel1 = min(max(hq1-3, 0), H_-KW) - kh0;
    int ws   = min(max(wq-3, 0), W_-KW) - kw0;
    int n_base = ((min(rel0, rel1) * 14) >> 3) * 8;

    // ---- Q fragments (pre-scaled, permuted by qkv GEMM)
    uint32_t qh[2][4];
    #pragma unroll
    for (int ks = 0; ks < 2; ks++) {
        long o0 = tok0*192 + head*16 + ks*8 + 2*tig;
        long o1 = tok1*192 + head*16 + ks*8 + 2*tig;
        uint2 h0v = *reinterpret_cast<const uint2*>(inH + o0);
        uint2 h1v = *reinterpret_cast<const uint2*>(inH + o1);
        qh[ks][0] = h0v.x; qh[ks][1] = h1v.x; qh[ks][2] = h0v.y; qh[ks][3] = h1v.y;
    }

    // ---- Scores
    float acc[15][4];
    #pragma unroll
    for (int nt = 0; nt < 15; nt++)
        #pragma unroll
        for (int i = 0; i < 4; i++) acc[nt][i] = 0.f;

    #pragma unroll
    for (int nt = 0; nt < 15; nt++) {
        int key = n_base + nt*8 + gid;
        #pragma unroll
        for (int ks = 0; ks < 2; ks++) {
            int o = key*AGSTR + ks*8 + 2*tig;
            uint2 bhv = *reinterpret_cast<uint2*>(&Ks[o]);
            uint32_t bh[2] = { bhv.x, bhv.y };
            mma_fp16(acc[nt], qh[ks], bh);
        }
    }

    // ---- Bias + mask + softmax
    int bh0c = kh0 - hq0 + 6;
    int bh1c = kh0 - hq1 + 6;
    int bwc  = kw0 - wq + 6;
    float mx0 = -1e30f, mx1 = -1e30f;
    #pragma unroll
    for (int nt = 0; nt < 15; nt++) {
        #pragma unroll
        for (int cc = 0; cc < 2; cc++) {
            int n = n_base + nt*8 + 2*tig + cc;
            int kr = n / 14;
            int kc = n - kr*14;
            bool vw = (unsigned)(kc - ws) <= 6u;
            bool v0 = vw && (unsigned)(kr - rel0) <= 6u;
            bool v1 = vw && (unsigned)(kr - rel1) <= 6u;
            float s0 = v0 ? acc[nt][cc]   + rb[(bh0c+kr)*13 + bwc + kc] : -1e30f;
            float s1 = v1 ? acc[nt][2+cc] + rb[(bh1c+kr)*13 + bwc + kc] : -1e30f;
            acc[nt][cc]   = s0;
            acc[nt][2+cc] = s1;
            mx0 = fmaxf(mx0, s0);
            mx1 = fmaxf(mx1, s1);
        }
    }
    mx0 = fmaxf(mx0, __shfl_xor_sync(0xffffffffu, mx0, 1));
    mx0 = fmaxf(mx0, __shfl_xor_sync(0xffffffffu, mx0, 2));
    mx1 = fmaxf(mx1, __shfl_xor_sync(0xffffffffu, mx1, 1));
    mx1 = fmaxf(mx1, __shfl_xor_sync(0xffffffffu, mx1, 2));

    float sum0 = 0.f, sum1 = 0.f;
    #pragma unroll
    for (int nt = 0; nt < 15; nt++) {
        #pragma unroll
        for (int cc = 0; cc < 2; cc++) {
            float e0 = __expf(acc[nt][cc]   - mx0);
            float e1 = __expf(acc[nt][2+cc] - mx1);
            acc[nt][cc]   = e0;
            acc[nt][2+cc] = e1;
            sum0 += e0;
            sum1 += e1;
        }
    }
    sum0 += __shfl_xor_sync(0xffffffffu, sum0, 1);
    sum0 += __shfl_xor_sync(0xffffffffu, sum0, 2);
    sum1 += __shfl_xor_sync(0xffffffffu, sum1, 1);
    sum1 += __shfl_xor_sync(0xffffffffu, sum1, 2);
    float inv0 = 1.0f / sum0;
    float inv1 = 1.0f / sum1;

    // ---- P (fp16, converted once) aliased over dead K region
    __syncthreads();
    uint32_t* Pw = smu + warp * (16 * PSTP);
    #pragma unroll
    for (int nt = 0; nt < 15; nt++) {
        Pw[gid*PSTP + nt*4 + tig]     = f22h2(acc[nt][0], acc[nt][1]);
        Pw[(gid+8)*PSTP + nt*4 + tig] = f22h2(acc[nt][2], acc[nt][3]);
    }
    Pw[gid*PSTP + 60 + tig] = 0;
    Pw[(gid+8)*PSTP + 60 + tig] = 0;
    __syncwarp();

    int nb2 = n_base >> 1;
    float o[4][4];
    #pragma unroll
    for (int nt = 0; nt < 4; nt++)
        #pragma unroll
        for (int i = 0; i < 4; i++) o[nt][i] = 0.f;

    #pragma unroll
    for (int kt = 0; kt < 8; kt++) {
        int p0 = gid*PSTP + kt*8 + tig;
        int p1 = (gid+8)*PSTP + kt*8 + tig;
        uint32_t ph[4] = { Pw[p0], Pw[p1], Pw[p0 + 4], Pw[p1 + 4] };
        #pragma unroll
        for (int nt = 0; nt < 4; nt++) {
            int vr = (nt*8 + gid)*VSTP + nb2 + kt*8 + tig;
            uint32_t vh[2] = { Vt[vr], Vt[vr + 4] };
            mma_fp16(o[nt], ph, vh);
        }
    }

    // ---- epilogue: write fp16 pairs for proj GEMM
    #pragma unroll
    for (int nt = 0; nt < 4; nt++) {
        int d = head*32 + nt*8 + 2*tig;
        int p = d >> 1;
        int idx = (p & ~7) | PERMJ(p & 7);
        outH[tok0*64 + idx] = f22h2(o[nt][0]*inv0, o[nt][1]*inv0);
        outH[tok1*64 + idx] = f22h2(o[nt][2]*inv1, o[nt][3]*inv1);
    }
}

// ---------------------------------------------------------------------------
// Transpose in: x (B,C,D,H,W) -> t (N=B*D*H*W, C)
// ---------------------------------------------------------------------------
__global__ void t_in_kernel(const float* __restrict__ x, float* __restrict__ t) {
    __shared__ float sm[16][17];
    int bz = blockIdx.z;
    int b = bz / (D_*H_);
    int rem = bz % (D_*H_);
    int d = rem / H_;
    int h = rem % H_;
    int w = blockIdx.x*16 + threadIdx.x;
    int c = blockIdx.y*16 + threadIdx.y;
    sm[threadIdx.y][threadIdx.x] =
        x[(( (long)b*C_ + c)*D_ + d)*(H_*W_) + h*W_ + w];
    __syncthreads();
    int c2 = blockIdx.y*16 + threadIdx.x;
    int w2 = blockIdx.x*16 + threadIdx.y;
    t[((((b*D_ + d)*H_ + h)*W_ + w2) * (long)C_) + c2] = sm[threadIdx.x][threadIdx.y];
}

// ---------------------------------------------------------------------------
// Launch
// ---------------------------------------------------------------------------
extern "C" void kernel_launch(void* const* d_in, const int* in_sizes, int n_in,
                              void* d_out, int out_size) {
    const float* x      = (const float*)d_in[0];
    const float* n1w    = (const float*)d_in[1];
    const float* n1b    = (const float*)d_in[2];
    const float* qkv_w  = (const float*)d_in[3];
    const float* qkv_b  = (const float*)d_in[4];
    const float* rpb    = (const float*)d_in[5];
    const float* proj_w = (const float*)d_in[6];
    const float* proj_b = (const float*)d_in[7];
    const float* n2w    = (const float*)d_in[8];
    const float* n2b    = (const float*)d_in[9];
    const float* fc1_w  = (const float*)d_in[10];
    const float* fc1_b  = (const float*)d_in[11];
    const float* fc2_w  = (const float*)d_in[12];
    const float* fc2_b  = (const float*)d_in[13];
    float* out = (float*)d_out;

    float *t_p;
    uint32_t *wh_p, *ah_p, *bh_p, *qh_p;
    cudaGetSymbolAddress((void**)&t_p,  g_t);
    cudaGetSymbolAddress((void**)&wh_p, g_wh);
    cudaGetSymbolAddress((void**)&ah_p, g_ah);
    cudaGetSymbolAddress((void**)&bh_p, g_bh);
    cudaGetSymbolAddress((void**)&qh_p, g_qkvh);

    int attn_smem = ATTN_SMEM_U32 * (int)sizeof(uint32_t);
    cudaFuncSetAttribute(attn_mma_kernel, cudaFuncAttributeMaxDynamicSharedMemorySize, attn_smem);
    cudaFuncSetAttribute(gemm_cp_kernel<2>, cudaFuncAttributeMaxDynamicSharedMemorySize, GEMM_SMEM);
    cudaFuncSetAttribute(gemm_cp_kernel<3>, cudaFuncAttributeMaxDynamicSharedMemorySize, GEMM_SMEM);
    cudaFuncSetAttribute(gemm_cp_kernel<4>, cudaFuncAttributeMaxDynamicSharedMemorySize, GEMM_SMEM);
    cudaFuncSetAttribute(gemm_cp_kernel<5>, cudaFuncAttributeMaxDynamicSharedMemorySize, GEMM_SMEM);

    dim3 tb(16, 16);
    dim3 tg(W_/16, C_/16, B_*D_*H_);

    // 0. convert weights to fp16 pairs
    wsplit_kernel<<<256, 256>>>(qkv_w, proj_w, fc1_w, fc2_w);
    // 1. transpose in
    t_in_kernel<<<tg, tb>>>(x, t_p);
    // 2. LN1 + fp16 convert
    ln_prep_kernel<<<NTOK/8, 256>>>(t_p, n1w, n1b, ah_p);
    // 3. qkv GEMM -> fp16 Q(scaled)/K/V   (M=384, K=128)
    gemm_cp_kernel<5><<<dim3(6, NTOK/128), 256, GEMM_SMEM>>>(
        ah_p, wh_p, qkv_b, nullptr, qh_p, nullptr, 384, 128);
    // 4. neighborhood attention -> fp16 out
    attn_mma_kernel<<<dim3(36, NHEAD, B_*D_), 128, attn_smem>>>(qh_p, rpb, ah_p);
    // 5. t += attn @ proj_w^T + b     (M=128, K=128)
    gemm_cp_kernel<2><<<dim3(2, NTOK/128), 256, GEMM_SMEM>>>(
        ah_p, wh_p + 24576, proj_b, t_p, nullptr, nullptr, 128, 128);
    // 6. LN2 + fp16 convert
    ln_prep_kernel<<<NTOK/8, 256>>>(t_p, n2w, n2b, ah_p);
    // 7. h1 = gelu(LN2(t) @ fc1_w^T + b) -> fp16  (M=256, K=128)
    gemm_cp_kernel<4><<<dim3(4, NTOK/128), 256, GEMM_SMEM>>>(
        ah_p, wh_p + 32768, fc1_b, nullptr, bh_p, nullptr, 256, 128);
    // 8. out = transpose(t + h1 @ fc2_w^T + b)   (M=128, K=256)
    gemm_cp_kernel<3><<<dim3(2, NTOK/128), 256, GEMM_SMEM>>>(
        bh_p, wh_p + 49152, fc2_b, out, nullptr, t_p, 128, 256);
}

// round 14
// speedup vs baseline: 4.1679x; 1.0048x over previous
#include <cuda_runtime.h>
#include <cuda_fp16.h>
#include <math.h>
#include <stdint.h>

// Problem constants
#define B_  2
#define C_  128
#define D_  4
#define H_  48
#define W_  48
#define NTOK (B_*D_*H_*W_)   // 18432
#define NHEAD 4
#define HD 32
#define KW 7

// Scratch (device globals — no allocation allowed)
__device__ float    g_t    [NTOK*128];
__device__ uint32_t g_qkvh [NTOK*192];   // fp16x2 qkv: Q[0:64) K[64:128) V[128:192) pairs
__device__ uint32_t g_ah   [NTOK*64];    // fp16x2 activations (ln out / attn out)
__device__ uint32_t g_bh   [NTOK*128];   // fp16x2 h1
// fp16x2 weights (packed k-pairs, PERMUTED within 8-pair groups)
__device__ uint32_t g_wh[65536];

#define PERMJ(j) ((j) < 4 ? 2*(j) : 2*(j)-7)

// ===========================================================================
// Helpers
// ===========================================================================
__device__ __forceinline__ void mma_fp16(float* c, const uint32_t* a, const uint32_t* b) {
    asm volatile(
        "mma.sync.aligned.m16n8k16.row.col.f32.f16.f16.f32 "
        "{%0,%1,%2,%3}, {%4,%5,%6,%7}, {%8,%9}, {%0,%1,%2,%3};"
        : "+f"(c[0]), "+f"(c[1]), "+f"(c[2]), "+f"(c[3])
        : "r"(a[0]), "r"(a[1]), "r"(a[2]), "r"(a[3]), "r"(b[0]), "r"(b[1]));
}

__device__ __forceinline__ uint32_t f22h2(float x0, float x1) {
    __half2 h = __floats2half2_rn(x0, x1);
    return *reinterpret_cast<uint32_t*>(&h);
}

#define CP_ASYNC16(dst_u32, src_ptr) \
    asm volatile("cp.async.cg.shared.global [%0], [%1], 16;" \
        :: "r"(dst_u32), "l"(__cvta_generic_to_global(src_ptr)) : "memory")
#define CP_COMMIT() asm volatile("cp.async.commit_group;" ::: "memory")
#define CP_WAIT1()  asm volatile("cp.async.wait_group 1;" ::: "memory")
#define CP_WAIT0()  asm volatile("cp.async.wait_group 0;" ::: "memory")

// ===========================================================================
// Weight convert + permute (fp16 pairs)
// ===========================================================================
__global__ void wsplit_kernel(const float* __restrict__ qkv_w,
                              const float* __restrict__ proj_w,
                              const float* __restrict__ fc1_w,
                              const float* __restrict__ fc2_w) {
    int i = blockIdx.x * 256 + threadIdx.x;
    const float* src;
    int li;
    if (i < 24576)      { src = qkv_w;  li = i; }
    else if (i < 32768) { src = proj_w; li = i - 24576; }
    else if (i < 49152) { src = fc1_w;  li = i - 32768; }
    else                { src = fc2_w;  li = i - 49152; }
    float2 v = *reinterpret_cast<const float2*>(src + 2 * li);
    int dst = (i & ~7) | PERMJ(i & 7);
    g_wh[dst] = f22h2(v.x, v.y);
}

// ===========================================================================
// Fused LN + fp16 convert + permute: warp per token -> ah
// ===========================================================================
__global__ void ln_prep_kernel(const float* __restrict__ in,
                               const float* __restrict__ w,
                               const float* __restrict__ b,
                               uint32_t* __restrict__ ah) {
    int n = blockIdx.x * 8 + (threadIdx.x >> 5);
    int lane = threadIdx.x & 31;
    float4 v = *reinterpret_cast<const float4*>(in + (long)n*128 + lane*4);
    float s  = v.x + v.y + v.z + v.w;
    float s2 = v.x*v.x + v.y*v.y + v.z*v.z + v.w*v.w;
    #pragma unroll
    for (int o = 16; o > 0; o >>= 1) {
        s  += __shfl_xor_sync(0xffffffffu, s,  o);
        s2 += __shfl_xor_sync(0xffffffffu, s2, o);
    }
    float m    = s  * (1.0f/128.0f);
    float rstd = rsqrtf(s2 * (1.0f/128.0f) - m*m + 1e-5f);
    float4 wv = *reinterpret_cast<const float4*>(w + lane*4);
    float4 bv = *reinterpret_cast<const float4*>(b + lane*4);
    float y0 = (v.x - m) * rstd * wv.x + bv.x;
    float y1 = (v.y - m) * rstd * wv.y + bv.y;
    float y2 = (v.z - m) * rstd * wv.z + bv.z;
    float y3 = (v.w - m) * rstd * wv.w + bv.w;
    int p0 = 2*lane, p1 = 2*lane + 1;
    int i0 = (p0 & ~7) | PERMJ(p0 & 7);
    int i1 = (p1 & ~7) | PERMJ(p1 & 7);
    long base = (long)n * 64;
    ah[base + i0] = f22h2(y0, y1);
    ah[base + i1] = f22h2(y2, y3);
}

// ===========================================================================
// fp16 tensor-core GEMM: cp.async 2-stage ring, 64-wide k-chunks.
// out[NTOK,M] = A[NTOK,K] @ W[M,K]^T + bias (+epilogue)
// EPI: 0 bias fp32; 2 bias+residual; 3 bias+residual+transposed store;
//      4 bias+GELU+fp16; 5 qkv fp16 epilogue (Q scaled+perm, K perm, V logical)
// ===========================================================================
#define GSTR 40                 // 32 data u32 + 8 pad: banks 8*gid+2*tig, conflict-free
#define STAGE_U32 7680          // A: 128*40=5120, B: 64*40=2560
#define GEMM_SMEM (2 * STAGE_U32 * 4)   // 61440 B -> 3 CTAs/SM

template<int EPI>
__global__ void __launch_bounds__(256, 3)
gemm_cp_kernel(const uint32_t* __restrict__ AHg,
               const uint32_t* __restrict__ WH,
               const float* __restrict__ bias,
               float* __restrict__ out,
               uint32_t* __restrict__ outH,
               const float* __restrict__ resid,
               int M, int K) {
    extern __shared__ uint32_t smg[];
    uint32_t smb = (uint32_t)__cvta_generic_to_shared(smg);

    int tid = threadIdx.x;
    int wid = tid >> 5, lane = tid & 31;
    int warp_m = wid & 3;
    int warp_n = wid >> 2;
    int gid = lane >> 2;
    int tig = lane & 3;

    int n0 = blockIdx.y * 128;
    int m0 = blockIdx.x * 64;
    int Kp = K >> 1;
    int nch = K >> 6;           // 64-wide chunks (K is 128 or 256)

    float acc[2][4][4];
    #pragma unroll
    for (int mt = 0; mt < 2; mt++)
        #pragma unroll
        for (int nt = 0; nt < 4; nt++)
            #pragma unroll
            for (int i = 0; i < 4; i++) acc[mt][nt][i] = 0.f;

    auto issue = [&](int ch, int s) {
        uint32_t base = smb + (uint32_t)(s * STAGE_U32) * 4u;
        long ka = (long)ch * 32;
        #pragma unroll
        for (int r = 0; r < 4; r++) {
            int seg = r * 256 + tid;
            int row = seg >> 3, q = seg & 7;
            CP_ASYNC16(base + (row*GSTR + q*4)*4, AHg + (long)(n0 + row)*Kp + ka + q*4);
        }
        #pragma unroll
        for (int r = 0; r < 2; r++) {
            int seg = r * 256 + tid;
            int row = seg >> 3, q = seg & 7;
            CP_ASYNC16(base + (5120 + row*GSTR + q*4)*4, WH + (long)(m0 + row)*Kp + ka + q*4);
        }
        CP_COMMIT();
    };

    issue(0, 0);
    if (nch > 1) issue(1, 1);

    for (int ch = 0; ch < nch; ch++) {
        if (ch + 1 < nch) { CP_WAIT1(); } else { CP_WAIT0(); }
        __syncthreads();

        uint32_t* AH = smg + (ch & 1) * STAGE_U32;
        uint32_t* BH = AH + 5120;
        #pragma unroll
        for (int ks = 0; ks < 4; ks++) {
            int jc = ks * 8 + 2 * tig;
            uint32_t ahi[2][4];
            #pragma unroll
            for (int mt = 0; mt < 2; mt++) {
                int r = warp_m * 32 + mt * 16 + gid;
                uint2 h0 = *reinterpret_cast<uint2*>(&AH[r * GSTR + jc]);
                uint2 h1 = *reinterpret_cast<uint2*>(&AH[(r + 8) * GSTR + jc]);
                ahi[mt][0] = h0.x; ahi[mt][1] = h1.x; ahi[mt][2] = h0.y; ahi[mt][3] = h1.y;
            }
            uint32_t bhi[4][2];
            #pragma unroll
            for (int nt = 0; nt < 4; nt++) {
                int br = warp_n * 32 + nt * 8 + gid;
                uint2 bh = *reinterpret_cast<uint2*>(&BH[br * GSTR + jc]);
                bhi[nt][0] = bh.x; bhi[nt][1] = bh.y;
            }
            #pragma unroll
            for (int mt = 0; mt < 2; mt++)
                #pragma unroll
                for (int nt = 0; nt < 4; nt++)
                    mma_fp16(acc[mt][nt], ahi[mt], bhi[nt]);
        }
        __syncthreads();

        if (ch + 2 < nch) issue(ch + 2, ch & 1);
    }

    // ---- epilogue
    int row_base = n0 + warp_m * 32;
    int col_base = m0 + warp_n * 32;
    #pragma unroll
    for (int nt = 0; nt < 4; nt++) {
        int col = col_base + nt * 8 + 2 * tig;
        float b0 = bias[col], b1 = bias[col + 1];
        #pragma unroll
        for (int mt = 0; mt < 2; mt++) {
            #pragma unroll
            for (int half = 0; half < 2; half++) {
                int r = row_base + mt * 16 + gid + half * 8;
                float v0 = acc[mt][nt][half * 2 + 0] + b0;
                float v1 = acc[mt][nt][half * 2 + 1] + b1;
                if (EPI == 5) {
                    int idx;
                    if (col < 128) {
                        const float sc = 0.17677669529663687f;
                        v0 *= sc; v1 *= sc;
                        int p = col >> 1;
                        idx = (p & ~7) | PERMJ(p & 7);
                    } else if (col < 256) {
                        int p = (col - 128) >> 1;
                        idx = 64 + ((p & ~7) | PERMJ(p & 7));
                    } else {
                        idx = 128 + ((col - 256) >> 1);
                    }
                    outH[(long)r * 192 + idx] = f22h2(v0, v1);
                } else if (EPI == 4) {
                    v0 = 0.5f * v0 * (1.0f + erff(v0 * 0.70710678118654752f));
                    v1 = 0.5f * v1 * (1.0f + erff(v1 * 0.70710678118654752f));
                    int p = col >> 1;
                    int idx = (p & ~7) | PERMJ(p & 7);
                    outH[(long)r * 128 + idx] = f22h2(v0, v1);
                } else if (EPI == 3) {
                    float2 rv = *reinterpret_cast<const float2*>(resid + (long)r * 128 + col);
                    v0 += rv.x; v1 += rv.y;
                    long o = (long)r + (r >= 9216 ? 1170432L : 0L) + (long)col * 9216;
                    out[o]        = v0;
                    out[o + 9216] = v1;
                } else {
                    float2* dst = reinterpret_cast<float2*>(out + (long)r * M + col);
                    if (EPI == 2) {
                        float2 old = *dst;
                        v0 += old.x; v1 += old.y;
                    }
                    float2 st; st.x = v0; st.y = v1;
                    *dst = st;
                }
            }
        }
    }
}

// ===========================================================================
// fp16 tensor-core neighborhood attention (unchanged from R13)
// ===========================================================================
#define AGSTR 24
#define VSTP  116
#define PSTP  68
#define ATTN_SMEM_U32 (224*AGSTR + 32*VSTP + 170)   // 9258

__global__ void __launch_bounds__(128, 4)
attn_mma_kernel(const uint32_t* __restrict__ inH,
                const float* __restrict__ rpb,
                uint32_t* __restrict__ outH) {
    extern __shared__ uint32_t smu[];
    uint32_t* Ks = smu;
    uint32_t* Vt = Ks + 224*AGSTR;
    float*    rb = reinterpret_cast<float*>(Vt + 32*VSTP);

    int tile = blockIdx.x, head = blockIdx.y, bd = blockIdx.z;
    int h0 = (tile / 6) * 8;
    int w0 = (tile % 6) * 8;
    int kh0 = min(max(h0 - 3, 0), H_ - KW);
    int kw0 = min(max(w0 - 3, 0), W_ - KW);
    int tid = threadIdx.x;

    for (int e = tid; e < 196*4; e += 128) {
        int key = e >> 2, q = e & 3;
        int kr = key / 14, kc = key % 14;
        int gh = min(kh0 + kr, H_-1);
        int gw = min(kw0 + kc, W_-1);
        long tok = ((long)(bd*H_ + gh))*W_ + gw;
        long src = tok*192 + 64 + head*16 + q*4;
        *reinterpret_cast<uint4*>(&Ks[key*AGSTR + q*4]) = *reinterpret_cast<const uint4*>(inH + src);
    }
    for (int e = tid; e < 28*6; e += 128) {
        int key = 196 + e / 6, q = e % 6;
        *reinterpret_cast<uint4*>(&Ks[key*AGSTR + q*4]) = make_uint4(0,0,0,0);
    }
    for (int e = tid; e < 98*4; e += 128) {
        int kp = e >> 2, pq = e & 3;
        int keyA = 2*kp;
        int kr = keyA / 14, kc = keyA % 14;
        int gh = min(kh0 + kr, H_-1);
        int gwA = min(kw0 + kc, W_-1);
        int gwB = min(kw0 + kc + 1, W_-1);
        long rowb = ((long)(bd*H_ + gh))*W_;
        long sA = (rowb + gwA)*192 + 128 + head*16 + pq*4;
        long sB = (rowb + gwB)*192 + 128 + head*16 + pq*4;
        uint4 HA = *reinterpret_cast<const uint4*>(inH + sA);
        uint4 HB = *reinterpret_cast<const uint4*>(inH + sB);
        uint32_t ha[4] = {HA.x, HA.y, HA.z, HA.w};
        uint32_t hb[4] = {HB.x, HB.y, HB.z, HB.w};
        #pragma unroll
        for (int j = 0; j < 4; j++) {
            int pp = pq*4 + j;
            Vt[(2*pp+0)*VSTP + kp] = __byte_perm(ha[j], hb[j], 0x5410);
            Vt[(2*pp+1)*VSTP + kp] = __byte_perm(ha[j], hb[j], 0x7632);
        }
    }
    for (int e = tid; e < 32*14; e += 128) {
        int dm = e / 14, kp = 98 + (e % 14);
        Vt[dm*VSTP + kp] = 0;
    }
    for (int i = tid; i < 169; i += 128) rb[i] = rpb[head*169 + i];
    __syncthreads();

    int warp = tid >> 5, lane = tid & 31;
    int gid = lane >> 2, tig = lane & 3;

    int hq0 = h0 + 2*warp;
    int hq1 = hq0 + 1;
    int wq  = w0 + gid;
    long tok0 = (long)(bd*H_ + hq0)*W_ + wq;
    long tok1 = tok0 + W_;
    int rel0 = min(max(hq0-3, 0), H_-KW) - kh0;
    int rel1 = min(max(hq1-3, 0), H_-KW) - kh0;
    int ws   = min(max(wq-3, 0), W_-KW) - kw0;
    int n_base = ((min(rel0, rel1) * 14) >> 3) * 8;

    uint32_t qh[2][4];
    #pragma unroll
    for (int ks = 0; ks < 2; ks++) {
        long o0 = tok0*192 + head*16 + ks*8 + 2*tig;
        long o1 = tok1*192 + head*16 + ks*8 + 2*tig;
        uint2 h0v = *reinterpret_cast<const uint2*>(inH + o0);
        uint2 h1v = *reinterpret_cast<const uint2*>(inH + o1);
        qh[ks][0] = h0v.x; qh[ks][1] = h1v.x; qh[ks][2] = h0v.y; qh[ks][3] = h1v.y;
    }

    float acc[15][4];
    #pragma unroll
    for (int nt = 0; nt < 15; nt++)
        #pragma unroll
        for (int i = 0; i < 4; i++) acc[nt][i] = 0.f;

    #pragma unroll
    for (int nt = 0; nt < 15; nt++) {
        int key = n_base + nt*8 + gid;
        #pragma unroll
        for (int ks = 0; ks < 2; ks++) {
            int o = key*AGSTR + ks*8 + 2*tig;
            uint2 bhv = *reinterpret_cast<uint2*>(&Ks[o]);
            uint32_t bh[2] = { bhv.x, bhv.y };
            mma_fp16(acc[nt], qh[ks], bh);
        }
    }

    int bh0c = kh0 - hq0 + 6;
    int bh1c = kh0 - hq1 + 6;
    int bwc  = kw0 - wq + 6;
    float mx0 = -1e30f, mx1 = -1e30f;
    #pragma unroll
    for (int nt = 0; nt < 15; nt++) {
        #pragma unroll
        for (int cc = 0; cc < 2; cc++) {
            int n = n_base + nt*8 + 2*tig + cc;
            int kr = n / 14;
            int kc = n - kr*14;
            bool vw = (unsigned)(kc - ws) <= 6u;
            bool v0 = vw && (unsigned)(kr - rel0) <= 6u;
            bool v1 = vw && (unsigned)(kr - rel1) <= 6u;
            float s0 = v0 ? acc[nt][cc]   + rb[(bh0c+kr)*13 + bwc + kc] : -1e30f;
            float s1 = v1 ? acc[nt][2+cc] + rb[(bh1c+kr)*13 + bwc + kc] : -1e30f;
            acc[nt][cc]   = s0;
            acc[nt][2+cc] = s1;
            mx0 = fmaxf(mx0, s0);
            mx1 = fmaxf(mx1, s1);
        }
    }
    mx0 = fmaxf(mx0, __shfl_xor_sync(0xffffffffu, mx0, 1));
    mx0 = fmaxf(mx0, __shfl_xor_sync(0xffffffffu, mx0, 2));
    mx1 = fmaxf(mx1, __shfl_xor_sync(0xffffffffu, mx1, 1));
    mx1 = fmaxf(mx1, __shfl_xor_sync(0xffffffffu, mx1, 2));

    float sum0 = 0.f, sum1 = 0.f;
    #pragma unroll
    for (int nt = 0; nt < 15; nt++) {
        #pragma unroll
        for (int cc = 0; cc < 2; cc++) {
            float e0 = __expf(acc[nt][cc]   - mx0);
            float e1 = __expf(acc[nt][2+cc] - mx1);
            acc[nt][cc]   = e0;
            acc[nt][2+cc] = e1;
            sum0 += e0;
            sum1 += e1;
        }
    }
    sum0 += __shfl_xor_sync(0xffffffffu, sum0, 1);
    sum0 += __shfl_xor_sync(0xffffffffu, sum0, 2);
    sum1 += __shfl_xor_sync(0xffffffffu, sum1, 1);
    sum1 += __shfl_xor_sync(0xffffffffu, sum1, 2);
    float inv0 = 1.0f / sum0;
    float inv1 = 1.0f / sum1;

    __syncthreads();
    uint32_t* Pw = smu + warp * (16 * PSTP);
    #pragma unroll
    for (int nt = 0; nt < 15; nt++) {
        Pw[gid*PSTP + nt*4 + tig]     = f22h2(acc[nt][0], acc[nt][1]);
        Pw[(gid+8)*PSTP + nt*4 + tig] = f22h2(acc[nt][2], acc[nt][3]);
    }
    Pw[gid*PSTP + 60 + tig] = 0;
    Pw[(gid+8)*PSTP + 60 + tig] = 0;
    __syncwarp();

    int nb2 = n_base >> 1;
    float o[4][4];
    #pragma unroll
    for (int nt = 0; nt < 4; nt++)
        #pragma unroll
        for (int i = 0; i < 4; i++) o[nt][i] = 0.f;

    #pragma unroll
    for (int kt = 0; kt < 8; kt++) {
        int p0 = gid*PSTP + kt*8 + tig;
        int p1 = (gid+8)*PSTP + kt*8 + tig;
        uint32_t ph[4] = { Pw[p0], Pw[p1], Pw[p0 + 4], Pw[p1 + 4] };
        #pragma unroll
        for (int nt = 0; nt < 4; nt++) {
            int vr = (nt*8 + gid)*VSTP + nb2 + kt*8 + tig;
            uint32_t vh[2] = { Vt[vr], Vt[vr + 4] };
            mma_fp16(o[nt], ph, vh);
        }
    }

    #pragma unroll
    for (int nt = 0; nt < 4; nt++) {
        int d = head*32 + nt*8 + 2*tig;
        int p = d >> 1;
        int idx = (p & ~7) | PERMJ(p & 7);
        outH[tok0*64 + idx] = f22h2(o[nt][0]*inv0, o[nt][1]*inv0);
        outH[tok1*64 + idx] = f22h2(o[nt][2]*inv1, o[nt][3]*inv1);
    }
}

// ---------------------------------------------------------------------------
// Transpose in: x (B,C,D,H,W) -> t (N=B*D*H*W, C)
// ---------------------------------------------------------------------------
__global__ void t_in_kernel(const float* __restrict__ x, float* __restrict__ t) {
    __shared__ float sm[16][17];
    int bz = blockIdx.z;
    int b = bz / (D_*H_);
    int rem = bz % (D_*H_);
    int d = rem / H_;
    int h = rem % H_;
    int w = blockIdx.x*16 + threadIdx.x;
    int c = blockIdx.y*16 + threadIdx.y;
    sm[threadIdx.y][threadIdx.x] =
        x[(( (long)b*C_ + c)*D_ + d)*(H_*W_) + h*W_ + w];
    __syncthreads();
    int c2 = blockIdx.y*16 + threadIdx.x;
    int w2 = blockIdx.x*16 + threadIdx.y;
    t[((((b*D_ + d)*H_ + h)*W_ + w2) * (long)C_) + c2] = sm[threadIdx.x][threadIdx.y];
}

// ---------------------------------------------------------------------------
// Launch
// ---------------------------------------------------------------------------
extern "C" void kernel_launch(void* const* d_in, const int* in_sizes, int n_in,
                              void* d_out, int out_size) {
    const float* x      = (const float*)d_in[0];
    const float* n1w    = (const float*)d_in[1];
    const float* n1b    = (const float*)d_in[2];
    const float* qkv_w  = (const float*)d_in[3];
    const float* qkv_b  = (const float*)d_in[4];
    const float* rpb    = (const float*)d_in[5];
    const float* proj_w = (const float*)d_in[6];
    const float* proj_b = (const float*)d_in[7];
    const float* n2w    = (const float*)d_in[8];
    const float* n2b    = (const float*)d_in[9];
    const float* fc1_w  = (const float*)d_in[10];
    const float* fc1_b  = (const float*)d_in[11];
    const float* fc2_w  = (const float*)d_in[12];
    const float* fc2_b  = (const float*)d_in[13];
    float* out = (float*)d_out;

    float *t_p;
    uint32_t *wh_p, *ah_p, *bh_p, *qh_p;
    cudaGetSymbolAddress((void**)&t_p,  g_t);
    cudaGetSymbolAddress((void**)&wh_p, g_wh);
    cudaGetSymbolAddress((void**)&ah_p, g_ah);
    cudaGetSymbolAddress((void**)&bh_p, g_bh);
    cudaGetSymbolAddress((void**)&qh_p, g_qkvh);

    int attn_smem = ATTN_SMEM_U32 * (int)sizeof(uint32_t);
    cudaFuncSetAttribute(attn_mma_kernel, cudaFuncAttributeMaxDynamicSharedMemorySize, attn_smem);
    cudaFuncSetAttribute(gemm_cp_kernel<2>, cudaFuncAttributeMaxDynamicSharedMemorySize, GEMM_SMEM);
    cudaFuncSetAttribute(gemm_cp_kernel<3>, cudaFuncAttributeMaxDynamicSharedMemorySize, GEMM_SMEM);
    cudaFuncSetAttribute(gemm_cp_kernel<4>, cudaFuncAttributeMaxDynamicSharedMemorySize, GEMM_SMEM);
    cudaFuncSetAttribute(gemm_cp_kernel<5>, cudaFuncAttributeMaxDynamicSharedMemorySize, GEMM_SMEM);

    dim3 tb(16, 16);
    dim3 tg(W_/16, C_/16, B_*D_*H_);

    // 0. convert weights to fp16 pairs
    wsplit_kernel<<<256, 256>>>(qkv_w, proj_w, fc1_w, fc2_w);
    // 1. transpose in
    t_in_kernel<<<tg, tb>>>(x, t_p);
    // 2. LN1 + fp16 convert
    ln_prep_kernel<<<NTOK/8, 256>>>(t_p, n1w, n1b, ah_p);
    // 3. qkv GEMM -> fp16 Q(scaled)/K/V   (M=384, K=128)
    gemm_cp_kernel<5><<<dim3(6, NTOK/128), 256, GEMM_SMEM>>>(
        ah_p, wh_p, qkv_b, nullptr, qh_p, nullptr, 384, 128);
    // 4. neighborhood attention -> fp16 out
    attn_mma_kernel<<<dim3(36, NHEAD, B_*D_), 128, attn_smem>>>(qh_p, rpb, ah_p);
    // 5. t += attn @ proj_w^T + b     (M=128, K=128)
    gemm_cp_kernel<2><<<dim3(2, NTOK/128), 256, GEMM_SMEM>>>(
        ah_p, wh_p + 24576, proj_b, t_p, nullptr, nullptr, 128, 128);
    // 6. LN2 + fp16 convert
    ln_prep_kernel<<<NTOK/8, 256>>>(t_p, n2w, n2b, ah_p);
    // 7. h1 = gelu(LN2(t) @ fc1_w^T + b) -> fp16  (M=256, K=128)
    gemm_cp_kernel<4><<<dim3(4, NTOK/128), 256, GEMM_SMEM>>>(
        ah_p, wh_p + 32768, fc1_b, nullptr, bh_p, nullptr, 256, 128);
    // 8. out = transpose(t + h1 @ fc2_w^T + b)   (M=128, K=256)
    gemm_cp_kernel<3><<<dim3(2, NTOK/128), 256, GEMM_SMEM>>>(
        bh_p, wh_p + 49152, fc2_b, out, nullptr, t_p, 128, 256);
}